// round 5
// baseline (speedup 1.0000x reference)
#include <cuda_runtime.h>
#include <cuda_fp16.h>
#include <math.h>
#include <stdint.h>

// ---------------- problem constants ----------------
#define B_    2
#define T_    1024
#define C_    1024
#define H_    16
#define HD_   64
#define DC_   256
#define DC1_  256
#define DR_   32
#define DN_   32
#define V_    32000
#define L_    4
#define NTOK  (B_*T_)             // 2048
#define DOWNW (DC_+DC1_+DR_)      // 544
#define KVW   (H_*(DN_+HD_))      // 1536
#define EPS_  1.1920929e-07f

// ---------------- scratch ----------------
__device__ float g_x   [NTOK*C_];
__device__ float g_x0  [NTOK*C_];
__device__ float g_xn  [NTOK*C_];
__device__ float g_down[NTOK*DOWNW];
__device__ float g_kv  [NTOK*KVW];
__device__ float g_qpre[NTOK*C_];
__device__ float g_q   [NTOK*C_];
__device__ float g_k   [NTOK*C_];
__device__ float g_v   [NTOK*C_];
__device__ float g_y   [NTOK*C_];
__device__ float g_h   [NTOK*4*C_];

// ---------------- helpers ----------------
__device__ __forceinline__ uint32_t smem_u32(const void* p) {
    uint32_t a;
    asm("{ .reg .u64 t; cvta.to.shared.u64 t, %1; cvt.u32.u64 %0, t; }" : "=r"(a) : "l"(p));
    return a;
}
__device__ __forceinline__ float warp_sum(float v) {
    v += __shfl_xor_sync(0xffffffffu, v, 16);
    v += __shfl_xor_sync(0xffffffffu, v, 8);
    v += __shfl_xor_sync(0xffffffffu, v, 4);
    v += __shfl_xor_sync(0xffffffffu, v, 2);
    v += __shfl_xor_sync(0xffffffffu, v, 1);
    return v;
}
__device__ __forceinline__ float block_sum(float v) {
    __shared__ float sh[32];
    int lane = threadIdx.x & 31, wid = threadIdx.x >> 5;
    v = warp_sum(v);
    if (lane == 0) sh[wid] = v;
    __syncthreads();
    int nw = blockDim.x >> 5;
    if (wid == 0) {
        float t = (lane < nw) ? sh[lane] : 0.f;
        t = warp_sum(t);
        if (lane == 0) sh[0] = t;
    }
    __syncthreads();
    return sh[0];
}

// ---------------- mma / ldmatrix wrappers ----------------
__device__ __forceinline__ void ldsm_x4(uint32_t* r, uint32_t addr) {
    asm volatile("ldmatrix.sync.aligned.m8n8.x4.shared.b16 {%0,%1,%2,%3}, [%4];"
                 : "=r"(r[0]), "=r"(r[1]), "=r"(r[2]), "=r"(r[3]) : "r"(addr));
}
__device__ __forceinline__ void ldsm_x2t(uint32_t* r, uint32_t addr) {
    asm volatile("ldmatrix.sync.aligned.m8n8.x2.trans.shared.b16 {%0,%1}, [%2];"
                 : "=r"(r[0]), "=r"(r[1]) : "r"(addr));
}
__device__ __forceinline__ void mma16816(float4& d, const uint32_t* a, const uint32_t* b) {
    asm volatile(
        "mma.sync.aligned.m16n8k16.row.col.f32.f16.f16.f32 "
        "{%0,%1,%2,%3},{%4,%5,%6,%7},{%8,%9},{%0,%1,%2,%3};"
        : "+f"(d.x), "+f"(d.y), "+f"(d.z), "+f"(d.w)
        : "r"(a[0]), "r"(a[1]), "r"(a[2]), "r"(a[3]), "r"(b[0]), "r"(b[1]));
}
__device__ __forceinline__ void splith(float x, uint16_t& hi, uint16_t& lo) {
    __half h = __float2half_rn(x);
    float r = x - __half2float(h);
    __half l = __float2half_rn(r);
    hi = __half_as_ushort(h);
    lo = __half_as_ushort(l);
}

// ---------------- embedding + rmsnorm ----------------
__global__ void embed_kernel(const int* __restrict__ idx, const float* __restrict__ wte) {
    int row = blockIdx.x;
    int tok = idx[row];
    const float* src = wte + (size_t)tok * C_;
    float s = 0.f;
    for (int i = threadIdx.x; i < C_; i += blockDim.x) { float v = src[i]; s += v * v; }
    s = block_sum(s);
    float r = rsqrtf(s * (1.0f / C_) + EPS_);
    for (int i = threadIdx.x; i < C_; i += blockDim.x) {
        float v = src[i] * r;
        g_x [(size_t)row * C_ + i] = v;
        g_x0[(size_t)row * C_ + i] = v;
    }
}

__global__ void mix_norm_kernel(const float* lr, const float* lx, int layer) {
    int row = blockIdx.x;
    float a = lr ? lr[layer] : 1.0f;
    float b = lx ? lx[layer] : 0.0f;
    float*       xr  = g_x  + (size_t)row * C_;
    const float* x0r = g_x0 + (size_t)row * C_;
    float s = 0.f;
    for (int i = threadIdx.x; i < C_; i += blockDim.x) {
        float v = a * xr[i] + b * x0r[i];
        xr[i] = v;
        s += v * v;
    }
    s = block_sum(s);
    float r = rsqrtf(s * (1.0f / C_) + EPS_);
    for (int i = threadIdx.x; i < C_; i += blockDim.x)
        g_xn[(size_t)row * C_ + i] = xr[i] * r;
}

// ---------------- 3xFP16 tensor-core GEMM (v2: 512 thr, Ktile 32) ------
// C[M,N] = A[M,K] @ B[K,N] (+D). mode 0 plain, 1 softcap, 2 relu^2.
// MT x 128 CTA tile (MT = 128 or 64), 16 warps (4x4), warp tile (MT/4)x32.
// SMEM per stage:
//   A plane [MT rows][128B]: hi halves at bytes 0..63 (k*2), lo at 64..127,
//     swizzle off ^= (off>>3)&0x70  (SW128).
//   B hi plane [32k][256B rows], xor ((k&7)<<4); lo plane at +8192.
#define KT2_ 32

template<int MT>
__global__ __launch_bounds__(512, 1) void gemm_h3(
    const float* __restrict__ A, const float* __restrict__ Bm,
    float* __restrict__ C, const float* __restrict__ D,
    int M, int N, int K, int lda, int ldb, int ldc, int mode)
{
    constexpr int MI   = MT / 64;            // 2 or 1
    constexpr int APB  = MT * 128;           // A plane bytes
    constexpr int STG  = APB + 16384;        // stage bytes
    constexpr int ANF4 = MT * 8;             // A float4 count per tile
    constexpr int AR   = ANF4 / 512;         // A float4 per thread (2 or 1)

    extern __shared__ __align__(1024) char sm[];
    int tid = threadIdx.x;
    int wid = tid >> 5, lane = tid & 31;
    int warp_m = wid >> 2, warp_n = wid & 3;
    int m0 = blockIdx.x * MT, n0 = blockIdx.y * 128;
    uint32_t smb = smem_u32(sm);

    float4 acc[MI][4];
#pragma unroll
    for (int i = 0; i < MI; i++)
#pragma unroll
        for (int j = 0; j < 4; j++) acc[i][j] = make_float4(0.f, 0.f, 0.f, 0.f);

    // fragment address components
    int arow0 = warp_m * (MT / 4) + (lane & 15);
    int akof  = (lane & 16);
    int bkrl  = (lane & 15);
    int bnof  = warp_n * 64;

    float4 ar[AR], br[2];
    int nk = K / KT2_;

    // ---- producer store helper indices ----
    // A: float4 v: m=v>>3, kq=v&7 -> hi uint2 @ m*128+kq*8 (sw), lo @ +64
    // B: float4 v: k=v>>5, nq=v&31 -> hi uint2 @ k*256+nq*8 ^ ((k&7)<<4); lo +8192

    // ---- prologue: load + split + store ktile 0 ----
    {
        const float* Ab = A + (size_t)m0 * lda;
        const float* Bb = Bm + n0;
#pragma unroll
        for (int r = 0; r < AR; r++) {
            int v = tid + r * 512;
            ar[r] = *reinterpret_cast<const float4*>(Ab + (size_t)(v >> 3) * lda + (v & 7) * 4);
        }
#pragma unroll
        for (int r = 0; r < 2; r++) {
            int v = tid + r * 512;
            int n = (v & 31) * 4;
            br[r] = (n0 + n < N)
                ? *reinterpret_cast<const float4*>(Bb + (size_t)(v >> 5) * ldb + n)
                : make_float4(0.f, 0.f, 0.f, 0.f);
        }
        char* Ap = sm;
        char* Bh = sm + APB;
        char* Bl = Bh + 8192;
#pragma unroll
        for (int r = 0; r < AR; r++) {
            int v = tid + r * 512;
            uint16_t h0,l0,h1,l1,h2,l2,h3,l3;
            splith(ar[r].x,h0,l0); splith(ar[r].y,h1,l1);
            splith(ar[r].z,h2,l2); splith(ar[r].w,h3,l3);
            uint32_t oh = (uint32_t)((v >> 3) * 128 + (v & 7) * 8);
            uint32_t ol = oh + 64;
            oh ^= (oh >> 3) & 0x70; ol ^= (ol >> 3) & 0x70;
            *reinterpret_cast<uint2*>(Ap + oh) =
                make_uint2((uint32_t)h0 | ((uint32_t)h1 << 16), (uint32_t)h2 | ((uint32_t)h3 << 16));
            *reinterpret_cast<uint2*>(Ap + ol) =
                make_uint2((uint32_t)l0 | ((uint32_t)l1 << 16), (uint32_t)l2 | ((uint32_t)l3 << 16));
        }
#pragma unroll
        for (int r = 0; r < 2; r++) {
            int v = tid + r * 512;
            uint16_t h0,l0,h1,l1,h2,l2,h3,l3;
            splith(br[r].x,h0,l0); splith(br[r].y,h1,l1);
            splith(br[r].z,h2,l2); splith(br[r].w,h3,l3);
            int k = v >> 5;
            uint32_t off = (uint32_t)(k * 256 + (v & 31) * 8) ^ ((uint32_t)(k & 7) << 4);
            *reinterpret_cast<uint2*>(Bh + off) =
                make_uint2((uint32_t)h0 | ((uint32_t)h1 << 16), (uint32_t)h2 | ((uint32_t)h3 << 16));
            *reinterpret_cast<uint2*>(Bl + off) =
                make_uint2((uint32_t)l0 | ((uint32_t)l1 << 16), (uint32_t)l2 | ((uint32_t)l3 << 16));
        }
    }
    __syncthreads();

    for (int kt = 0; kt < nk; kt++) {
        int p = kt & 1;
        // ---- prefetch next ktile ----
        if (kt + 1 < nk) {
            const float* Ab = A + (size_t)m0 * lda + (kt + 1) * KT2_;
            const float* Bb = Bm + (size_t)((kt + 1) * KT2_) * ldb + n0;
#pragma unroll
            for (int r = 0; r < AR; r++) {
                int v = tid + r * 512;
                ar[r] = *reinterpret_cast<const float4*>(Ab + (size_t)(v >> 3) * lda + (v & 7) * 4);
            }
#pragma unroll
            for (int r = 0; r < 2; r++) {
                int v = tid + r * 512;
                int n = (v & 31) * 4;
                br[r] = (n0 + n < N)
                    ? *reinterpret_cast<const float4*>(Bb + (size_t)(v >> 5) * ldb + n)
                    : make_float4(0.f, 0.f, 0.f, 0.f);
            }
        }

        // ---- mma over stage p ----
        uint32_t sA  = smb + p * STG;
        uint32_t sBh = sA + APB;
        uint32_t sBl = sBh + 8192;
#pragma unroll
        for (int ks = 0; ks < 2; ks++) {
            uint32_t ahi[MI][4], alo[MI][4], bhi[4][2], blo[4][2];
#pragma unroll
            for (int mi = 0; mi < MI; mi++) {
                uint32_t oh = (uint32_t)((arow0 + mi * 16) * 128 + ks * 32 + akof);
                uint32_t ol = oh + 64;
                oh ^= (oh >> 3) & 0x70; ol ^= (ol >> 3) & 0x70;
                ldsm_x4(ahi[mi], sA + oh);
                ldsm_x4(alo[mi], sA + ol);
            }
#pragma unroll
            for (int ni = 0; ni < 4; ni++) {
                int krow = ks * 16 + bkrl;
                uint32_t off = (uint32_t)(krow * 256 + bnof + ni * 16) ^ ((uint32_t)(krow & 7) << 4);
                ldsm_x2t(bhi[ni], sBh + off);
                ldsm_x2t(blo[ni], sBl + off);
            }
            // term-outer ordering: consecutive mmas hit different accumulators
#pragma unroll
            for (int mi = 0; mi < MI; mi++)
#pragma unroll
                for (int ni = 0; ni < 4; ni++) mma16816(acc[mi][ni], ahi[mi], bhi[ni]);
#pragma unroll
            for (int mi = 0; mi < MI; mi++)
#pragma unroll
                for (int ni = 0; ni < 4; ni++) mma16816(acc[mi][ni], ahi[mi], blo[ni]);
#pragma unroll
            for (int mi = 0; mi < MI; mi++)
#pragma unroll
                for (int ni = 0; ni < 4; ni++) mma16816(acc[mi][ni], alo[mi], bhi[ni]);
        }

        // ---- split + store next stage ----
        if (kt + 1 < nk) {
            int q = p ^ 1;
            char* Ap = sm + q * STG;
            char* Bh = Ap + APB;
            char* Bl = Bh + 8192;
#pragma unroll
            for (int r = 0; r < AR; r++) {
                int v = tid + r * 512;
                uint16_t h0,l0,h1,l1,h2,l2,h3,l3;
                splith(ar[r].x,h0,l0); splith(ar[r].y,h1,l1);
                splith(ar[r].z,h2,l2); splith(ar[r].w,h3,l3);
                uint32_t oh = (uint32_t)((v >> 3) * 128 + (v & 7) * 8);
                uint32_t ol = oh + 64;
                oh ^= (oh >> 3) & 0x70; ol ^= (ol >> 3) & 0x70;
                *reinterpret_cast<uint2*>(Ap + oh) =
                    make_uint2((uint32_t)h0 | ((uint32_t)h1 << 16), (uint32_t)h2 | ((uint32_t)h3 << 16));
                *reinterpret_cast<uint2*>(Ap + ol) =
                    make_uint2((uint32_t)l0 | ((uint32_t)l1 << 16), (uint32_t)l2 | ((uint32_t)l3 << 16));
            }
#pragma unroll
            for (int r = 0; r < 2; r++) {
                int v = tid + r * 512;
                uint16_t h0,l0,h1,l1,h2,l2,h3,l3;
                splith(br[r].x,h0,l0); splith(br[r].y,h1,l1);
                splith(br[r].z,h2,l2); splith(br[r].w,h3,l3);
                int k = v >> 5;
                uint32_t off = (uint32_t)(k * 256 + (v & 31) * 8) ^ ((uint32_t)(k & 7) << 4);
                *reinterpret_cast<uint2*>(Bh + off) =
                    make_uint2((uint32_t)h0 | ((uint32_t)h1 << 16), (uint32_t)h2 | ((uint32_t)h3 << 16));
                *reinterpret_cast<uint2*>(Bl + off) =
                    make_uint2((uint32_t)l0 | ((uint32_t)l1 << 16), (uint32_t)l2 | ((uint32_t)l3 << 16));
            }
        }
        __syncthreads();
    }

    // ---- epilogue ----
    int g = lane >> 2, t4 = lane & 3;
#pragma unroll
    for (int mi = 0; mi < MI; mi++) {
        int r0 = m0 + warp_m * (MT / 4) + mi * 16 + g;
#pragma unroll
        for (int ni = 0; ni < 4; ni++) {
            int col = n0 + warp_n * 32 + ni * 8 + 2 * t4;
            if (col >= N) continue;
            float4 v = acc[mi][ni];
            if (D) {
                float2 d0 = *reinterpret_cast<const float2*>(D + (size_t)r0 * ldc + col);
                float2 d1 = *reinterpret_cast<const float2*>(D + (size_t)(r0 + 8) * ldc + col);
                v.x += d0.x; v.y += d0.y; v.z += d1.x; v.w += d1.y;
            }
            if (mode == 1) {
                v.x = 15.0f * tanhf(v.x * (1.f / 15.f));
                v.y = 15.0f * tanhf(v.y * (1.f / 15.f));
                v.z = 15.0f * tanhf(v.z * (1.f / 15.f));
                v.w = 15.0f * tanhf(v.w * (1.f / 15.f));
            } else if (mode == 2) {
                v.x = (v.x > 0.f) ? v.x * v.x : 0.f;
                v.y = (v.y > 0.f) ? v.y * v.y : 0.f;
                v.z = (v.z > 0.f) ? v.z * v.z : 0.f;
                v.w = (v.w > 0.f) ? v.w * v.w : 0.f;
            }
            *reinterpret_cast<float2*>(C + (size_t)r0 * ldc + col) = make_float2(v.x, v.y);
            *reinterpret_cast<float2*>(C + (size_t)(r0 + 8) * ldc + col) = make_float2(v.z, v.w);
        }
    }
}

// ---------------- per-token q/k/v build ----------------
__global__ void build_qkv_kernel(const int* __restrict__ idx,
                                 const float* __restrict__ cosp, const float* __restrict__ sinp,
                                 const float* __restrict__ vg, const float* __restrict__ vetab)
{
    int row = blockIdx.x;
    int h    = threadIdx.x >> 5;
    int lane = threadIdx.x & 31;
    const float* cosr = cosp + (size_t)row * (DR_ / 2);
    const float* sinr = sinp + (size_t)row * (DR_ / 2);

    float gv = g_xn[(size_t)row * C_ + lane] * vg[lane * H_ + h];
    gv = warp_sum(gv);
    float gate = 2.0f / (1.0f + __expf(-gv));

    int r16 = (lane < 16) ? lane : lane - 16;
    float c = cosr[r16], s = sinr[r16];

    float kn = g_kv[(size_t)row * KVW + h * 96 + lane];
    const float* dro = g_down + (size_t)row * DOWNW + 512;
    float kr = (lane < 16) ? (dro[lane] * c + dro[lane + 16] * s)
                           : (-dro[lane - 16] * s + dro[lane] * c);
    float ssk = warp_sum(kn * kn + kr * kr);
    float rk = rsqrtf(ssk * (1.0f / 64.0f) + EPS_);
    g_k[(size_t)row * C_ + h * 64 + lane]      = kn * rk;
    g_k[(size_t)row * C_ + h * 64 + lane + 32] = kr * rk;

    const float* qp = g_qpre + (size_t)row * C_ + h * 64;
    float qn = qp[lane];
    float qr = (lane < 16) ? (qp[32 + lane] * c + qp[48 + lane] * s)
                           : (-qp[16 + lane] * s + qp[32 + lane] * c);
    float ssq = warp_sum(qn * qn + qr * qr);
    float rq = rsqrtf(ssq * (1.0f / 64.0f) + EPS_);
    g_q[(size_t)row * C_ + h * 64 + lane]      = qn * rq;
    g_q[(size_t)row * C_ + h * 64 + lane + 32] = qr * rq;

    int tok = idx[row];
    const float* ver = vetab + (size_t)tok * C_ + h * 64;
    const float* kvv = g_kv + (size_t)row * KVW + h * 96 + 32;
    g_v[(size_t)row * C_ + h * 64 + lane]      = kvv[lane]      + gate * ver[lane];
    g_v[(size_t)row * C_ + h * 64 + lane + 32] = kvv[lane + 32] + gate * ver[lane + 32];
}

// ---------------- causal flash attention ----------------
__global__ void attn_kernel()
{
    __shared__ float Qs[64][65];
    __shared__ float Ks[32][65];
    __shared__ float VsT[64][33];
    __shared__ float Ps[64][33];

    int q0 = blockIdx.x * 64;
    int h  = blockIdx.y;
    int b  = blockIdx.z;
    int tid = threadIdx.x;
    int tx = tid & 15, ty = tid >> 4;

    for (int i = tid; i < 64 * 64; i += 256) {
        int r = i >> 6, d = i & 63;
        Qs[r][d] = g_q[((size_t)(b * T_ + q0 + r) * H_ + h) * HD_ + d];
    }

    float m[4], l[4], acc[4][4];
#pragma unroll
    for (int i = 0; i < 4; i++) {
        m[i] = -1e30f; l[i] = 0.f;
#pragma unroll
        for (int j = 0; j < 4; j++) acc[i][j] = 0.f;
    }
    __syncthreads();

    for (int k0 = 0; k0 <= q0 + 32; k0 += 32) {
        for (int i = tid; i < 32 * 64; i += 256) {
            int r = i >> 6, d = i & 63;
            float v = g_k[((size_t)(b * T_ + k0 + r) * H_ + h) * HD_ + d];
            float w = g_v[((size_t)(b * T_ + k0 + r) * H_ + h) * HD_ + d];
            Ks[r][d]  = v;
            VsT[d][r] = w;
        }
        __syncthreads();

        float sv[4][2] = {};
#pragma unroll
        for (int d = 0; d < 64; d++) {
            float a0 = Qs[ty * 4 + 0][d], a1 = Qs[ty * 4 + 1][d];
            float a2 = Qs[ty * 4 + 2][d], a3 = Qs[ty * 4 + 3][d];
            float b0 = Ks[tx * 2 + 0][d], b1 = Ks[tx * 2 + 1][d];
            sv[0][0] += a0 * b0; sv[0][1] += a0 * b1;
            sv[1][0] += a1 * b0; sv[1][1] += a1 * b1;
            sv[2][0] += a2 * b0; sv[2][1] += a2 * b1;
            sv[3][0] += a3 * b0; sv[3][1] += a3 * b1;
        }

#pragma unroll
        for (int i = 0; i < 4; i++) {
            int qi = q0 + ty * 4 + i;
#pragma unroll
            for (int j = 0; j < 2; j++) {
                int ki = k0 + tx * 2 + j;
                sv[i][j] = (ki <= qi) ? sv[i][j] * 0.125f : -1e30f;
            }
            float rm = fmaxf(sv[i][0], sv[i][1]);
            rm = fmaxf(rm, __shfl_xor_sync(0xffffffffu, rm, 8, 16));
            rm = fmaxf(rm, __shfl_xor_sync(0xffffffffu, rm, 4, 16));
            rm = fmaxf(rm, __shfl_xor_sync(0xffffffffu, rm, 2, 16));
            rm = fmaxf(rm, __shfl_xor_sync(0xffffffffu, rm, 1, 16));
            float mn = fmaxf(m[i], rm);
            float corr = __expf(m[i] - mn);
            float p0 = __expf(sv[i][0] - mn);
            float p1 = __expf(sv[i][1] - mn);
            float rs = p0 + p1;
            rs += __shfl_xor_sync(0xffffffffu, rs, 8, 16);
            rs += __shfl_xor_sync(0xffffffffu, rs, 4, 16);
            rs += __shfl_xor_sync(0xffffffffu, rs, 2, 16);
            rs += __shfl_xor_sync(0xffffffffu, rs, 1, 16);
            l[i] = l[i] * corr + rs;
            m[i] = mn;
#pragma unroll
            for (int j = 0; j < 4; j++) acc[i][j] *= corr;
            Ps[ty * 4 + i][tx * 2 + 0] = p0;
            Ps[ty * 4 + i][tx * 2 + 1] = p1;
        }
        __syncwarp();

#pragma unroll
        for (int k = 0; k < 32; k++) {
            float a0 = Ps[ty * 4 + 0][k], a1 = Ps[ty * 4 + 1][k];
            float a2 = Ps[ty * 4 + 2][k], a3 = Ps[ty * 4 + 3][k];
            float b0 = VsT[tx * 4 + 0][k], b1 = VsT[tx * 4 + 1][k];
            float b2 = VsT[tx * 4 + 2][k], b3 = VsT[tx * 4 + 3][k];
            acc[0][0] += a0 * b0; acc[0][1] += a0 * b1; acc[0][2] += a0 * b2; acc[0][3] += a0 * b3;
            acc[1][0] += a1 * b0; acc[1][1] += a1 * b1; acc[1][2] += a1 * b2; acc[1][3] += a1 * b3;
            acc[2][0] += a2 * b0; acc[2][1] += a2 * b1; acc[2][2] += a2 * b2; acc[2][3] += a2 * b3;
            acc[3][0] += a3 * b0; acc[3][1] += a3 * b1; acc[3][2] += a3 * b2; acc[3][3] += a3 * b3;
        }
        __syncthreads();
    }

#pragma unroll
    for (int i = 0; i < 4; i++) {
        float inv = 1.0f / l[i];
        int r = q0 + ty * 4 + i;
#pragma unroll
        for (int j = 0; j < 4; j++)
            g_y[((size_t)(b * T_ + r) * H_ + h) * HD_ + tx * 4 + j] = acc[i][j] * inv;
    }
}

// ---------------- host orchestration ----------------
extern "C" void kernel_launch(void* const* d_in, const int* in_sizes, int n_in,
                              void* d_out, int out_size)
{
    (void)in_sizes; (void)n_in; (void)out_size;
    const int*   idx  = (const int*)  d_in[0];
    const float* cosp = (const float*)d_in[1];
    const float* sinp = (const float*)d_in[2];
    const float* wte  = (const float*)d_in[3];
    const float* vemb = (const float*)d_in[4];
    const float* wd   = (const float*)d_in[5];
    const float* wukv = (const float*)d_in[6];
    const float* wuq  = (const float*)d_in[7];
    const float* vg   = (const float*)d_in[8];
    const float* ap   = (const float*)d_in[9];
    const float* fc   = (const float*)d_in[10];
    const float* pj   = (const float*)d_in[11];
    const float* lr   = (const float*)d_in[12];
    const float* lx   = (const float*)d_in[13];
    const float* lmh  = (const float*)d_in[14];
    float* out = (float*)d_out;

    float *px, *pxn, *pdown, *pkv, *pqpre, *py, *ph;
    cudaGetSymbolAddress((void**)&px,    g_x);
    cudaGetSymbolAddress((void**)&pxn,   g_xn);
    cudaGetSymbolAddress((void**)&pdown, g_down);
    cudaGetSymbolAddress((void**)&pkv,   g_kv);
    cudaGetSymbolAddress((void**)&pqpre, g_qpre);
    cudaGetSymbolAddress((void**)&py,    g_y);
    cudaGetSymbolAddress((void**)&ph,    g_h);

    const int SM128 = 2 * (128 * 128 + 16384);   // 64 KB
    const int SM64  = 2 * (64 * 128 + 16384);    // 48 KB
    cudaFuncSetAttribute(gemm_h3<128>, cudaFuncAttributeMaxDynamicSharedMemorySize, SM128);
    cudaFuncSetAttribute(gemm_h3<64>,  cudaFuncAttributeMaxDynamicSharedMemorySize, SM64);

    embed_kernel<<<NTOK, 256>>>(idx, wte);

    for (int l = 0; l < L_; l++) {
        mix_norm_kernel<<<NTOK, 256>>>(lr, lx, l);

        // down = xn @ wd[l]  [2048,1024]@[1024,544]  (grid 32x5 = 160)
        gemm_h3<64><<<dim3(NTOK / 64, (DOWNW + 127) / 128), 512, SM64>>>(
            pxn, wd + (size_t)l * C_ * DOWNW, pdown, nullptr,
            NTOK, DOWNW, C_, C_, DOWNW, DOWNW, 0);

        // kv = down[:, :256] @ wukv[l]  [2048,256]@[256,1536]  (grid 32x12 = 384)
        gemm_h3<64><<<dim3(NTOK / 64, KVW / 128), 512, SM64>>>(
            pdown, wukv + (size_t)l * DC_ * KVW, pkv, nullptr,
            NTOK, KVW, DC_, DOWNW, KVW, KVW, 0);

        // qpre = down[:, 256:512] @ wuq[l]  [2048,256]@[256,1024]  (grid 32x8 = 256)
        gemm_h3<64><<<dim3(NTOK / 64, C_ / 128), 512, SM64>>>(
            pdown + DC_, wuq + (size_t)l * DC1_ * C_, pqpre, nullptr,
            NTOK, C_, DC1_, DOWNW, C_, C_, 0);

        build_qkv_kernel<<<NTOK, 512>>>(idx, cosp, sinp,
                                        vg + (size_t)l * 32 * H_,
                                        vemb + (size_t)l * V_ * C_);

        attn_kernel<<<dim3(T_ / 64, H_, B_), 256>>>();

        // x += y @ ap[l]  (grid 32x8 = 256)
        gemm_h3<64><<<dim3(NTOK / 64, C_ / 128), 512, SM64>>>(
            py, ap + (size_t)l * C_ * C_, px, px,
            NTOK, C_, C_, C_, C_, C_, 0);

        mix_norm_kernel<<<NTOK, 256>>>(nullptr, nullptr, 0);

        // h = relu(xn @ fc[l])^2  (grid 16x32 = 512)
        gemm_h3<128><<<dim3(NTOK / 128, 4 * C_ / 128), 512, SM128>>>(
            pxn, fc + (size_t)l * C_ * 4 * C_, ph, nullptr,
            NTOK, 4 * C_, C_, C_, 4 * C_, 4 * C_, 2);

        // x += h @ pj[l]  (grid 32x8 = 256)
        gemm_h3<64><<<dim3(NTOK / 64, C_ / 128), 512, SM64>>>(
            ph, pj + (size_t)l * 4 * C_ * C_, px, px,
            NTOK, C_, 4 * C_, 4 * C_, C_, C_, 0);
    }

    mix_norm_kernel<<<NTOK, 256>>>(nullptr, nullptr, 0);
    // out = softcap(xn @ lm_head)  (grid 16x250 = 4000)
    gemm_h3<128><<<dim3(NTOK / 128, V_ / 128), 512, SM128>>>(
        pxn, lmh, out, nullptr,
        NTOK, V_, C_, C_, V_, V_, 1);
}

// round 6
// speedup vs baseline: 1.0620x; 1.0620x over previous
#include <cuda_runtime.h>
#include <cuda_fp16.h>
#include <math.h>
#include <stdint.h>

// ---------------- problem constants ----------------
#define B_    2
#define T_    1024
#define C_    1024
#define H_    16
#define HD_   64
#define DC_   256
#define DC1_  256
#define DR_   32
#define DN_   32
#define V_    32000
#define L_    4
#define NTOK  (B_*T_)             // 2048
#define DOWNW (DC_+DC1_+DR_)      // 544
#define KVW   (H_*(DN_+HD_))      // 1536
#define EPS_  1.1920929e-07f

// ---------------- scratch ----------------
__device__ float g_x   [NTOK*C_];
__device__ float g_x0  [NTOK*C_];
__device__ float g_xn  [NTOK*C_];
__device__ float g_down[NTOK*DOWNW];
__device__ float g_kv  [NTOK*KVW];
__device__ float g_qpre[NTOK*C_];
__device__ float g_q   [NTOK*C_];
__device__ float g_k   [NTOK*C_];
__device__ float g_v   [NTOK*C_];
__device__ float g_y   [NTOK*C_];
__device__ float g_h   [NTOK*4*C_];

// ---------------- helpers ----------------
__device__ __forceinline__ uint32_t smem_u32(const void* p) {
    uint32_t a;
    asm("{ .reg .u64 t; cvta.to.shared.u64 t, %1; cvt.u32.u64 %0, t; }" : "=r"(a) : "l"(p));
    return a;
}
__device__ __forceinline__ float warp_sum(float v) {
    v += __shfl_xor_sync(0xffffffffu, v, 16);
    v += __shfl_xor_sync(0xffffffffu, v, 8);
    v += __shfl_xor_sync(0xffffffffu, v, 4);
    v += __shfl_xor_sync(0xffffffffu, v, 2);
    v += __shfl_xor_sync(0xffffffffu, v, 1);
    return v;
}
__device__ __forceinline__ float block_sum(float v) {
    __shared__ float sh[32];
    int lane = threadIdx.x & 31, wid = threadIdx.x >> 5;
    v = warp_sum(v);
    if (lane == 0) sh[wid] = v;
    __syncthreads();
    int nw = blockDim.x >> 5;
    if (wid == 0) {
        float t = (lane < nw) ? sh[lane] : 0.f;
        t = warp_sum(t);
        if (lane == 0) sh[0] = t;
    }
    __syncthreads();
    return sh[0];
}

// ---------------- mma / ldmatrix wrappers ----------------
__device__ __forceinline__ void ldsm_x4(uint32_t* r, uint32_t addr) {
    asm volatile("ldmatrix.sync.aligned.m8n8.x4.shared.b16 {%0,%1,%2,%3}, [%4];"
                 : "=r"(r[0]), "=r"(r[1]), "=r"(r[2]), "=r"(r[3]) : "r"(addr));
}
__device__ __forceinline__ void ldsm_x4t(uint32_t* r, uint32_t addr) {
    asm volatile("ldmatrix.sync.aligned.m8n8.x4.trans.shared.b16 {%0,%1,%2,%3}, [%4];"
                 : "=r"(r[0]), "=r"(r[1]), "=r"(r[2]), "=r"(r[3]) : "r"(addr));
}
__device__ __forceinline__ void mma16816(float4& d, const uint32_t* a, const uint32_t* b) {
    asm volatile(
        "mma.sync.aligned.m16n8k16.row.col.f32.f16.f16.f32 "
        "{%0,%1,%2,%3},{%4,%5,%6,%7},{%8,%9},{%0,%1,%2,%3};"
        : "+f"(d.x), "+f"(d.y), "+f"(d.z), "+f"(d.w)
        : "r"(a[0]), "r"(a[1]), "r"(a[2]), "r"(a[3]), "r"(b[0]), "r"(b[1]));
}
__device__ __forceinline__ void splith(float x, uint16_t& hi, uint16_t& lo) {
    __half h = __float2half_rn(x);
    float r = x - __half2float(h);
    __half l = __float2half_rn(r);
    hi = __half_as_ushort(h);
    lo = __half_as_ushort(l);
}

// ---------------- embedding + rmsnorm ----------------
__global__ void embed_kernel(const int* __restrict__ idx, const float* __restrict__ wte) {
    int row = blockIdx.x;
    int tok = idx[row];
    const float* src = wte + (size_t)tok * C_;
    float s = 0.f;
    for (int i = threadIdx.x; i < C_; i += blockDim.x) { float v = src[i]; s += v * v; }
    s = block_sum(s);
    float r = rsqrtf(s * (1.0f / C_) + EPS_);
    for (int i = threadIdx.x; i < C_; i += blockDim.x) {
        float v = src[i] * r;
        g_x [(size_t)row * C_ + i] = v;
        g_x0[(size_t)row * C_ + i] = v;
    }
}

__global__ void mix_norm_kernel(const float* lr, const float* lx, int layer) {
    int row = blockIdx.x;
    float a = lr ? lr[layer] : 1.0f;
    float b = lx ? lx[layer] : 0.0f;
    float*       xr  = g_x  + (size_t)row * C_;
    const float* x0r = g_x0 + (size_t)row * C_;
    float s = 0.f;
    for (int i = threadIdx.x; i < C_; i += blockDim.x) {
        float v = a * xr[i] + b * x0r[i];
        xr[i] = v;
        s += v * v;
    }
    s = block_sum(s);
    float r = rsqrtf(s * (1.0f / C_) + EPS_);
    for (int i = threadIdx.x; i < C_; i += blockDim.x)
        g_xn[(size_t)row * C_ + i] = xr[i] * r;
}

// ---------------- 3xFP16 tensor-core GEMM (v3) ----------------
// C[M,N] = A[M,K] @ B[K,N] (+D). mode 0 plain, 1 softcap, 2 relu^2.
// 128x128 CTA tile, 256 thr / 8 warps (2x4), warp tile 64x32, Ktile 32.
// SMEM per stage (32KB):
//   A plane [128 rows][128B]: hi at bytes k*2 (0..63), lo at 64+k*2,
//     swizzle off ^= (off>>3)&0x70.
//   B hi plane [32k][256B], off = k*256+n*2 ^ ((k&7)<<4); lo plane +8192.
// Sequential term processing (hi*hi, hi*lo, lo*hi) keeps <=32 frag regs live.
#define KT3_  32
#define APB3  16384
#define STG3  32768

__global__ __launch_bounds__(256, 1) void gemm_h3(
    const float* __restrict__ A, const float* __restrict__ Bm,
    float* __restrict__ C, const float* __restrict__ D,
    int M, int N, int K, int lda, int ldb, int ldc, int mode)
{
    extern __shared__ __align__(1024) char sm[];
    int tid = threadIdx.x;
    int wid = tid >> 5, lane = tid & 31;
    int warp_m = wid >> 2, warp_n = wid & 3;
    int m0 = blockIdx.x * 128, n0 = blockIdx.y * 128;
    uint32_t smb = smem_u32(sm);

    float4 acc[4][4];
#pragma unroll
    for (int i = 0; i < 4; i++)
#pragma unroll
        for (int j = 0; j < 4; j++) acc[i][j] = make_float4(0.f, 0.f, 0.f, 0.f);

    // fragment address components
    int arow0 = warp_m * 64 + (lane & 15);      // + mi*16
    int akof  = (lane & 16);                    // 0/16 bytes within k-half
    int bkr   = (lane & 15);                    // k row within k16
    int bco   = warp_n * 64 + ((lane >> 4) << 4); // + nj*32

    float4 ar[4], br[4];
    int nk = K / KT3_;

    // ---- producer helpers (inline) ----
    // A tile 128x32: f = tid + r*256 (r<4): m=f>>3, kq=f&7
    // B tile 32x128: f = tid + r*256 (r<4): k=f>>5, nq=f&31
#define LOAD_TILE(ktt) do { \
        const float* Ab_ = A + (size_t)m0 * lda + (ktt) * KT3_; \
        const float* Bb_ = Bm + (size_t)((ktt) * KT3_) * ldb + n0; \
        _Pragma("unroll") \
        for (int r = 0; r < 4; r++) { \
            int v = tid + r * 256; \
            ar[r] = *reinterpret_cast<const float4*>(Ab_ + (size_t)(v >> 3) * lda + (v & 7) * 4); \
        } \
        _Pragma("unroll") \
        for (int r = 0; r < 4; r++) { \
            int v = tid + r * 256; \
            int n_ = (v & 31) * 4; \
            br[r] = (n0 + n_ < N) \
                ? *reinterpret_cast<const float4*>(Bb_ + (size_t)(v >> 5) * ldb + n_) \
                : make_float4(0.f, 0.f, 0.f, 0.f); \
        } \
    } while (0)

#define STORE_TILE(stg) do { \
        char* Ap_ = sm + (stg) * STG3; \
        char* Bh_ = Ap_ + APB3; \
        char* Bl_ = Bh_ + 8192; \
        _Pragma("unroll") \
        for (int r = 0; r < 4; r++) { \
            int v = tid + r * 256; \
            uint16_t h0,l0,h1,l1,h2,l2,h3,l3; \
            splith(ar[r].x,h0,l0); splith(ar[r].y,h1,l1); \
            splith(ar[r].z,h2,l2); splith(ar[r].w,h3,l3); \
            uint32_t oh = (uint32_t)((v >> 3) * 128 + (v & 7) * 8); \
            uint32_t ol = oh + 64; \
            oh ^= (oh >> 3) & 0x70; ol ^= (ol >> 3) & 0x70; \
            *reinterpret_cast<uint2*>(Ap_ + oh) = \
                make_uint2((uint32_t)h0 | ((uint32_t)h1 << 16), (uint32_t)h2 | ((uint32_t)h3 << 16)); \
            *reinterpret_cast<uint2*>(Ap_ + ol) = \
                make_uint2((uint32_t)l0 | ((uint32_t)l1 << 16), (uint32_t)l2 | ((uint32_t)l3 << 16)); \
        } \
        _Pragma("unroll") \
        for (int r = 0; r < 4; r++) { \
            int v = tid + r * 256; \
            uint16_t h0,l0,h1,l1,h2,l2,h3,l3; \
            splith(br[r].x,h0,l0); splith(br[r].y,h1,l1); \
            splith(br[r].z,h2,l2); splith(br[r].w,h3,l3); \
            int k_ = v >> 5; \
            uint32_t off = (uint32_t)(k_ * 256 + (v & 31) * 8) ^ ((uint32_t)(k_ & 7) << 4); \
            *reinterpret_cast<uint2*>(Bh_ + off) = \
                make_uint2((uint32_t)h0 | ((uint32_t)h1 << 16), (uint32_t)h2 | ((uint32_t)h3 << 16)); \
            *reinterpret_cast<uint2*>(Bl_ + off) = \
                make_uint2((uint32_t)l0 | ((uint32_t)l1 << 16), (uint32_t)l2 | ((uint32_t)l3 << 16)); \
        } \
    } while (0)

    // prologue
    LOAD_TILE(0);
    STORE_TILE(0);
    __syncthreads();

    for (int kt = 0; kt < nk; kt++) {
        int p = kt & 1;
        if (kt + 1 < nk) LOAD_TILE(kt + 1);

        uint32_t sA  = smb + p * STG3;
        uint32_t sBh = sA + APB3;
        uint32_t sBl = sBh + 8192;

#pragma unroll
        for (int ks = 0; ks < 2; ks++) {
            uint32_t af[4][4], bh[2][4], bl[2][4];
            // ---- term 1: ahi * bhi ----
#pragma unroll
            for (int mi = 0; mi < 4; mi++) {
                uint32_t oh = (uint32_t)((arow0 + mi * 16) * 128 + ks * 32 + akof);
                oh ^= (oh >> 3) & 0x70;
                ldsm_x4(af[mi], sA + oh);
            }
#pragma unroll
            for (int nj = 0; nj < 2; nj++) {
                int krow = ks * 16 + bkr;
                uint32_t off = (uint32_t)(krow * 256 + bco + nj * 32) ^ ((uint32_t)(krow & 7) << 4);
                ldsm_x4t(bh[nj], sBh + off);
            }
#pragma unroll
            for (int mi = 0; mi < 4; mi++)
#pragma unroll
                for (int ni = 0; ni < 4; ni++)
                    mma16816(acc[mi][ni], af[mi], &bh[ni >> 1][(ni & 1) * 2]);
            // ---- term 2: ahi * blo ----
#pragma unroll
            for (int nj = 0; nj < 2; nj++) {
                int krow = ks * 16 + bkr;
                uint32_t off = (uint32_t)(krow * 256 + bco + nj * 32) ^ ((uint32_t)(krow & 7) << 4);
                ldsm_x4t(bl[nj], sBl + off);
            }
#pragma unroll
            for (int mi = 0; mi < 4; mi++)
#pragma unroll
                for (int ni = 0; ni < 4; ni++)
                    mma16816(acc[mi][ni], af[mi], &bl[ni >> 1][(ni & 1) * 2]);
            // ---- term 3: alo * bhi (overwrite af) ----
#pragma unroll
            for (int mi = 0; mi < 4; mi++) {
                uint32_t ol = (uint32_t)((arow0 + mi * 16) * 128 + ks * 32 + akof + 64);
                ol ^= (ol >> 3) & 0x70;
                ldsm_x4(af[mi], sA + ol);
            }
#pragma unroll
            for (int mi = 0; mi < 4; mi++)
#pragma unroll
                for (int ni = 0; ni < 4; ni++)
                    mma16816(acc[mi][ni], af[mi], &bh[ni >> 1][(ni & 1) * 2]);
        }

        if (kt + 1 < nk) STORE_TILE(p ^ 1);
        __syncthreads();
    }

    // ---- epilogue ----
    int g = lane >> 2, t4 = lane & 3;
#pragma unroll
    for (int mi = 0; mi < 4; mi++) {
        int r0 = m0 + warp_m * 64 + mi * 16 + g;
#pragma unroll
        for (int ni = 0; ni < 4; ni++) {
            int col = n0 + warp_n * 32 + ni * 8 + 2 * t4;
            if (col >= N) continue;
            float4 v = acc[mi][ni];
            if (D) {
                float2 d0 = *reinterpret_cast<const float2*>(D + (size_t)r0 * ldc + col);
                float2 d1 = *reinterpret_cast<const float2*>(D + (size_t)(r0 + 8) * ldc + col);
                v.x += d0.x; v.y += d0.y; v.z += d1.x; v.w += d1.y;
            }
            if (mode == 1) {
                v.x = 15.0f * tanhf(v.x * (1.f / 15.f));
                v.y = 15.0f * tanhf(v.y * (1.f / 15.f));
                v.z = 15.0f * tanhf(v.z * (1.f / 15.f));
                v.w = 15.0f * tanhf(v.w * (1.f / 15.f));
            } else if (mode == 2) {
                v.x = (v.x > 0.f) ? v.x * v.x : 0.f;
                v.y = (v.y > 0.f) ? v.y * v.y : 0.f;
                v.z = (v.z > 0.f) ? v.z * v.z : 0.f;
                v.w = (v.w > 0.f) ? v.w * v.w : 0.f;
            }
            *reinterpret_cast<float2*>(C + (size_t)r0 * ldc + col) = make_float2(v.x, v.y);
            *reinterpret_cast<float2*>(C + (size_t)(r0 + 8) * ldc + col) = make_float2(v.z, v.w);
        }
    }
#undef LOAD_TILE
#undef STORE_TILE
}

// ---------------- per-token q/k/v build ----------------
__global__ void build_qkv_kernel(const int* __restrict__ idx,
                                 const float* __restrict__ cosp, const float* __restrict__ sinp,
                                 const float* __restrict__ vg, const float* __restrict__ vetab)
{
    int row = blockIdx.x;
    int h    = threadIdx.x >> 5;
    int lane = threadIdx.x & 31;
    const float* cosr = cosp + (size_t)row * (DR_ / 2);
    const float* sinr = sinp + (size_t)row * (DR_ / 2);

    float gv = g_xn[(size_t)row * C_ + lane] * vg[lane * H_ + h];
    gv = warp_sum(gv);
    float gate = 2.0f / (1.0f + __expf(-gv));

    int r16 = (lane < 16) ? lane : lane - 16;
    float c = cosr[r16], s = sinr[r16];

    float kn = g_kv[(size_t)row * KVW + h * 96 + lane];
    const float* dro = g_down + (size_t)row * DOWNW + 512;
    float kr = (lane < 16) ? (dro[lane] * c + dro[lane + 16] * s)
                           : (-dro[lane - 16] * s + dro[lane] * c);
    float ssk = warp_sum(kn * kn + kr * kr);
    float rk = rsqrtf(ssk * (1.0f / 64.0f) + EPS_);
    g_k[(size_t)row * C_ + h * 64 + lane]      = kn * rk;
    g_k[(size_t)row * C_ + h * 64 + lane + 32] = kr * rk;

    const float* qp = g_qpre + (size_t)row * C_ + h * 64;
    float qn = qp[lane];
    float qr = (lane < 16) ? (qp[32 + lane] * c + qp[48 + lane] * s)
                           : (-qp[16 + lane] * s + qp[32 + lane] * c);
    float ssq = warp_sum(qn * qn + qr * qr);
    float rq = rsqrtf(ssq * (1.0f / 64.0f) + EPS_);
    g_q[(size_t)row * C_ + h * 64 + lane]      = qn * rq;
    g_q[(size_t)row * C_ + h * 64 + lane + 32] = qr * rq;

    int tok = idx[row];
    const float* ver = vetab + (size_t)tok * C_ + h * 64;
    const float* kvv = g_kv + (size_t)row * KVW + h * 96 + 32;
    g_v[(size_t)row * C_ + h * 64 + lane]      = kvv[lane]      + gate * ver[lane];
    g_v[(size_t)row * C_ + h * 64 + lane + 32] = kvv[lane + 32] + gate * ver[lane + 32];
}

// ---------------- causal flash attention ----------------
__global__ void attn_kernel()
{
    __shared__ float Qs[64][65];
    __shared__ float Ks[32][65];
    __shared__ float VsT[64][33];
    __shared__ float Ps[64][33];

    int q0 = blockIdx.x * 64;
    int h  = blockIdx.y;
    int b  = blockIdx.z;
    int tid = threadIdx.x;
    int tx = tid & 15, ty = tid >> 4;

    for (int i = tid; i < 64 * 64; i += 256) {
        int r = i >> 6, d = i & 63;
        Qs[r][d] = g_q[((size_t)(b * T_ + q0 + r) * H_ + h) * HD_ + d];
    }

    float m[4], l[4], acc[4][4];
#pragma unroll
    for (int i = 0; i < 4; i++) {
        m[i] = -1e30f; l[i] = 0.f;
#pragma unroll
        for (int j = 0; j < 4; j++) acc[i][j] = 0.f;
    }
    __syncthreads();

    for (int k0 = 0; k0 <= q0 + 32; k0 += 32) {
        for (int i = tid; i < 32 * 64; i += 256) {
            int r = i >> 6, d = i & 63;
            float v = g_k[((size_t)(b * T_ + k0 + r) * H_ + h) * HD_ + d];
            float w = g_v[((size_t)(b * T_ + k0 + r) * H_ + h) * HD_ + d];
            Ks[r][d]  = v;
            VsT[d][r] = w;
        }
        __syncthreads();

        float sv[4][2] = {};
#pragma unroll
        for (int d = 0; d < 64; d++) {
            float a0 = Qs[ty * 4 + 0][d], a1 = Qs[ty * 4 + 1][d];
            float a2 = Qs[ty * 4 + 2][d], a3 = Qs[ty * 4 + 3][d];
            float b0 = Ks[tx * 2 + 0][d], b1 = Ks[tx * 2 + 1][d];
            sv[0][0] += a0 * b0; sv[0][1] += a0 * b1;
            sv[1][0] += a1 * b0; sv[1][1] += a1 * b1;
            sv[2][0] += a2 * b0; sv[2][1] += a2 * b1;
            sv[3][0] += a3 * b0; sv[3][1] += a3 * b1;
        }

#pragma unroll
        for (int i = 0; i < 4; i++) {
            int qi = q0 + ty * 4 + i;
#pragma unroll
            for (int j = 0; j < 2; j++) {
                int ki = k0 + tx * 2 + j;
                sv[i][j] = (ki <= qi) ? sv[i][j] * 0.125f : -1e30f;
            }
            float rm = fmaxf(sv[i][0], sv[i][1]);
            rm = fmaxf(rm, __shfl_xor_sync(0xffffffffu, rm, 8, 16));
            rm = fmaxf(rm, __shfl_xor_sync(0xffffffffu, rm, 4, 16));
            rm = fmaxf(rm, __shfl_xor_sync(0xffffffffu, rm, 2, 16));
            rm = fmaxf(rm, __shfl_xor_sync(0xffffffffu, rm, 1, 16));
            float mn = fmaxf(m[i], rm);
            float corr = __expf(m[i] - mn);
            float p0 = __expf(sv[i][0] - mn);
            float p1 = __expf(sv[i][1] - mn);
            float rs = p0 + p1;
            rs += __shfl_xor_sync(0xffffffffu, rs, 8, 16);
            rs += __shfl_xor_sync(0xffffffffu, rs, 4, 16);
            rs += __shfl_xor_sync(0xffffffffu, rs, 2, 16);
            rs += __shfl_xor_sync(0xffffffffu, rs, 1, 16);
            l[i] = l[i] * corr + rs;
            m[i] = mn;
#pragma unroll
            for (int j = 0; j < 4; j++) acc[i][j] *= corr;
            Ps[ty * 4 + i][tx * 2 + 0] = p0;
            Ps[ty * 4 + i][tx * 2 + 1] = p1;
        }
        __syncwarp();

#pragma unroll
        for (int k = 0; k < 32; k++) {
            float a0 = Ps[ty * 4 + 0][k], a1 = Ps[ty * 4 + 1][k];
            float a2 = Ps[ty * 4 + 2][k], a3 = Ps[ty * 4 + 3][k];
            float b0 = VsT[tx * 4 + 0][k], b1 = VsT[tx * 4 + 1][k];
            float b2 = VsT[tx * 4 + 2][k], b3 = VsT[tx * 4 + 3][k];
            acc[0][0] += a0 * b0; acc[0][1] += a0 * b1; acc[0][2] += a0 * b2; acc[0][3] += a0 * b3;
            acc[1][0] += a1 * b0; acc[1][1] += a1 * b1; acc[1][2] += a1 * b2; acc[1][3] += a1 * b3;
            acc[2][0] += a2 * b0; acc[2][1] += a2 * b1; acc[2][2] += a2 * b2; acc[2][3] += a2 * b3;
            acc[3][0] += a3 * b0; acc[3][1] += a3 * b1; acc[3][2] += a3 * b2; acc[3][3] += a3 * b3;
        }
        __syncthreads();
    }

#pragma unroll
    for (int i = 0; i < 4; i++) {
        float inv = 1.0f / l[i];
        int r = q0 + ty * 4 + i;
#pragma unroll
        for (int j = 0; j < 4; j++)
            g_y[((size_t)(b * T_ + r) * H_ + h) * HD_ + tx * 4 + j] = acc[i][j] * inv;
    }
}

// ---------------- host orchestration ----------------
extern "C" void kernel_launch(void* const* d_in, const int* in_sizes, int n_in,
                              void* d_out, int out_size)
{
    (void)in_sizes; (void)n_in; (void)out_size;
    const int*   idx  = (const int*)  d_in[0];
    const float* cosp = (const float*)d_in[1];
    const float* sinp = (const float*)d_in[2];
    const float* wte  = (const float*)d_in[3];
    const float* vemb = (const float*)d_in[4];
    const float* wd   = (const float*)d_in[5];
    const float* wukv = (const float*)d_in[6];
    const float* wuq  = (const float*)d_in[7];
    const float* vg   = (const float*)d_in[8];
    const float* ap   = (const float*)d_in[9];
    const float* fc   = (const float*)d_in[10];
    const float* pj   = (const float*)d_in[11];
    const float* lr   = (const float*)d_in[12];
    const float* lx   = (const float*)d_in[13];
    const float* lmh  = (const float*)d_in[14];
    float* out = (float*)d_out;

    float *px, *pxn, *pdown, *pkv, *pqpre, *py, *ph;
    cudaGetSymbolAddress((void**)&px,    g_x);
    cudaGetSymbolAddress((void**)&pxn,   g_xn);
    cudaGetSymbolAddress((void**)&pdown, g_down);
    cudaGetSymbolAddress((void**)&pkv,   g_kv);
    cudaGetSymbolAddress((void**)&pqpre, g_qpre);
    cudaGetSymbolAddress((void**)&py,    g_y);
    cudaGetSymbolAddress((void**)&ph,    g_h);

    const int SMEMSZ = 2 * STG3;   // 64 KB
    cudaFuncSetAttribute(gemm_h3, cudaFuncAttributeMaxDynamicSharedMemorySize, SMEMSZ);

    const int GM = NTOK / 128;     // 16 m-blocks

    embed_kernel<<<NTOK, 256>>>(idx, wte);

    for (int l = 0; l < L_; l++) {
        mix_norm_kernel<<<NTOK, 256>>>(lr, lx, l);

        // down = xn @ wd[l]  [2048,1024]@[1024,544]
        gemm_h3<<<dim3(GM, (DOWNW + 127) / 128), 256, SMEMSZ>>>(
            pxn, wd + (size_t)l * C_ * DOWNW, pdown, nullptr,
            NTOK, DOWNW, C_, C_, DOWNW, DOWNW, 0);

        // kv = down[:, :256] @ wukv[l]  [2048,256]@[256,1536]
        gemm_h3<<<dim3(GM, KVW / 128), 256, SMEMSZ>>>(
            pdown, wukv + (size_t)l * DC_ * KVW, pkv, nullptr,
            NTOK, KVW, DC_, DOWNW, KVW, KVW, 0);

        // qpre = down[:, 256:512] @ wuq[l]  [2048,256]@[256,1024]
        gemm_h3<<<dim3(GM, C_ / 128), 256, SMEMSZ>>>(
            pdown + DC_, wuq + (size_t)l * DC1_ * C_, pqpre, nullptr,
            NTOK, C_, DC1_, DOWNW, C_, C_, 0);

        build_qkv_kernel<<<NTOK, 512>>>(idx, cosp, sinp,
                                        vg + (size_t)l * 32 * H_,
                                        vemb + (size_t)l * V_ * C_);

        attn_kernel<<<dim3(T_ / 64, H_, B_), 256>>>();

        // x += y @ ap[l]
        gemm_h3<<<dim3(GM, C_ / 128), 256, SMEMSZ>>>(
            py, ap + (size_t)l * C_ * C_, px, px,
            NTOK, C_, C_, C_, C_, C_, 0);

        mix_norm_kernel<<<NTOK, 256>>>(nullptr, nullptr, 0);

        // h = relu(xn @ fc[l])^2
        gemm_h3<<<dim3(GM, 4 * C_ / 128), 256, SMEMSZ>>>(
            pxn, fc + (size_t)l * C_ * 4 * C_, ph, nullptr,
            NTOK, 4 * C_, C_, C_, 4 * C_, 4 * C_, 2);

        // x += h @ pj[l]
        gemm_h3<<<dim3(GM, C_ / 128), 256, SMEMSZ>>>(
            ph, pj + (size_t)l * 4 * C_ * C_, px, px,
            NTOK, C_, 4 * C_, 4 * C_, C_, C_, 0);
    }

    mix_norm_kernel<<<NTOK, 256>>>(nullptr, nullptr, 0);
    // out = softcap(xn @ lm_head)
    gemm_h3<<<dim3(GM, V_ / 128), 256, SMEMSZ>>>(
        pxn, lmh, out, nullptr,
        NTOK, V_, C_, C_, V_, V_, 1);
}

// round 7
// speedup vs baseline: 1.3398x; 1.2617x over previous
#include <cuda_runtime.h>
#include <cuda_fp16.h>
#include <math.h>
#include <stdint.h>

// ---------------- problem constants ----------------
#define B_    2
#define T_    1024
#define C_    1024
#define H_    16
#define HD_   64
#define DC_   256
#define DC1_  256
#define DR_   32
#define DN_   32
#define V_    32000
#define L_    4
#define NTOK  (B_*T_)             // 2048
#define DOWNW (DC_+DC1_+DR_)      // 544
#define WDP   640                 // padded wd output width
#define KVW   (H_*(DN_+HD_))      // 1536
#define EPS_  1.1920929e-07f

// ---------------- fp32 scratch ----------------
__device__ float g_x   [NTOK*C_];
__device__ float g_x0  [NTOK*C_];
__device__ float g_xn  [NTOK*C_];
__device__ float g_down[NTOK*DOWNW];
__device__ float g_kv  [NTOK*KVW];
__device__ float g_qpre[NTOK*C_];
__device__ float g_q   [NTOK*C_];
__device__ float g_k   [NTOK*C_];
__device__ float g_v   [NTOK*C_];

// ---------------- fp16 hi/lo planes ----------------
// weights (split once per launch)
__device__ __half g_wd_h  [L_*C_*WDP],    g_wd_l  [L_*C_*WDP];
__device__ __half g_wukv_h[L_*DC_*KVW],   g_wukv_l[L_*DC_*KVW];
__device__ __half g_wuq_h [L_*DC1_*C_],   g_wuq_l [L_*DC1_*C_];
__device__ __half g_ap_h  [L_*C_*C_],     g_ap_l  [L_*C_*C_];
__device__ __half g_fc_h  [L_*C_*4*C_],   g_fc_l  [L_*C_*4*C_];
__device__ __half g_pj_h  [L_*4*C_*C_],   g_pj_l  [L_*4*C_*C_];
__device__ __half g_lmh_h [C_*V_],        g_lmh_l [C_*V_];
// activations (split at producers)
__device__ __half g_xn_h  [NTOK*C_],      g_xn_l  [NTOK*C_];
__device__ __half g_dn_h  [NTOK*DOWNW],   g_dn_l  [NTOK*DOWNW];
__device__ __half g_y_h   [NTOK*C_],      g_y_l   [NTOK*C_];
__device__ __half g_h_h   [NTOK*4*C_],    g_h_l   [NTOK*4*C_];

// ---------------- helpers ----------------
__device__ __forceinline__ uint32_t smem_u32(const void* p) {
    uint32_t a;
    asm("{ .reg .u64 t; cvta.to.shared.u64 t, %1; cvt.u32.u64 %0, t; }" : "=r"(a) : "l"(p));
    return a;
}
__device__ __forceinline__ float warp_sum(float v) {
    v += __shfl_xor_sync(0xffffffffu, v, 16);
    v += __shfl_xor_sync(0xffffffffu, v, 8);
    v += __shfl_xor_sync(0xffffffffu, v, 4);
    v += __shfl_xor_sync(0xffffffffu, v, 2);
    v += __shfl_xor_sync(0xffffffffu, v, 1);
    return v;
}
__device__ __forceinline__ float block_sum(float v) {
    __shared__ float sh[32];
    int lane = threadIdx.x & 31, wid = threadIdx.x >> 5;
    v = warp_sum(v);
    if (lane == 0) sh[wid] = v;
    __syncthreads();
    int nw = blockDim.x >> 5;
    if (wid == 0) {
        float t = (lane < nw) ? sh[lane] : 0.f;
        t = warp_sum(t);
        if (lane == 0) sh[0] = t;
    }
    __syncthreads();
    return sh[0];
}
__device__ __forceinline__ void splith(float x, __half& hi, __half& lo) {
    hi = __float2half_rn(x);
    lo = __float2half_rn(x - __half2float(hi));
}

// ---------------- mma / ldmatrix / cp.async wrappers ----------------
__device__ __forceinline__ void ldsm_x4(uint32_t* r, uint32_t addr) {
    asm volatile("ldmatrix.sync.aligned.m8n8.x4.shared.b16 {%0,%1,%2,%3}, [%4];"
                 : "=r"(r[0]), "=r"(r[1]), "=r"(r[2]), "=r"(r[3]) : "r"(addr));
}
__device__ __forceinline__ void ldsm_x4t(uint32_t* r, uint32_t addr) {
    asm volatile("ldmatrix.sync.aligned.m8n8.x4.trans.shared.b16 {%0,%1,%2,%3}, [%4];"
                 : "=r"(r[0]), "=r"(r[1]), "=r"(r[2]), "=r"(r[3]) : "r"(addr));
}
__device__ __forceinline__ void mma16816(float4& d, const uint32_t* a, const uint32_t* b) {
    asm volatile(
        "mma.sync.aligned.m16n8k16.row.col.f32.f16.f16.f32 "
        "{%0,%1,%2,%3},{%4,%5,%6,%7},{%8,%9},{%0,%1,%2,%3};"
        : "+f"(d.x), "+f"(d.y), "+f"(d.z), "+f"(d.w)
        : "r"(a[0]), "r"(a[1]), "r"(a[2]), "r"(a[3]), "r"(b[0]), "r"(b[1]));
}
#define CP16(dst, src) \
    asm volatile("cp.async.cg.shared.global [%0], [%1], 16;" :: "r"(dst), "l"(src) : "memory")
#define CPCOMMIT() asm volatile("cp.async.commit_group;" ::: "memory")
#define CPWAITG(n) asm volatile("cp.async.wait_group " #n ";" ::: "memory")

// ---------------- weight split: fp32 [R][Cs] -> fp16 hi/lo [R][Cd] --------
__global__ void wsplit_kernel(const float* __restrict__ src,
                              __half* __restrict__ hi, __half* __restrict__ lo,
                              int Cs, int Cd, long total)
{
    long stride = (long)gridDim.x * blockDim.x;
    for (long i = (long)blockIdx.x * blockDim.x + threadIdx.x; i < total; i += stride) {
        float v;
        if (Cs == Cd) {
            v = src[i];
        } else {
            long r = i / Cd;
            int  c = (int)(i - r * Cd);
            v = (c < Cs) ? src[r * Cs + c] : 0.f;
        }
        __half h, l;
        splith(v, h, l);
        hi[i] = h; lo[i] = l;
    }
}

// ---------------- embedding + rmsnorm ----------------
__global__ void embed_kernel(const int* __restrict__ idx, const float* __restrict__ wte) {
    int row = blockIdx.x;
    int tok = idx[row];
    const float* src = wte + (size_t)tok * C_;
    float s = 0.f;
    for (int i = threadIdx.x; i < C_; i += blockDim.x) { float v = src[i]; s += v * v; }
    s = block_sum(s);
    float r = rsqrtf(s * (1.0f / C_) + EPS_);
    for (int i = threadIdx.x; i < C_; i += blockDim.x) {
        float v = src[i] * r;
        g_x [(size_t)row * C_ + i] = v;
        g_x0[(size_t)row * C_ + i] = v;
    }
}

// x = a*x + b*x0; xn = rmsnorm(x) (fp32 + fp16 planes)
__global__ void mix_norm_kernel(const float* lr, const float* lx, int layer) {
    int row = blockIdx.x;
    float a = lr ? lr[layer] : 1.0f;
    float b = lx ? lx[layer] : 0.0f;
    float*       xr  = g_x  + (size_t)row * C_;
    const float* x0r = g_x0 + (size_t)row * C_;
    float s = 0.f;
    for (int i = threadIdx.x; i < C_; i += blockDim.x) {
        float v = a * xr[i] + b * x0r[i];
        xr[i] = v;
        s += v * v;
    }
    s = block_sum(s);
    float r = rsqrtf(s * (1.0f / C_) + EPS_);
    for (int i = threadIdx.x; i < C_; i += blockDim.x) {
        float v = xr[i] * r;
        g_xn[(size_t)row * C_ + i] = v;
        __half h, l;
        splith(v, h, l);
        g_xn_h[(size_t)row * C_ + i] = h;
        g_xn_l[(size_t)row * C_ + i] = l;
    }
}

// ---------------- 3xFP16 tensor-core GEMM v4 (cp.async, pre-split) --------
// C[M,N] = A @ B (+D). mode 0 plain, 1 softcap, 2 relu^2.
// A given as hi/lo fp16 planes [M][lda]; B as hi/lo planes [K][ldb] (padded,
// so no bounds checks on loads). Optional Chi/Clo fp16 plane output [M][ldp].
// 128x128 CTA, 256 thr / 8 warps (2x4), warp tile 64x32, Ktile 32, 3 stages.
// Stage layout (32KB): A rows [128][128B] (hi 0-63 | lo 64-127, SW128 xor),
//                      B hi [32][256B] ^((k&7)<<4) at +16384, lo at +24576.
#define STG4 32768

__global__ __launch_bounds__(256, 2) void gemm_h4(
    const __half* __restrict__ Ah, const __half* __restrict__ Al,
    const __half* __restrict__ Bh, const __half* __restrict__ Bl,
    float* __restrict__ C, const float* __restrict__ D,
    __half* __restrict__ Chi, __half* __restrict__ Clo,
    int N, int K, int lda, int ldb, int ldc, int ldp, int mode)
{
    extern __shared__ __align__(1024) char sm[];
    int tid = threadIdx.x;
    int wid = tid >> 5, lane = tid & 31;
    int warp_m = wid >> 2, warp_n = wid & 3;
    int m0 = blockIdx.x * 128, n0 = blockIdx.y * 128;
    uint32_t smb = smem_u32(sm);

    float4 acc[4][4];
#pragma unroll
    for (int i = 0; i < 4; i++)
#pragma unroll
        for (int j = 0; j < 4; j++) acc[i][j] = make_float4(0.f, 0.f, 0.f, 0.f);

    // producer thread mapping (constant per thread)
    int a_m   = tid >> 3;            // +r*32, r<4
    int a_hl  = (tid >> 2) & 1;      // 0 hi, 1 lo
    int a_j   = tid & 3;
    int b_k0  = tid >> 4;            // +16*(r&1)
    int b_j   = tid & 15;
    const __half* Asel = a_hl ? Al : Ah;

    // consumer fragment addressing
    int arow0 = warp_m * 64 + (lane & 15);
    int akof  = (lane & 16);
    int bkr   = (lane & 15);
    int bco   = warp_n * 64 + ((lane >> 4) << 4);

    int nk = K >> 5;

    // ---- stage issue ----
    auto issue = [&](int kt, int stg) {
        uint32_t sA = smb + stg * STG4;
        uint32_t sB = sA + 16384;
#pragma unroll
        for (int r = 0; r < 4; r++) {
            int m = a_m + r * 32;
            uint32_t off = (uint32_t)(m * 128 + a_hl * 64 + a_j * 16);
            off ^= (off >> 3) & 0x70;
            const __half* src = Asel + (size_t)(m0 + m) * lda + kt * 32 + a_j * 8;
            CP16(sA + off, src);
        }
#pragma unroll
        for (int r = 0; r < 4; r++) {
            int k = b_k0 + (r & 1) * 16;
            const __half* Bp = (r < 2) ? Bh : Bl;
            uint32_t off = ((uint32_t)(k * 256 + b_j * 16)) ^ ((uint32_t)(k & 7) << 4);
            off += (r < 2) ? 0u : 8192u;
            const __half* src = Bp + (size_t)(kt * 32 + k) * ldb + n0 + b_j * 8;
            CP16(sB + off, src);
        }
        CPCOMMIT();
    };

    issue(0, 0);
    issue(1, 1);
    issue(2, 2);

    for (int kt = 0; kt < nk; kt++) {
        int s = kt % 3;
        if (kt == nk - 1) { CPWAITG(0); } else { CPWAITG(2); }
        __syncthreads();

        uint32_t sA  = smb + s * STG4;
        uint32_t sBh = sA + 16384;
        uint32_t sBl = sA + 24576;
#pragma unroll
        for (int ks = 0; ks < 2; ks++) {
            uint32_t af[4][4], bh[2][4], bl[2][4];
            // term 1: ahi * bhi
#pragma unroll
            for (int mi = 0; mi < 4; mi++) {
                uint32_t oh = (uint32_t)((arow0 + mi * 16) * 128 + ks * 32 + akof);
                oh ^= (oh >> 3) & 0x70;
                ldsm_x4(af[mi], sA + oh);
            }
#pragma unroll
            for (int nj = 0; nj < 2; nj++) {
                int krow = ks * 16 + bkr;
                uint32_t off = (uint32_t)(krow * 256 + bco + nj * 32) ^ ((uint32_t)(krow & 7) << 4);
                ldsm_x4t(bh[nj], sBh + off);
            }
#pragma unroll
            for (int mi = 0; mi < 4; mi++)
#pragma unroll
                for (int ni = 0; ni < 4; ni++)
                    mma16816(acc[mi][ni], af[mi], &bh[ni >> 1][(ni & 1) * 2]);
            // term 2: ahi * blo
#pragma unroll
            for (int nj = 0; nj < 2; nj++) {
                int krow = ks * 16 + bkr;
                uint32_t off = (uint32_t)(krow * 256 + bco + nj * 32) ^ ((uint32_t)(krow & 7) << 4);
                ldsm_x4t(bl[nj], sBl + off);
            }
#pragma unroll
            for (int mi = 0; mi < 4; mi++)
#pragma unroll
                for (int ni = 0; ni < 4; ni++)
                    mma16816(acc[mi][ni], af[mi], &bl[ni >> 1][(ni & 1) * 2]);
            // term 3: alo * bhi (reuse af regs)
#pragma unroll
            for (int mi = 0; mi < 4; mi++) {
                uint32_t ol = (uint32_t)((arow0 + mi * 16) * 128 + ks * 32 + akof + 64);
                ol ^= (ol >> 3) & 0x70;
                ldsm_x4(af[mi], sA + ol);
            }
#pragma unroll
            for (int mi = 0; mi < 4; mi++)
#pragma unroll
                for (int ni = 0; ni < 4; ni++)
                    mma16816(acc[mi][ni], af[mi], &bh[ni >> 1][(ni & 1) * 2]);
        }
        __syncthreads();
        if (kt + 3 < nk) issue(kt + 3, s);
    }

    // ---- epilogue ----
    int g = lane >> 2, t4 = lane & 3;
#pragma unroll
    for (int mi = 0; mi < 4; mi++) {
        int r0 = m0 + warp_m * 64 + mi * 16 + g;
#pragma unroll
        for (int ni = 0; ni < 4; ni++) {
            int col = n0 + warp_n * 32 + ni * 8 + 2 * t4;
            if (col >= N) continue;
            float4 v = acc[mi][ni];
            if (D) {
                float2 d0 = *reinterpret_cast<const float2*>(D + (size_t)r0 * ldc + col);
                float2 d1 = *reinterpret_cast<const float2*>(D + (size_t)(r0 + 8) * ldc + col);
                v.x += d0.x; v.y += d0.y; v.z += d1.x; v.w += d1.y;
            }
            if (mode == 1) {
                v.x = 15.0f * tanhf(v.x * (1.f / 15.f));
                v.y = 15.0f * tanhf(v.y * (1.f / 15.f));
                v.z = 15.0f * tanhf(v.z * (1.f / 15.f));
                v.w = 15.0f * tanhf(v.w * (1.f / 15.f));
            } else if (mode == 2) {
                v.x = (v.x > 0.f) ? v.x * v.x : 0.f;
                v.y = (v.y > 0.f) ? v.y * v.y : 0.f;
                v.z = (v.z > 0.f) ? v.z * v.z : 0.f;
                v.w = (v.w > 0.f) ? v.w * v.w : 0.f;
            }
            if (C) {
                *reinterpret_cast<float2*>(C + (size_t)r0 * ldc + col) = make_float2(v.x, v.y);
                *reinterpret_cast<float2*>(C + (size_t)(r0 + 8) * ldc + col) = make_float2(v.z, v.w);
            }
            if (Chi) {
                __half hx, lx_, hy, ly, hz, lz, hw, lw;
                splith(v.x, hx, lx_); splith(v.y, hy, ly);
                splith(v.z, hz, lz);  splith(v.w, hw, lw);
                uint32_t ph0 = (uint32_t)__half_as_ushort(hx) | ((uint32_t)__half_as_ushort(hy) << 16);
                uint32_t pl0 = (uint32_t)__half_as_ushort(lx_) | ((uint32_t)__half_as_ushort(ly) << 16);
                uint32_t ph1 = (uint32_t)__half_as_ushort(hz) | ((uint32_t)__half_as_ushort(hw) << 16);
                uint32_t pl1 = (uint32_t)__half_as_ushort(lz) | ((uint32_t)__half_as_ushort(lw) << 16);
                *reinterpret_cast<uint32_t*>(Chi + (size_t)r0 * ldp + col)       = ph0;
                *reinterpret_cast<uint32_t*>(Clo + (size_t)r0 * ldp + col)       = pl0;
                *reinterpret_cast<uint32_t*>(Chi + (size_t)(r0 + 8) * ldp + col) = ph1;
                *reinterpret_cast<uint32_t*>(Clo + (size_t)(r0 + 8) * ldp + col) = pl1;
            }
        }
    }
}

// ---------------- per-token q/k/v build ----------------
__global__ void build_qkv_kernel(const int* __restrict__ idx,
                                 const float* __restrict__ cosp, const float* __restrict__ sinp,
                                 const float* __restrict__ vg, const float* __restrict__ vetab)
{
    int row = blockIdx.x;
    int h    = threadIdx.x >> 5;
    int lane = threadIdx.x & 31;
    const float* cosr = cosp + (size_t)row * (DR_ / 2);
    const float* sinr = sinp + (size_t)row * (DR_ / 2);

    float gv = g_xn[(size_t)row * C_ + lane] * vg[lane * H_ + h];
    gv = warp_sum(gv);
    float gate = 2.0f / (1.0f + __expf(-gv));

    int r16 = (lane < 16) ? lane : lane - 16;
    float c = cosr[r16], s = sinr[r16];

    float kn = g_kv[(size_t)row * KVW + h * 96 + lane];
    const float* dro = g_down + (size_t)row * DOWNW + 512;
    float kr = (lane < 16) ? (dro[lane] * c + dro[lane + 16] * s)
                           : (-dro[lane - 16] * s + dro[lane] * c);
    float ssk = warp_sum(kn * kn + kr * kr);
    float rk = rsqrtf(ssk * (1.0f / 64.0f) + EPS_);
    g_k[(size_t)row * C_ + h * 64 + lane]      = kn * rk;
    g_k[(size_t)row * C_ + h * 64 + lane + 32] = kr * rk;

    const float* qp = g_qpre + (size_t)row * C_ + h * 64;
    float qn = qp[lane];
    float qr = (lane < 16) ? (qp[32 + lane] * c + qp[48 + lane] * s)
                           : (-qp[16 + lane] * s + qp[32 + lane] * c);
    float ssq = warp_sum(qn * qn + qr * qr);
    float rq = rsqrtf(ssq * (1.0f / 64.0f) + EPS_);
    g_q[(size_t)row * C_ + h * 64 + lane]      = qn * rq;
    g_q[(size_t)row * C_ + h * 64 + lane + 32] = qr * rq;

    int tok = idx[row];
    const float* ver = vetab + (size_t)tok * C_ + h * 64;
    const float* kvv = g_kv + (size_t)row * KVW + h * 96 + 32;
    g_v[(size_t)row * C_ + h * 64 + lane]      = kvv[lane]      + gate * ver[lane];
    g_v[(size_t)row * C_ + h * 64 + lane + 32] = kvv[lane + 32] + gate * ver[lane + 32];
}

// ---------------- causal flash attention (writes y hi/lo planes) ----------
__global__ void attn_kernel()
{
    __shared__ float Qs[64][65];
    __shared__ float Ks[32][65];
    __shared__ float VsT[64][33];
    __shared__ float Ps[64][33];

    int q0 = blockIdx.x * 64;
    int hh = blockIdx.y;
    int b  = blockIdx.z;
    int tid = threadIdx.x;
    int tx = tid & 15, ty = tid >> 4;

    for (int i = tid; i < 64 * 64; i += 256) {
        int r = i >> 6, d = i & 63;
        Qs[r][d] = g_q[((size_t)(b * T_ + q0 + r) * H_ + hh) * HD_ + d];
    }

    float m[4], l[4], acc[4][4];
#pragma unroll
    for (int i = 0; i < 4; i++) {
        m[i] = -1e30f; l[i] = 0.f;
#pragma unroll
        for (int j = 0; j < 4; j++) acc[i][j] = 0.f;
    }
    __syncthreads();

    for (int k0 = 0; k0 <= q0 + 32; k0 += 32) {
        for (int i = tid; i < 32 * 64; i += 256) {
            int r = i >> 6, d = i & 63;
            float v = g_k[((size_t)(b * T_ + k0 + r) * H_ + hh) * HD_ + d];
            float w = g_v[((size_t)(b * T_ + k0 + r) * H_ + hh) * HD_ + d];
            Ks[r][d]  = v;
            VsT[d][r] = w;
        }
        __syncthreads();

        float sv[4][2] = {};
#pragma unroll
        for (int d = 0; d < 64; d++) {
            float a0 = Qs[ty * 4 + 0][d], a1 = Qs[ty * 4 + 1][d];
            float a2 = Qs[ty * 4 + 2][d], a3 = Qs[ty * 4 + 3][d];
            float b0 = Ks[tx * 2 + 0][d], b1 = Ks[tx * 2 + 1][d];
            sv[0][0] += a0 * b0; sv[0][1] += a0 * b1;
            sv[1][0] += a1 * b0; sv[1][1] += a1 * b1;
            sv[2][0] += a2 * b0; sv[2][1] += a2 * b1;
            sv[3][0] += a3 * b0; sv[3][1] += a3 * b1;
        }

#pragma unroll
        for (int i = 0; i < 4; i++) {
            int qi = q0 + ty * 4 + i;
#pragma unroll
            for (int j = 0; j < 2; j++) {
                int ki = k0 + tx * 2 + j;
                sv[i][j] = (ki <= qi) ? sv[i][j] * 0.125f : -1e30f;
            }
            float rm = fmaxf(sv[i][0], sv[i][1]);
            rm = fmaxf(rm, __shfl_xor_sync(0xffffffffu, rm, 8, 16));
            rm = fmaxf(rm, __shfl_xor_sync(0xffffffffu, rm, 4, 16));
            rm = fmaxf(rm, __shfl_xor_sync(0xffffffffu, rm, 2, 16));
            rm = fmaxf(rm, __shfl_xor_sync(0xffffffffu, rm, 1, 16));
            float mn = fmaxf(m[i], rm);
            float corr = __expf(m[i] - mn);
            float p0 = __expf(sv[i][0] - mn);
            float p1 = __expf(sv[i][1] - mn);
            float rs = p0 + p1;
            rs += __shfl_xor_sync(0xffffffffu, rs, 8, 16);
            rs += __shfl_xor_sync(0xffffffffu, rs, 4, 16);
            rs += __shfl_xor_sync(0xffffffffu, rs, 2, 16);
            rs += __shfl_xor_sync(0xffffffffu, rs, 1, 16);
            l[i] = l[i] * corr + rs;
            m[i] = mn;
#pragma unroll
            for (int j = 0; j < 4; j++) acc[i][j] *= corr;
            Ps[ty * 4 + i][tx * 2 + 0] = p0;
            Ps[ty * 4 + i][tx * 2 + 1] = p1;
        }
        __syncwarp();

#pragma unroll
        for (int k = 0; k < 32; k++) {
            float a0 = Ps[ty * 4 + 0][k], a1 = Ps[ty * 4 + 1][k];
            float a2 = Ps[ty * 4 + 2][k], a3 = Ps[ty * 4 + 3][k];
            float b0 = VsT[tx * 4 + 0][k], b1 = VsT[tx * 4 + 1][k];
            float b2 = VsT[tx * 4 + 2][k], b3 = VsT[tx * 4 + 3][k];
            acc[0][0] += a0 * b0; acc[0][1] += a0 * b1; acc[0][2] += a0 * b2; acc[0][3] += a0 * b3;
            acc[1][0] += a1 * b0; acc[1][1] += a1 * b1; acc[1][2] += a1 * b2; acc[1][3] += a1 * b3;
            acc[2][0] += a2 * b0; acc[2][1] += a2 * b1; acc[2][2] += a2 * b2; acc[2][3] += a2 * b3;
            acc[3][0] += a3 * b0; acc[3][1] += a3 * b1; acc[3][2] += a3 * b2; acc[3][3] += a3 * b3;
        }
        __syncthreads();
    }

#pragma unroll
    for (int i = 0; i < 4; i++) {
        float inv = 1.0f / l[i];
        int r = q0 + ty * 4 + i;
        size_t rowoff = (size_t)(b * T_ + r) * C_ + hh * 64;
#pragma unroll
        for (int j = 0; j < 4; j++) {
            float o = acc[i][j] * inv;
            __half h, lo;
            splith(o, h, lo);
            g_y_h[rowoff + tx * 4 + j] = h;
            g_y_l[rowoff + tx * 4 + j] = lo;
        }
    }
}

// ---------------- host orchestration ----------------
extern "C" void kernel_launch(void* const* d_in, const int* in_sizes, int n_in,
                              void* d_out, int out_size)
{
    (void)in_sizes; (void)n_in; (void)out_size;
    const int*   idx  = (const int*)  d_in[0];
    const float* cosp = (const float*)d_in[1];
    const float* sinp = (const float*)d_in[2];
    const float* wte  = (const float*)d_in[3];
    const float* vemb = (const float*)d_in[4];
    const float* wd   = (const float*)d_in[5];
    const float* wukv = (const float*)d_in[6];
    const float* wuq  = (const float*)d_in[7];
    const float* vg   = (const float*)d_in[8];
    const float* ap   = (const float*)d_in[9];
    const float* fc   = (const float*)d_in[10];
    const float* pj   = (const float*)d_in[11];
    const float* lr   = (const float*)d_in[12];
    const float* lx   = (const float*)d_in[13];
    const float* lmh  = (const float*)d_in[14];
    float* out = (float*)d_out;

    float *px, *pdown, *pkv, *pqpre;
    cudaGetSymbolAddress((void**)&px,    g_x);
    cudaGetSymbolAddress((void**)&pdown, g_down);
    cudaGetSymbolAddress((void**)&pkv,   g_kv);
    cudaGetSymbolAddress((void**)&pqpre, g_qpre);

    __half *wd_h, *wd_l, *wukv_h, *wukv_l, *wuq_h, *wuq_l, *ap_h, *ap_l;
    __half *fc_h, *fc_l, *pj_h, *pj_l, *lmh_h, *lmh_l;
    __half *xn_h, *xn_l, *dn_h, *dn_l, *y_h, *y_l, *h_h, *h_l;
    cudaGetSymbolAddress((void**)&wd_h,   g_wd_h);   cudaGetSymbolAddress((void**)&wd_l,   g_wd_l);
    cudaGetSymbolAddress((void**)&wukv_h, g_wukv_h); cudaGetSymbolAddress((void**)&wukv_l, g_wukv_l);
    cudaGetSymbolAddress((void**)&wuq_h,  g_wuq_h);  cudaGetSymbolAddress((void**)&wuq_l,  g_wuq_l);
    cudaGetSymbolAddress((void**)&ap_h,   g_ap_h);   cudaGetSymbolAddress((void**)&ap_l,   g_ap_l);
    cudaGetSymbolAddress((void**)&fc_h,   g_fc_h);   cudaGetSymbolAddress((void**)&fc_l,   g_fc_l);
    cudaGetSymbolAddress((void**)&pj_h,   g_pj_h);   cudaGetSymbolAddress((void**)&pj_l,   g_pj_l);
    cudaGetSymbolAddress((void**)&lmh_h,  g_lmh_h);  cudaGetSymbolAddress((void**)&lmh_l,  g_lmh_l);
    cudaGetSymbolAddress((void**)&xn_h,   g_xn_h);   cudaGetSymbolAddress((void**)&xn_l,   g_xn_l);
    cudaGetSymbolAddress((void**)&dn_h,   g_dn_h);   cudaGetSymbolAddress((void**)&dn_l,   g_dn_l);
    cudaGetSymbolAddress((void**)&y_h,    g_y_h);    cudaGetSymbolAddress((void**)&y_l,    g_y_l);
    cudaGetSymbolAddress((void**)&h_h,    g_h_h);    cudaGetSymbolAddress((void**)&h_l,    g_h_l);

    const int SMEMSZ = 3 * STG4;   // 96 KB
    cudaFuncSetAttribute(gemm_h4, cudaFuncAttributeMaxDynamicSharedMemorySize, SMEMSZ);

    // ---- split weights into fp16 hi/lo planes ----
    wsplit_kernel<<<4096, 512>>>(wd,   wd_h,   wd_l,   DOWNW, WDP,  (long)L_ * C_ * WDP);
    wsplit_kernel<<<4096, 512>>>(wukv, wukv_h, wukv_l, KVW,   KVW,  (long)L_ * DC_ * KVW);
    wsplit_kernel<<<4096, 512>>>(wuq,  wuq_h,  wuq_l,  C_,    C_,   (long)L_ * DC1_ * C_);
    wsplit_kernel<<<4096, 512>>>(ap,   ap_h,   ap_l,   C_,    C_,   (long)L_ * C_ * C_);
    wsplit_kernel<<<4096, 512>>>(fc,   fc_h,   fc_l,   4*C_,  4*C_, (long)L_ * C_ * 4 * C_);
    wsplit_kernel<<<4096, 512>>>(pj,   pj_h,   pj_l,   C_,    C_,   (long)L_ * 4 * C_ * C_);
    wsplit_kernel<<<4096, 512>>>(lmh,  lmh_h,  lmh_l,  V_,    V_,   (long)C_ * V_);

    const int GM = NTOK / 128;     // 16 m-blocks

    embed_kernel<<<NTOK, 256>>>(idx, wte);

    for (int l = 0; l < L_; l++) {
        mix_norm_kernel<<<NTOK, 256>>>(lr, lx, l);

        // down = xn @ wd[l]; fp32 out + planes
        gemm_h4<<<dim3(GM, WDP / 128), 256, SMEMSZ>>>(
            xn_h, xn_l, wd_h + (size_t)l * C_ * WDP, wd_l + (size_t)l * C_ * WDP,
            pdown, nullptr, dn_h, dn_l,
            DOWNW, C_, C_, WDP, DOWNW, DOWNW, 0);

        // kv = down[:, :256] @ wukv[l]
        gemm_h4<<<dim3(GM, KVW / 128), 256, SMEMSZ>>>(
            dn_h, dn_l, wukv_h + (size_t)l * DC_ * KVW, wukv_l + (size_t)l * DC_ * KVW,
            pkv, nullptr, nullptr, nullptr,
            KVW, DC_, DOWNW, KVW, KVW, 0, 0);

        // qpre = down[:, 256:512] @ wuq[l]
        gemm_h4<<<dim3(GM, C_ / 128), 256, SMEMSZ>>>(
            dn_h + DC_, dn_l + DC_, wuq_h + (size_t)l * DC1_ * C_, wuq_l + (size_t)l * DC1_ * C_,
            pqpre, nullptr, nullptr, nullptr,
            C_, DC1_, DOWNW, C_, C_, 0, 0);

        build_qkv_kernel<<<NTOK, 512>>>(idx, cosp, sinp,
                                        vg + (size_t)l * 32 * H_,
                                        vemb + (size_t)l * V_ * C_);

        attn_kernel<<<dim3(T_ / 64, H_, B_), 256>>>();

        // x += y @ ap[l]
        gemm_h4<<<dim3(GM, C_ / 128), 256, SMEMSZ>>>(
            y_h, y_l, ap_h + (size_t)l * C_ * C_, ap_l + (size_t)l * C_ * C_,
            px, px, nullptr, nullptr,
            C_, C_, C_, C_, C_, 0, 0);

        mix_norm_kernel<<<NTOK, 256>>>(nullptr, nullptr, 0);

        // h = relu(xn @ fc[l])^2 -> planes only
        gemm_h4<<<dim3(GM, 4 * C_ / 128), 256, SMEMSZ>>>(
            xn_h, xn_l, fc_h + (size_t)l * C_ * 4 * C_, fc_l + (size_t)l * C_ * 4 * C_,
            nullptr, nullptr, h_h, h_l,
            4 * C_, C_, C_, 4 * C_, 0, 4 * C_, 2);

        // x += h @ pj[l]
        gemm_h4<<<dim3(GM, C_ / 128), 256, SMEMSZ>>>(
            h_h, h_l, pj_h + (size_t)l * 4 * C_ * C_, pj_l + (size_t)l * 4 * C_ * C_,
            px, px, nullptr, nullptr,
            C_, 4 * C_, 4 * C_, C_, C_, 0, 0);
    }

    mix_norm_kernel<<<NTOK, 256>>>(nullptr, nullptr, 0);
    // out = softcap(xn @ lm_head)
    gemm_h4<<<dim3(GM, V_ / 128), 256, SMEMSZ>>>(
        xn_h, xn_l, lmh_h, lmh_l,
        out, nullptr, nullptr, nullptr,
        V_, C_, C_, V_, V_, 0, 1);
}

// round 8
// speedup vs baseline: 1.6300x; 1.2166x over previous
#include <cuda_runtime.h>
#include <cuda_fp16.h>
#include <math.h>
#include <stdint.h>

// ---------------- problem constants ----------------
#define B_    2
#define T_    1024
#define C_    1024
#define H_    16
#define HD_   64
#define DC_   256
#define DC1_  256
#define DR_   32
#define DN_   32
#define V_    32000
#define L_    4
#define NTOK  (B_*T_)             // 2048
#define DOWNW (DC_+DC1_+DR_)      // 544
#define WDP   640                 // padded wd output width
#define KVW   (H_*(DN_+HD_))      // 1536
#define EPS_  1.1920929e-07f

// ---------------- fp32 scratch ----------------
__device__ float g_x   [NTOK*C_];
__device__ float g_x0  [NTOK*C_];
__device__ float g_xn  [NTOK*C_];
__device__ float g_down[NTOK*DOWNW];
__device__ float g_kv  [NTOK*KVW];
__device__ float g_qpre[NTOK*C_];

// ---------------- fp16 hi/lo planes ----------------
__device__ __half g_wd_h  [L_*C_*WDP],    g_wd_l  [L_*C_*WDP];
__device__ __half g_wukv_h[L_*DC_*KVW],   g_wukv_l[L_*DC_*KVW];
__device__ __half g_wuq_h [L_*DC1_*C_],   g_wuq_l [L_*DC1_*C_];
__device__ __half g_ap_h  [L_*C_*C_],     g_ap_l  [L_*C_*C_];
__device__ __half g_fc_h  [L_*C_*4*C_],   g_fc_l  [L_*C_*4*C_];
__device__ __half g_pj_h  [L_*4*C_*C_],   g_pj_l  [L_*4*C_*C_];
__device__ __half g_lmh_h [C_*V_],        g_lmh_l [C_*V_];
__device__ __half g_xn_h  [NTOK*C_],      g_xn_l  [NTOK*C_];
__device__ __half g_dn_h  [NTOK*DOWNW],   g_dn_l  [NTOK*DOWNW];
__device__ __half g_y_h   [NTOK*C_],      g_y_l   [NTOK*C_];
__device__ __half g_h_h   [NTOK*4*C_],    g_h_l   [NTOK*4*C_];
// attention operand planes (q pre-scaled by 0.125)
__device__ __half g_q_h   [NTOK*C_],      g_q_l   [NTOK*C_];
__device__ __half g_k_h   [NTOK*C_],      g_k_l   [NTOK*C_];
__device__ __half g_v_h   [NTOK*C_],      g_v_l   [NTOK*C_];

// ---------------- helpers ----------------
__device__ __forceinline__ uint32_t smem_u32(const void* p) {
    uint32_t a;
    asm("{ .reg .u64 t; cvta.to.shared.u64 t, %1; cvt.u32.u64 %0, t; }" : "=r"(a) : "l"(p));
    return a;
}
__device__ __forceinline__ float warp_sum(float v) {
    v += __shfl_xor_sync(0xffffffffu, v, 16);
    v += __shfl_xor_sync(0xffffffffu, v, 8);
    v += __shfl_xor_sync(0xffffffffu, v, 4);
    v += __shfl_xor_sync(0xffffffffu, v, 2);
    v += __shfl_xor_sync(0xffffffffu, v, 1);
    return v;
}
__device__ __forceinline__ float block_sum(float v) {
    __shared__ float sh[32];
    int lane = threadIdx.x & 31, wid = threadIdx.x >> 5;
    v = warp_sum(v);
    if (lane == 0) sh[wid] = v;
    __syncthreads();
    int nw = blockDim.x >> 5;
    if (wid == 0) {
        float t = (lane < nw) ? sh[lane] : 0.f;
        t = warp_sum(t);
        if (lane == 0) sh[0] = t;
    }
    __syncthreads();
    return sh[0];
}
__device__ __forceinline__ void splith(float x, __half& hi, __half& lo) {
    hi = __float2half_rn(x);
    lo = __float2half_rn(x - __half2float(hi));
}
__device__ __forceinline__ uint32_t packh2(__half a, __half b) {
    return (uint32_t)__half_as_ushort(a) | ((uint32_t)__half_as_ushort(b) << 16);
}

// ---------------- mma / ldmatrix / cp.async wrappers ----------------
__device__ __forceinline__ void ldsm_x4(uint32_t* r, uint32_t addr) {
    asm volatile("ldmatrix.sync.aligned.m8n8.x4.shared.b16 {%0,%1,%2,%3}, [%4];"
                 : "=r"(r[0]), "=r"(r[1]), "=r"(r[2]), "=r"(r[3]) : "r"(addr));
}
__device__ __forceinline__ void ldsm_x4t(uint32_t* r, uint32_t addr) {
    asm volatile("ldmatrix.sync.aligned.m8n8.x4.trans.shared.b16 {%0,%1,%2,%3}, [%4];"
                 : "=r"(r[0]), "=r"(r[1]), "=r"(r[2]), "=r"(r[3]) : "r"(addr));
}
__device__ __forceinline__ void mma16816(float4& d, const uint32_t* a, uint32_t b0, uint32_t b1) {
    asm volatile(
        "mma.sync.aligned.m16n8k16.row.col.f32.f16.f16.f32 "
        "{%0,%1,%2,%3},{%4,%5,%6,%7},{%8,%9},{%0,%1,%2,%3};"
        : "+f"(d.x), "+f"(d.y), "+f"(d.z), "+f"(d.w)
        : "r"(a[0]), "r"(a[1]), "r"(a[2]), "r"(a[3]), "r"(b0), "r"(b1));
}
#define CP16(dst, src) \
    asm volatile("cp.async.cg.shared.global [%0], [%1], 16;" :: "r"(dst), "l"(src) : "memory")
#define CPCOMMIT() asm volatile("cp.async.commit_group;" ::: "memory")
#define CPWAITG(n) asm volatile("cp.async.wait_group " #n ";" ::: "memory")

// ---------------- fast vectorized split (no padding) ----------------
__global__ void wsplit4(const float4* __restrict__ src,
                        uint2* __restrict__ hi, uint2* __restrict__ lo, long n4)
{
    long stride = (long)gridDim.x * blockDim.x;
    for (long i = (long)blockIdx.x * blockDim.x + threadIdx.x; i < n4; i += stride) {
        float4 f = src[i];
        __half h0,l0,h1,l1,h2,l2,h3,l3;
        splith(f.x,h0,l0); splith(f.y,h1,l1); splith(f.z,h2,l2); splith(f.w,h3,l3);
        hi[i] = make_uint2(packh2(h0,h1), packh2(h2,h3));
        lo[i] = make_uint2(packh2(l0,l1), packh2(l2,l3));
    }
}

// ---------------- padded split (wd only) ----------------
__global__ void wsplit_pad(const float* __restrict__ src,
                           __half* __restrict__ hi, __half* __restrict__ lo,
                           int Cs, int Cd, long total)
{
    long stride = (long)gridDim.x * blockDim.x;
    for (long i = (long)blockIdx.x * blockDim.x + threadIdx.x; i < total; i += stride) {
        long r = i / Cd;
        int  c = (int)(i - r * Cd);
        float v = (c < Cs) ? src[r * Cs + c] : 0.f;
        __half h, l;
        splith(v, h, l);
        hi[i] = h; lo[i] = l;
    }
}

// ---------------- embedding + rmsnorm ----------------
__global__ void embed_kernel(const int* __restrict__ idx, const float* __restrict__ wte) {
    int row = blockIdx.x;
    int tok = idx[row];
    const float* src = wte + (size_t)tok * C_;
    float s = 0.f;
    for (int i = threadIdx.x; i < C_; i += blockDim.x) { float v = src[i]; s += v * v; }
    s = block_sum(s);
    float r = rsqrtf(s * (1.0f / C_) + EPS_);
    for (int i = threadIdx.x; i < C_; i += blockDim.x) {
        float v = src[i] * r;
        g_x [(size_t)row * C_ + i] = v;
        g_x0[(size_t)row * C_ + i] = v;
    }
}

__global__ void mix_norm_kernel(const float* lr, const float* lx, int layer) {
    int row = blockIdx.x;
    float a = lr ? lr[layer] : 1.0f;
    float b = lx ? lx[layer] : 0.0f;
    float*       xr  = g_x  + (size_t)row * C_;
    const float* x0r = g_x0 + (size_t)row * C_;
    float s = 0.f;
    for (int i = threadIdx.x; i < C_; i += blockDim.x) {
        float v = a * xr[i] + b * x0r[i];
        xr[i] = v;
        s += v * v;
    }
    s = block_sum(s);
    float r = rsqrtf(s * (1.0f / C_) + EPS_);
    for (int i = threadIdx.x; i < C_; i += blockDim.x) {
        float v = xr[i] * r;
        g_xn[(size_t)row * C_ + i] = v;
        __half h, l;
        splith(v, h, l);
        g_xn_h[(size_t)row * C_ + i] = h;
        g_xn_l[(size_t)row * C_ + i] = l;
    }
}

// ---------------- 3xFP16 tensor-core GEMM v4 (unchanged from R7) --------
#define STG4 32768
__global__ __launch_bounds__(256, 2) void gemm_h4(
    const __half* __restrict__ Ah, const __half* __restrict__ Al,
    const __half* __restrict__ Bh, const __half* __restrict__ Bl,
    float* __restrict__ C, const float* __restrict__ D,
    __half* __restrict__ Chi, __half* __restrict__ Clo,
    int N, int K, int lda, int ldb, int ldc, int ldp, int mode)
{
    extern __shared__ __align__(1024) char sm[];
    int tid = threadIdx.x;
    int wid = tid >> 5, lane = tid & 31;
    int warp_m = wid >> 2, warp_n = wid & 3;
    int m0 = blockIdx.x * 128, n0 = blockIdx.y * 128;
    uint32_t smb = smem_u32(sm);

    float4 acc[4][4];
#pragma unroll
    for (int i = 0; i < 4; i++)
#pragma unroll
        for (int j = 0; j < 4; j++) acc[i][j] = make_float4(0.f, 0.f, 0.f, 0.f);

    int a_m   = tid >> 3;
    int a_hl  = (tid >> 2) & 1;
    int a_j   = tid & 3;
    int b_k0  = tid >> 4;
    int b_j   = tid & 15;
    const __half* Asel = a_hl ? Al : Ah;

    int arow0 = warp_m * 64 + (lane & 15);
    int akof  = (lane & 16);
    int bkr   = (lane & 15);
    int bco   = warp_n * 64 + ((lane >> 4) << 4);

    int nk = K >> 5;

    auto issue = [&](int kt, int stg) {
        uint32_t sA = smb + stg * STG4;
        uint32_t sB = sA + 16384;
#pragma unroll
        for (int r = 0; r < 4; r++) {
            int m = a_m + r * 32;
            uint32_t off = (uint32_t)(m * 128 + a_hl * 64 + a_j * 16);
            off ^= (off >> 3) & 0x70;
            const __half* src = Asel + (size_t)(m0 + m) * lda + kt * 32 + a_j * 8;
            CP16(sA + off, src);
        }
#pragma unroll
        for (int r = 0; r < 4; r++) {
            int k = b_k0 + (r & 1) * 16;
            const __half* Bp = (r < 2) ? Bh : Bl;
            uint32_t off = ((uint32_t)(k * 256 + b_j * 16)) ^ ((uint32_t)(k & 7) << 4);
            off += (r < 2) ? 0u : 8192u;
            const __half* src = Bp + (size_t)(kt * 32 + k) * ldb + n0 + b_j * 8;
            CP16(sB + off, src);
        }
        CPCOMMIT();
    };

    issue(0, 0);
    issue(1, 1);
    issue(2, 2);

    for (int kt = 0; kt < nk; kt++) {
        int s = kt % 3;
        if (kt == nk - 1) { CPWAITG(0); } else { CPWAITG(2); }
        __syncthreads();

        uint32_t sA  = smb + s * STG4;
        uint32_t sBh = sA + 16384;
        uint32_t sBl = sA + 24576;
#pragma unroll
        for (int ks = 0; ks < 2; ks++) {
            uint32_t af[4][4], bh[2][4], bl[2][4];
#pragma unroll
            for (int mi = 0; mi < 4; mi++) {
                uint32_t oh = (uint32_t)((arow0 + mi * 16) * 128 + ks * 32 + akof);
                oh ^= (oh >> 3) & 0x70;
                ldsm_x4(af[mi], sA + oh);
            }
#pragma unroll
            for (int nj = 0; nj < 2; nj++) {
                int krow = ks * 16 + bkr;
                uint32_t off = (uint32_t)(krow * 256 + bco + nj * 32) ^ ((uint32_t)(krow & 7) << 4);
                ldsm_x4t(bh[nj], sBh + off);
            }
#pragma unroll
            for (int mi = 0; mi < 4; mi++)
#pragma unroll
                for (int ni = 0; ni < 4; ni++)
                    mma16816(acc[mi][ni], af[mi], bh[ni >> 1][(ni & 1) * 2], bh[ni >> 1][(ni & 1) * 2 + 1]);
#pragma unroll
            for (int nj = 0; nj < 2; nj++) {
                int krow = ks * 16 + bkr;
                uint32_t off = (uint32_t)(krow * 256 + bco + nj * 32) ^ ((uint32_t)(krow & 7) << 4);
                ldsm_x4t(bl[nj], sBl + off);
            }
#pragma unroll
            for (int mi = 0; mi < 4; mi++)
#pragma unroll
                for (int ni = 0; ni < 4; ni++)
                    mma16816(acc[mi][ni], af[mi], bl[ni >> 1][(ni & 1) * 2], bl[ni >> 1][(ni & 1) * 2 + 1]);
#pragma unroll
            for (int mi = 0; mi < 4; mi++) {
                uint32_t ol = (uint32_t)((arow0 + mi * 16) * 128 + ks * 32 + akof + 64);
                ol ^= (ol >> 3) & 0x70;
                ldsm_x4(af[mi], sA + ol);
            }
#pragma unroll
            for (int mi = 0; mi < 4; mi++)
#pragma unroll
                for (int ni = 0; ni < 4; ni++)
                    mma16816(acc[mi][ni], af[mi], bh[ni >> 1][(ni & 1) * 2], bh[ni >> 1][(ni & 1) * 2 + 1]);
        }
        __syncthreads();
        if (kt + 3 < nk) issue(kt + 3, s);
    }

    int g = lane >> 2, t4 = lane & 3;
#pragma unroll
    for (int mi = 0; mi < 4; mi++) {
        int r0 = m0 + warp_m * 64 + mi * 16 + g;
#pragma unroll
        for (int ni = 0; ni < 4; ni++) {
            int col = n0 + warp_n * 32 + ni * 8 + 2 * t4;
            if (col >= N) continue;
            float4 v = acc[mi][ni];
            if (D) {
                float2 d0 = *reinterpret_cast<const float2*>(D + (size_t)r0 * ldc + col);
                float2 d1 = *reinterpret_cast<const float2*>(D + (size_t)(r0 + 8) * ldc + col);
                v.x += d0.x; v.y += d0.y; v.z += d1.x; v.w += d1.y;
            }
            if (mode == 1) {
                v.x = 15.0f * tanhf(v.x * (1.f / 15.f));
                v.y = 15.0f * tanhf(v.y * (1.f / 15.f));
                v.z = 15.0f * tanhf(v.z * (1.f / 15.f));
                v.w = 15.0f * tanhf(v.w * (1.f / 15.f));
            } else if (mode == 2) {
                v.x = (v.x > 0.f) ? v.x * v.x : 0.f;
                v.y = (v.y > 0.f) ? v.y * v.y : 0.f;
                v.z = (v.z > 0.f) ? v.z * v.z : 0.f;
                v.w = (v.w > 0.f) ? v.w * v.w : 0.f;
            }
            if (C) {
                *reinterpret_cast<float2*>(C + (size_t)r0 * ldc + col) = make_float2(v.x, v.y);
                *reinterpret_cast<float2*>(C + (size_t)(r0 + 8) * ldc + col) = make_float2(v.z, v.w);
            }
            if (Chi) {
                __half hx, lx_, hy, ly, hz, lz, hw, lw;
                splith(v.x, hx, lx_); splith(v.y, hy, ly);
                splith(v.z, hz, lz);  splith(v.w, hw, lw);
                *reinterpret_cast<uint32_t*>(Chi + (size_t)r0 * ldp + col)       = packh2(hx, hy);
                *reinterpret_cast<uint32_t*>(Clo + (size_t)r0 * ldp + col)       = packh2(lx_, ly);
                *reinterpret_cast<uint32_t*>(Chi + (size_t)(r0 + 8) * ldp + col) = packh2(hz, hw);
                *reinterpret_cast<uint32_t*>(Clo + (size_t)(r0 + 8) * ldp + col) = packh2(lz, lw);
            }
        }
    }
}

// ---------------- per-token q/k/v build -> fp16 hi/lo planes --------------
__global__ void build_qkv_kernel(const int* __restrict__ idx,
                                 const float* __restrict__ cosp, const float* __restrict__ sinp,
                                 const float* __restrict__ vg, const float* __restrict__ vetab)
{
    int row = blockIdx.x;
    int h    = threadIdx.x >> 5;
    int lane = threadIdx.x & 31;
    const float* cosr = cosp + (size_t)row * (DR_ / 2);
    const float* sinr = sinp + (size_t)row * (DR_ / 2);

    float gv = g_xn[(size_t)row * C_ + lane] * vg[lane * H_ + h];
    gv = warp_sum(gv);
    float gate = 2.0f / (1.0f + __expf(-gv));

    int r16 = (lane < 16) ? lane : lane - 16;
    float c = cosr[r16], s = sinr[r16];
    size_t base = (size_t)row * C_ + h * 64;

    // k
    float kn = g_kv[(size_t)row * KVW + h * 96 + lane];
    const float* dro = g_down + (size_t)row * DOWNW + 512;
    float kr = (lane < 16) ? (dro[lane] * c + dro[lane + 16] * s)
                           : (-dro[lane - 16] * s + dro[lane] * c);
    float ssk = warp_sum(kn * kn + kr * kr);
    float rk = rsqrtf(ssk * (1.0f / 64.0f) + EPS_);
    __half hh_, ll_;
    splith(kn * rk, hh_, ll_);  g_k_h[base + lane]      = hh_; g_k_l[base + lane]      = ll_;
    splith(kr * rk, hh_, ll_);  g_k_h[base + lane + 32] = hh_; g_k_l[base + lane + 32] = ll_;

    // q (pre-scaled by 1/sqrt(HD) = 0.125)
    const float* qp = g_qpre + (size_t)row * C_ + h * 64;
    float qn = qp[lane];
    float qr = (lane < 16) ? (qp[32 + lane] * c + qp[48 + lane] * s)
                           : (-qp[16 + lane] * s + qp[32 + lane] * c);
    float ssq = warp_sum(qn * qn + qr * qr);
    float rq = rsqrtf(ssq * (1.0f / 64.0f) + EPS_) * 0.125f;
    splith(qn * rq, hh_, ll_);  g_q_h[base + lane]      = hh_; g_q_l[base + lane]      = ll_;
    splith(qr * rq, hh_, ll_);  g_q_h[base + lane + 32] = hh_; g_q_l[base + lane + 32] = ll_;

    // v
    int tok = idx[row];
    const float* ver = vetab + (size_t)tok * C_ + h * 64;
    const float* kvv = g_kv + (size_t)row * KVW + h * 96 + 32;
    splith(kvv[lane]      + gate * ver[lane],      hh_, ll_);
    g_v_h[base + lane]      = hh_; g_v_l[base + lane]      = ll_;
    splith(kvv[lane + 32] + gate * ver[lane + 32], hh_, ll_);
    g_v_h[base + lane + 32] = hh_; g_v_l[base + lane + 32] = ll_;
}

// ---------------- tensor-core causal flash attention ----------------------
// grid (T/64, H, B), 128 threads (4 warps); warp handles 16 q-rows.
// smem: Qhi@0 Qlo@8192 Khi@16384 Klo@24576 Vhi@32768 Vlo@40960 (each 8KB,
// 64 rows x 128B, SW128 xor swizzle).
__global__ __launch_bounds__(128) void attn_mma()
{
    extern __shared__ __align__(1024) char dsm[];
    uint32_t smb = smem_u32(dsm);
    int tid = threadIdx.x;
    int wid = tid >> 5, lane = tid & 31;
    int q0 = blockIdx.x * 64;
    int hh = blockIdx.y;
    int b  = blockIdx.z;
    int t4 = lane & 3, g = lane >> 2;

    // ---- load Q tile ----
#pragma unroll
    for (int j = 0; j < 4; j++) {
        int idxq = tid + j * 128;
        int r = idxq >> 3, ch = idxq & 7;
        uint32_t off = (uint32_t)(r * 128 + ch * 16);
        off ^= (off >> 3) & 0x70;
        size_t src = (size_t)(b * T_ + q0 + r) * C_ + hh * 64 + ch * 8;
        CP16(smb + off,        g_q_h + src);
        CP16(smb + 8192 + off, g_q_l + src);
    }
    CPCOMMIT(); CPWAITG(0);
    __syncthreads();

    // ---- preload Q fragments ----
    int arow0 = wid * 16 + (lane & 15);
    int akof  = (lane & 16);
    uint32_t qh[4][4], ql[4][4];
#pragma unroll
    for (int ks = 0; ks < 4; ks++) {
        uint32_t off = (uint32_t)(arow0 * 128 + ks * 32 + akof);
        off ^= (off >> 3) & 0x70;
        ldsm_x4(qh[ks], smb + off);
        ldsm_x4(ql[ks], smb + 8192 + off);
    }

    float4 oacc[8];
#pragma unroll
    for (int i = 0; i < 8; i++) oacc[i] = make_float4(0.f, 0.f, 0.f, 0.f);
    float mrow0 = -1e30f, mrow1 = -1e30f, lrow0 = 0.f, lrow1 = 0.f;

    for (int k0 = 0; k0 <= q0; k0 += 64) {
        // ---- load K,V tiles ----
#pragma unroll
        for (int j = 0; j < 4; j++) {
            int idxq = tid + j * 128;
            int r = idxq >> 3, ch = idxq & 7;
            uint32_t off = (uint32_t)(r * 128 + ch * 16);
            off ^= (off >> 3) & 0x70;
            size_t src = (size_t)(b * T_ + k0 + r) * C_ + hh * 64 + ch * 8;
            CP16(smb + 16384 + off, g_k_h + src);
            CP16(smb + 24576 + off, g_k_l + src);
            CP16(smb + 32768 + off, g_v_h + src);
            CP16(smb + 40960 + off, g_v_l + src);
        }
        CPCOMMIT(); CPWAITG(0);
        __syncthreads();

        // ---- S = Q K^T (3-term) ----
        float4 sacc[8];
#pragma unroll
        for (int i = 0; i < 8; i++) sacc[i] = make_float4(0.f, 0.f, 0.f, 0.f);
#pragma unroll
        for (int ks = 0; ks < 4; ks++) {
#pragma unroll
            for (int njp = 0; njp < 4; njp++) {
                uint32_t kh[4], kl[4];
                uint32_t off = (uint32_t)(((lane & 15) + njp * 16) * 128 + ks * 32 + akof);
                off ^= (off >> 3) & 0x70;
                ldsm_x4(kh, smb + 16384 + off);
                ldsm_x4(kl, smb + 24576 + off);
                mma16816(sacc[2 * njp],     qh[ks], kh[0], kh[2]);
                mma16816(sacc[2 * njp + 1], qh[ks], kh[1], kh[3]);
                mma16816(sacc[2 * njp],     qh[ks], kl[0], kl[2]);
                mma16816(sacc[2 * njp + 1], qh[ks], kl[1], kl[3]);
                mma16816(sacc[2 * njp],     ql[ks], kh[0], kh[2]);
                mma16816(sacc[2 * njp + 1], ql[ks], kh[1], kh[3]);
            }
        }

        // ---- diagonal mask ----
        if (k0 == q0) {
            int qiA = wid * 16 + g, qiB = qiA + 8;
#pragma unroll
            for (int nj = 0; nj < 8; nj++) {
                int ki = nj * 8 + t4 * 2;
                if (ki     > qiA) sacc[nj].x = -1e30f;
                if (ki + 1 > qiA) sacc[nj].y = -1e30f;
                if (ki     > qiB) sacc[nj].z = -1e30f;
                if (ki + 1 > qiB) sacc[nj].w = -1e30f;
            }
        }

        // ---- online softmax ----
        float mx0 = -1e30f, mx1 = -1e30f;
#pragma unroll
        for (int nj = 0; nj < 8; nj++) {
            mx0 = fmaxf(mx0, fmaxf(sacc[nj].x, sacc[nj].y));
            mx1 = fmaxf(mx1, fmaxf(sacc[nj].z, sacc[nj].w));
        }
        mx0 = fmaxf(mx0, __shfl_xor_sync(0xffffffffu, mx0, 1));
        mx0 = fmaxf(mx0, __shfl_xor_sync(0xffffffffu, mx0, 2));
        mx1 = fmaxf(mx1, __shfl_xor_sync(0xffffffffu, mx1, 1));
        mx1 = fmaxf(mx1, __shfl_xor_sync(0xffffffffu, mx1, 2));
        float mn0 = fmaxf(mrow0, mx0), mn1 = fmaxf(mrow1, mx1);
        float c0 = __expf(mrow0 - mn0), c1 = __expf(mrow1 - mn1);
        float sum0 = 0.f, sum1 = 0.f;
#pragma unroll
        for (int nj = 0; nj < 8; nj++) {
            sacc[nj].x = __expf(sacc[nj].x - mn0);
            sacc[nj].y = __expf(sacc[nj].y - mn0);
            sacc[nj].z = __expf(sacc[nj].z - mn1);
            sacc[nj].w = __expf(sacc[nj].w - mn1);
            sum0 += sacc[nj].x + sacc[nj].y;
            sum1 += sacc[nj].z + sacc[nj].w;
        }
        sum0 += __shfl_xor_sync(0xffffffffu, sum0, 1);
        sum0 += __shfl_xor_sync(0xffffffffu, sum0, 2);
        sum1 += __shfl_xor_sync(0xffffffffu, sum1, 1);
        sum1 += __shfl_xor_sync(0xffffffffu, sum1, 2);
        lrow0 = lrow0 * c0 + sum0;
        lrow1 = lrow1 * c1 + sum1;
        mrow0 = mn0; mrow1 = mn1;
#pragma unroll
        for (int nd = 0; nd < 8; nd++) {
            oacc[nd].x *= c0; oacc[nd].y *= c0;
            oacc[nd].z *= c1; oacc[nd].w *= c1;
        }

        // ---- O += P V (3-term) ----
#pragma unroll
        for (int kk = 0; kk < 4; kk++) {
            __half h0,l0,h1,l1,h2,l2,h3,l3,h4,l4,h5,l5,h6,l6,h7,l7;
            splith(sacc[2*kk].x, h0, l0);   splith(sacc[2*kk].y, h1, l1);
            splith(sacc[2*kk].z, h2, l2);   splith(sacc[2*kk].w, h3, l3);
            splith(sacc[2*kk+1].x, h4, l4); splith(sacc[2*kk+1].y, h5, l5);
            splith(sacc[2*kk+1].z, h6, l6); splith(sacc[2*kk+1].w, h7, l7);
            uint32_t ah[4] = { packh2(h0,h1), packh2(h2,h3), packh2(h4,h5), packh2(h6,h7) };
            uint32_t al[4] = { packh2(l0,l1), packh2(l2,l3), packh2(l4,l5), packh2(l6,l7) };
#pragma unroll
            for (int ndp = 0; ndp < 4; ndp++) {
                uint32_t vh[4], vl[4];
                uint32_t off = (uint32_t)((kk * 16 + (lane & 15)) * 128 + ndp * 32 + akof);
                off ^= (off >> 3) & 0x70;
                ldsm_x4t(vh, smb + 32768 + off);
                ldsm_x4t(vl, smb + 40960 + off);
                mma16816(oacc[2 * ndp],     ah, vh[0], vh[1]);
                mma16816(oacc[2 * ndp + 1], ah, vh[2], vh[3]);
                mma16816(oacc[2 * ndp],     ah, vl[0], vl[1]);
                mma16816(oacc[2 * ndp + 1], ah, vl[2], vl[3]);
                mma16816(oacc[2 * ndp],     al, vh[0], vh[1]);
                mma16816(oacc[2 * ndp + 1], al, vh[2], vh[3]);
            }
        }
        __syncthreads();
    }

    // ---- epilogue: y = O / l -> hi/lo planes ----
    float inv0 = 1.0f / lrow0, inv1 = 1.0f / lrow1;
    int r0 = q0 + wid * 16 + g, r1 = r0 + 8;
    size_t b0 = (size_t)(b * T_ + r0) * C_ + hh * 64;
    size_t b1 = (size_t)(b * T_ + r1) * C_ + hh * 64;
#pragma unroll
    for (int nd = 0; nd < 8; nd++) {
        int d = nd * 8 + t4 * 2;
        __half hx, lx_, hy, ly;
        splith(oacc[nd].x * inv0, hx, lx_);
        splith(oacc[nd].y * inv0, hy, ly);
        *reinterpret_cast<uint32_t*>(g_y_h + b0 + d) = packh2(hx, hy);
        *reinterpret_cast<uint32_t*>(g_y_l + b0 + d) = packh2(lx_, ly);
        splith(oacc[nd].z * inv1, hx, lx_);
        splith(oacc[nd].w * inv1, hy, ly);
        *reinterpret_cast<uint32_t*>(g_y_h + b1 + d) = packh2(hx, hy);
        *reinterpret_cast<uint32_t*>(g_y_l + b1 + d) = packh2(lx_, ly);
    }
}

// ---------------- host orchestration ----------------
extern "C" void kernel_launch(void* const* d_in, const int* in_sizes, int n_in,
                              void* d_out, int out_size)
{
    (void)in_sizes; (void)n_in; (void)out_size;
    const int*   idx  = (const int*)  d_in[0];
    const float* cosp = (const float*)d_in[1];
    const float* sinp = (const float*)d_in[2];
    const float* wte  = (const float*)d_in[3];
    const float* vemb = (const float*)d_in[4];
    const float* wd   = (const float*)d_in[5];
    const float* wukv = (const float*)d_in[6];
    const float* wuq  = (const float*)d_in[7];
    const float* vg   = (const float*)d_in[8];
    const float* ap   = (const float*)d_in[9];
    const float* fc   = (const float*)d_in[10];
    const float* pj   = (const float*)d_in[11];
    const float* lr   = (const float*)d_in[12];
    const float* lx   = (const float*)d_in[13];
    const float* lmh  = (const float*)d_in[14];
    float* out = (float*)d_out;

    float *px, *pdown, *pkv, *pqpre;
    cudaGetSymbolAddress((void**)&px,    g_x);
    cudaGetSymbolAddress((void**)&pdown, g_down);
    cudaGetSymbolAddress((void**)&pkv,   g_kv);
    cudaGetSymbolAddress((void**)&pqpre, g_qpre);

    __half *wd_h, *wd_l, *wukv_h, *wukv_l, *wuq_h, *wuq_l, *ap_h, *ap_l;
    __half *fc_h, *fc_l, *pj_h, *pj_l, *lmh_h, *lmh_l;
    __half *xn_h, *xn_l, *dn_h, *dn_l, *y_h, *y_l, *h_h, *h_l;
    cudaGetSymbolAddress((void**)&wd_h,   g_wd_h);   cudaGetSymbolAddress((void**)&wd_l,   g_wd_l);
    cudaGetSymbolAddress((void**)&wukv_h, g_wukv_h); cudaGetSymbolAddress((void**)&wukv_l, g_wukv_l);
    cudaGetSymbolAddress((void**)&wuq_h,  g_wuq_h);  cudaGetSymbolAddress((void**)&wuq_l,  g_wuq_l);
    cudaGetSymbolAddress((void**)&ap_h,   g_ap_h);   cudaGetSymbolAddress((void**)&ap_l,   g_ap_l);
    cudaGetSymbolAddress((void**)&fc_h,   g_fc_h);   cudaGetSymbolAddress((void**)&fc_l,   g_fc_l);
    cudaGetSymbolAddress((void**)&pj_h,   g_pj_h);   cudaGetSymbolAddress((void**)&pj_l,   g_pj_l);
    cudaGetSymbolAddress((void**)&lmh_h,  g_lmh_h);  cudaGetSymbolAddress((void**)&lmh_l,  g_lmh_l);
    cudaGetSymbolAddress((void**)&xn_h,   g_xn_h);   cudaGetSymbolAddress((void**)&xn_l,   g_xn_l);
    cudaGetSymbolAddress((void**)&dn_h,   g_dn_h);   cudaGetSymbolAddress((void**)&dn_l,   g_dn_l);
    cudaGetSymbolAddress((void**)&y_h,    g_y_h);    cudaGetSymbolAddress((void**)&y_l,    g_y_l);
    cudaGetSymbolAddress((void**)&h_h,    g_h_h);    cudaGetSymbolAddress((void**)&h_l,    g_h_l);

    const int SMEMSZ = 3 * STG4;   // 96 KB
    cudaFuncSetAttribute(gemm_h4, cudaFuncAttributeMaxDynamicSharedMemorySize, SMEMSZ);
    const int ASM = 49152;         // 48 KB
    cudaFuncSetAttribute(attn_mma, cudaFuncAttributeMaxDynamicSharedMemorySize, ASM);

    // ---- split weights (fast vectorized path; wd needs padding) ----
    wsplit_pad<<<2048, 256>>>(wd, wd_h, wd_l, DOWNW, WDP, (long)L_ * C_ * WDP);
    wsplit4<<<2048, 256>>>((const float4*)wukv, (uint2*)wukv_h, (uint2*)wukv_l, (long)L_ * DC_ * KVW / 4);
    wsplit4<<<2048, 256>>>((const float4*)wuq,  (uint2*)wuq_h,  (uint2*)wuq_l,  (long)L_ * DC1_ * C_ / 4);
    wsplit4<<<2048, 256>>>((const float4*)ap,   (uint2*)ap_h,   (uint2*)ap_l,   (long)L_ * C_ * C_ / 4);
    wsplit4<<<2048, 256>>>((const float4*)fc,   (uint2*)fc_h,   (uint2*)fc_l,   (long)L_ * C_ * 4 * C_ / 4);
    wsplit4<<<2048, 256>>>((const float4*)pj,   (uint2*)pj_h,   (uint2*)pj_l,   (long)L_ * 4 * C_ * C_ / 4);
    wsplit4<<<2048, 256>>>((const float4*)lmh,  (uint2*)lmh_h,  (uint2*)lmh_l,  (long)C_ * V_ / 4);

    const int GM = NTOK / 128;     // 16 m-blocks

    embed_kernel<<<NTOK, 256>>>(idx, wte);

    for (int l = 0; l < L_; l++) {
        mix_norm_kernel<<<NTOK, 256>>>(lr, lx, l);

        gemm_h4<<<dim3(GM, WDP / 128), 256, SMEMSZ>>>(
            xn_h, xn_l, wd_h + (size_t)l * C_ * WDP, wd_l + (size_t)l * C_ * WDP,
            pdown, nullptr, dn_h, dn_l,
            DOWNW, C_, C_, WDP, DOWNW, DOWNW, 0);

        gemm_h4<<<dim3(GM, KVW / 128), 256, SMEMSZ>>>(
            dn_h, dn_l, wukv_h + (size_t)l * DC_ * KVW, wukv_l + (size_t)l * DC_ * KVW,
            pkv, nullptr, nullptr, nullptr,
            KVW, DC_, DOWNW, KVW, KVW, 0, 0);

        gemm_h4<<<dim3(GM, C_ / 128), 256, SMEMSZ>>>(
            dn_h + DC_, dn_l + DC_, wuq_h + (size_t)l * DC1_ * C_, wuq_l + (size_t)l * DC1_ * C_,
            pqpre, nullptr, nullptr, nullptr,
            C_, DC1_, DOWNW, C_, C_, 0, 0);

        build_qkv_kernel<<<NTOK, 512>>>(idx, cosp, sinp,
                                        vg + (size_t)l * 32 * H_,
                                        vemb + (size_t)l * V_ * C_);

        attn_mma<<<dim3(T_ / 64, H_, B_), 128, ASM>>>();

        gemm_h4<<<dim3(GM, C_ / 128), 256, SMEMSZ>>>(
            y_h, y_l, ap_h + (size_t)l * C_ * C_, ap_l + (size_t)l * C_ * C_,
            px, px, nullptr, nullptr,
            C_, C_, C_, C_, C_, 0, 0);

        mix_norm_kernel<<<NTOK, 256>>>(nullptr, nullptr, 0);

        gemm_h4<<<dim3(GM, 4 * C_ / 128), 256, SMEMSZ>>>(
            xn_h, xn_l, fc_h + (size_t)l * C_ * 4 * C_, fc_l + (size_t)l * C_ * 4 * C_,
            nullptr, nullptr, h_h, h_l,
            4 * C_, C_, C_, 4 * C_, 0, 4 * C_, 2);

        gemm_h4<<<dim3(GM, C_ / 128), 256, SMEMSZ>>>(
            h_h, h_l, pj_h + (size_t)l * 4 * C_ * C_, pj_l + (size_t)l * 4 * C_ * C_,
            px, px, nullptr, nullptr,
            C_, 4 * C_, 4 * C_, C_, C_, 0, 0);
    }

    mix_norm_kernel<<<NTOK, 256>>>(nullptr, nullptr, 0);
    gemm_h4<<<dim3(GM, V_ / 128), 256, SMEMSZ>>>(
        xn_h, xn_l, lmh_h, lmh_l,
        out, nullptr, nullptr, nullptr,
        V_, C_, C_, V_, V_, 0, 1);
}

// round 9
// speedup vs baseline: 1.6747x; 1.0274x over previous
#include <cuda_runtime.h>
#include <cuda_fp16.h>
#include <math.h>
#include <stdint.h>

// ---------------- problem constants ----------------
#define B_    2
#define T_    1024
#define C_    1024
#define H_    16
#define HD_   64
#define DC_   256
#define DC1_  256
#define DR_   32
#define DN_   32
#define V_    32000
#define L_    4
#define NTOK  (B_*T_)             // 2048
#define DOWNW (DC_+DC1_+DR_)      // 544
#define WDP   640                 // padded wd output width
#define KVW   (H_*(DN_+HD_))      // 1536
#define EPS_  1.1920929e-07f

// ---------------- fp32 scratch ----------------
__device__ float g_x   [NTOK*C_];
__device__ float g_x0  [NTOK*C_];
__device__ float g_xn  [NTOK*C_];
__device__ float g_down[NTOK*DOWNW];
__device__ float g_kv  [NTOK*KVW];
__device__ float g_qpre[NTOK*C_];

// ---------------- fp16 hi/lo planes ----------------
__device__ __half g_wd_h  [L_*C_*WDP],    g_wd_l  [L_*C_*WDP];
__device__ __half g_wukv_h[L_*DC_*KVW],   g_wukv_l[L_*DC_*KVW];
__device__ __half g_wuq_h [L_*DC1_*C_],   g_wuq_l [L_*DC1_*C_];
__device__ __half g_ap_h  [L_*C_*C_],     g_ap_l  [L_*C_*C_];
__device__ __half g_fc_h  [L_*C_*4*C_],   g_fc_l  [L_*C_*4*C_];
__device__ __half g_pj_h  [L_*4*C_*C_],   g_pj_l  [L_*4*C_*C_];
__device__ __half g_lmh_h [C_*V_],        g_lmh_l [C_*V_];
__device__ __half g_xn_h  [NTOK*C_],      g_xn_l  [NTOK*C_];
__device__ __half g_dn_h  [NTOK*DOWNW],   g_dn_l  [NTOK*DOWNW];
__device__ __half g_y_h   [NTOK*C_],      g_y_l   [NTOK*C_];
__device__ __half g_h_h   [NTOK*4*C_],    g_h_l   [NTOK*4*C_];
// attention operand planes (q pre-scaled by 0.125)
__device__ __half g_q_h   [NTOK*C_],      g_q_l   [NTOK*C_];
__device__ __half g_k_h   [NTOK*C_],      g_k_l   [NTOK*C_];
__device__ __half g_v_h   [NTOK*C_],      g_v_l   [NTOK*C_];

// ---------------- helpers ----------------
__device__ __forceinline__ uint32_t smem_u32(const void* p) {
    uint32_t a;
    asm("{ .reg .u64 t; cvta.to.shared.u64 t, %1; cvt.u32.u64 %0, t; }" : "=r"(a) : "l"(p));
    return a;
}
__device__ __forceinline__ float warp_sum(float v) {
    v += __shfl_xor_sync(0xffffffffu, v, 16);
    v += __shfl_xor_sync(0xffffffffu, v, 8);
    v += __shfl_xor_sync(0xffffffffu, v, 4);
    v += __shfl_xor_sync(0xffffffffu, v, 2);
    v += __shfl_xor_sync(0xffffffffu, v, 1);
    return v;
}
__device__ __forceinline__ float block_sum(float v) {
    __shared__ float sh[32];
    int lane = threadIdx.x & 31, wid = threadIdx.x >> 5;
    v = warp_sum(v);
    if (lane == 0) sh[wid] = v;
    __syncthreads();
    int nw = blockDim.x >> 5;
    if (wid == 0) {
        float t = (lane < nw) ? sh[lane] : 0.f;
        t = warp_sum(t);
        if (lane == 0) sh[0] = t;
    }
    __syncthreads();
    return sh[0];
}
__device__ __forceinline__ void splith(float x, __half& hi, __half& lo) {
    hi = __float2half_rn(x);
    lo = __float2half_rn(x - __half2float(hi));
}
__device__ __forceinline__ uint32_t packh2(__half a, __half b) {
    return (uint32_t)__half_as_ushort(a) | ((uint32_t)__half_as_ushort(b) << 16);
}

// ---------------- mma / ldmatrix / cp.async wrappers ----------------
__device__ __forceinline__ void ldsm_x4(uint32_t* r, uint32_t addr) {
    asm volatile("ldmatrix.sync.aligned.m8n8.x4.shared.b16 {%0,%1,%2,%3}, [%4];"
                 : "=r"(r[0]), "=r"(r[1]), "=r"(r[2]), "=r"(r[3]) : "r"(addr));
}
__device__ __forceinline__ void ldsm_x4t(uint32_t* r, uint32_t addr) {
    asm volatile("ldmatrix.sync.aligned.m8n8.x4.trans.shared.b16 {%0,%1,%2,%3}, [%4];"
                 : "=r"(r[0]), "=r"(r[1]), "=r"(r[2]), "=r"(r[3]) : "r"(addr));
}
__device__ __forceinline__ void mma16816(float4& d, const uint32_t* a, uint32_t b0, uint32_t b1) {
    asm volatile(
        "mma.sync.aligned.m16n8k16.row.col.f32.f16.f16.f32 "
        "{%0,%1,%2,%3},{%4,%5,%6,%7},{%8,%9},{%0,%1,%2,%3};"
        : "+f"(d.x), "+f"(d.y), "+f"(d.z), "+f"(d.w)
        : "r"(a[0]), "r"(a[1]), "r"(a[2]), "r"(a[3]), "r"(b0), "r"(b1));
}
#define CP16(dst, src) \
    asm volatile("cp.async.cg.shared.global [%0], [%1], 16;" :: "r"(dst), "l"(src) : "memory")
#define CPCOMMIT() asm volatile("cp.async.commit_group;" ::: "memory")
#define CPWAITG(n) asm volatile("cp.async.wait_group " #n ";" ::: "memory")

// ---------------- fast vectorized split: 8 floats/thread ----------------
__global__ void wsplit8(const float4* __restrict__ src,
                        uint4* __restrict__ hi, uint4* __restrict__ lo, long n8)
{
    long stride = (long)gridDim.x * blockDim.x;
    for (long i = (long)blockIdx.x * blockDim.x + threadIdx.x; i < n8; i += stride) {
        float4 f0 = src[2 * i];
        float4 f1 = src[2 * i + 1];
        __half h0,l0,h1,l1,h2,l2,h3,l3,h4,l4,h5,l5,h6,l6,h7,l7;
        splith(f0.x,h0,l0); splith(f0.y,h1,l1); splith(f0.z,h2,l2); splith(f0.w,h3,l3);
        splith(f1.x,h4,l4); splith(f1.y,h5,l5); splith(f1.z,h6,l6); splith(f1.w,h7,l7);
        hi[i] = make_uint4(packh2(h0,h1), packh2(h2,h3), packh2(h4,h5), packh2(h6,h7));
        lo[i] = make_uint4(packh2(l0,l1), packh2(l2,l3), packh2(l4,l5), packh2(l6,l7));
    }
}

// ---------------- padded split (wd only) ----------------
__global__ void wsplit_pad(const float* __restrict__ src,
                           __half* __restrict__ hi, __half* __restrict__ lo,
                           int Cs, int Cd, long total)
{
    long stride = (long)gridDim.x * blockDim.x;
    for (long i = (long)blockIdx.x * blockDim.x + threadIdx.x; i < total; i += stride) {
        long r = i / Cd;
        int  c = (int)(i - r * Cd);
        float v = (c < Cs) ? src[r * Cs + c] : 0.f;
        __half h, l;
        splith(v, h, l);
        hi[i] = h; lo[i] = l;
    }
}

// ---------------- embedding + rmsnorm ----------------
__global__ void embed_kernel(const int* __restrict__ idx, const float* __restrict__ wte) {
    int row = blockIdx.x;
    int tok = idx[row];
    const float* src = wte + (size_t)tok * C_;
    float s = 0.f;
    for (int i = threadIdx.x; i < C_; i += blockDim.x) { float v = src[i]; s += v * v; }
    s = block_sum(s);
    float r = rsqrtf(s * (1.0f / C_) + EPS_);
    for (int i = threadIdx.x; i < C_; i += blockDim.x) {
        float v = src[i] * r;
        g_x [(size_t)row * C_ + i] = v;
        g_x0[(size_t)row * C_ + i] = v;
    }
}

__global__ void mix_norm_kernel(const float* lr, const float* lx, int layer) {
    int row = blockIdx.x;
    float a = lr ? lr[layer] : 1.0f;
    float b = lx ? lx[layer] : 0.0f;
    float*       xr  = g_x  + (size_t)row * C_;
    const float* x0r = g_x0 + (size_t)row * C_;
    float s = 0.f;
    for (int i = threadIdx.x; i < C_; i += blockDim.x) {
        float v = a * xr[i] + b * x0r[i];
        xr[i] = v;
        s += v * v;
    }
    s = block_sum(s);
    float r = rsqrtf(s * (1.0f / C_) + EPS_);
    for (int i = threadIdx.x; i < C_; i += blockDim.x) {
        float v = xr[i] * r;
        g_xn[(size_t)row * C_ + i] = v;
        __half h, l;
        splith(v, h, l);
        g_xn_h[(size_t)row * C_ + i] = h;
        g_xn_l[(size_t)row * C_ + i] = l;
    }
}

// ---------------- 3xFP16 tensor-core GEMM v4 (+nterms) ----------------
#define STG4 32768
__global__ __launch_bounds__(256, 2) void gemm_h4(
    const __half* __restrict__ Ah, const __half* __restrict__ Al,
    const __half* __restrict__ Bh, const __half* __restrict__ Bl,
    float* __restrict__ C, const float* __restrict__ D,
    __half* __restrict__ Chi, __half* __restrict__ Clo,
    int N, int K, int lda, int ldb, int ldc, int ldp, int mode, int nterms)
{
    extern __shared__ __align__(1024) char sm[];
    int tid = threadIdx.x;
    int wid = tid >> 5, lane = tid & 31;
    int warp_m = wid >> 2, warp_n = wid & 3;
    int m0 = blockIdx.x * 128, n0 = blockIdx.y * 128;
    uint32_t smb = smem_u32(sm);

    float4 acc[4][4];
#pragma unroll
    for (int i = 0; i < 4; i++)
#pragma unroll
        for (int j = 0; j < 4; j++) acc[i][j] = make_float4(0.f, 0.f, 0.f, 0.f);

    int a_m   = tid >> 3;
    int a_hl  = (tid >> 2) & 1;
    int a_j   = tid & 3;
    int b_k0  = tid >> 4;
    int b_j   = tid & 15;
    const __half* Asel = a_hl ? Al : Ah;

    int arow0 = warp_m * 64 + (lane & 15);
    int akof  = (lane & 16);
    int bkr   = (lane & 15);
    int bco   = warp_n * 64 + ((lane >> 4) << 4);

    int nk = K >> 5;

    auto issue = [&](int kt, int stg) {
        uint32_t sA = smb + stg * STG4;
        uint32_t sB = sA + 16384;
#pragma unroll
        for (int r = 0; r < 4; r++) {
            int m = a_m + r * 32;
            uint32_t off = (uint32_t)(m * 128 + a_hl * 64 + a_j * 16);
            off ^= (off >> 3) & 0x70;
            const __half* src = Asel + (size_t)(m0 + m) * lda + kt * 32 + a_j * 8;
            CP16(sA + off, src);
        }
#pragma unroll
        for (int r = 0; r < 4; r++) {
            int k = b_k0 + (r & 1) * 16;
            const __half* Bp = (r < 2) ? Bh : Bl;
            uint32_t off = ((uint32_t)(k * 256 + b_j * 16)) ^ ((uint32_t)(k & 7) << 4);
            off += (r < 2) ? 0u : 8192u;
            const __half* src = Bp + (size_t)(kt * 32 + k) * ldb + n0 + b_j * 8;
            CP16(sB + off, src);
        }
        CPCOMMIT();
    };

    issue(0, 0);
    issue(1, 1);
    issue(2, 2);

    for (int kt = 0; kt < nk; kt++) {
        int s = kt % 3;
        if (kt == nk - 1) { CPWAITG(0); } else { CPWAITG(2); }
        __syncthreads();

        uint32_t sA  = smb + s * STG4;
        uint32_t sBh = sA + 16384;
        uint32_t sBl = sA + 24576;
#pragma unroll
        for (int ks = 0; ks < 2; ks++) {
            uint32_t af[4][4], bh[2][4], bl[2][4];
#pragma unroll
            for (int mi = 0; mi < 4; mi++) {
                uint32_t oh = (uint32_t)((arow0 + mi * 16) * 128 + ks * 32 + akof);
                oh ^= (oh >> 3) & 0x70;
                ldsm_x4(af[mi], sA + oh);
            }
#pragma unroll
            for (int nj = 0; nj < 2; nj++) {
                int krow = ks * 16 + bkr;
                uint32_t off = (uint32_t)(krow * 256 + bco + nj * 32) ^ ((uint32_t)(krow & 7) << 4);
                ldsm_x4t(bh[nj], sBh + off);
            }
#pragma unroll
            for (int mi = 0; mi < 4; mi++)
#pragma unroll
                for (int ni = 0; ni < 4; ni++)
                    mma16816(acc[mi][ni], af[mi], bh[ni >> 1][(ni & 1) * 2], bh[ni >> 1][(ni & 1) * 2 + 1]);
#pragma unroll
            for (int nj = 0; nj < 2; nj++) {
                int krow = ks * 16 + bkr;
                uint32_t off = (uint32_t)(krow * 256 + bco + nj * 32) ^ ((uint32_t)(krow & 7) << 4);
                ldsm_x4t(bl[nj], sBl + off);
            }
#pragma unroll
            for (int mi = 0; mi < 4; mi++)
#pragma unroll
                for (int ni = 0; ni < 4; ni++)
                    mma16816(acc[mi][ni], af[mi], bl[ni >> 1][(ni & 1) * 2], bl[ni >> 1][(ni & 1) * 2 + 1]);
            if (nterms == 3) {
#pragma unroll
                for (int mi = 0; mi < 4; mi++) {
                    uint32_t ol = (uint32_t)((arow0 + mi * 16) * 128 + ks * 32 + akof + 64);
                    ol ^= (ol >> 3) & 0x70;
                    ldsm_x4(af[mi], sA + ol);
                }
#pragma unroll
                for (int mi = 0; mi < 4; mi++)
#pragma unroll
                    for (int ni = 0; ni < 4; ni++)
                        mma16816(acc[mi][ni], af[mi], bh[ni >> 1][(ni & 1) * 2], bh[ni >> 1][(ni & 1) * 2 + 1]);
            }
        }
        __syncthreads();
        if (kt + 3 < nk) issue(kt + 3, s);
    }

    int g = lane >> 2, t4 = lane & 3;
#pragma unroll
    for (int mi = 0; mi < 4; mi++) {
        int r0 = m0 + warp_m * 64 + mi * 16 + g;
#pragma unroll
        for (int ni = 0; ni < 4; ni++) {
            int col = n0 + warp_n * 32 + ni * 8 + 2 * t4;
            if (col >= N) continue;
            float4 v = acc[mi][ni];
            if (D) {
                float2 d0 = *reinterpret_cast<const float2*>(D + (size_t)r0 * ldc + col);
                float2 d1 = *reinterpret_cast<const float2*>(D + (size_t)(r0 + 8) * ldc + col);
                v.x += d0.x; v.y += d0.y; v.z += d1.x; v.w += d1.y;
            }
            if (mode == 1) {
                v.x = 15.0f * tanhf(v.x * (1.f / 15.f));
                v.y = 15.0f * tanhf(v.y * (1.f / 15.f));
                v.z = 15.0f * tanhf(v.z * (1.f / 15.f));
                v.w = 15.0f * tanhf(v.w * (1.f / 15.f));
            } else if (mode == 2) {
                v.x = (v.x > 0.f) ? v.x * v.x : 0.f;
                v.y = (v.y > 0.f) ? v.y * v.y : 0.f;
                v.z = (v.z > 0.f) ? v.z * v.z : 0.f;
                v.w = (v.w > 0.f) ? v.w * v.w : 0.f;
            }
            if (C) {
                *reinterpret_cast<float2*>(C + (size_t)r0 * ldc + col) = make_float2(v.x, v.y);
                *reinterpret_cast<float2*>(C + (size_t)(r0 + 8) * ldc + col) = make_float2(v.z, v.w);
            }
            if (Chi) {
                __half hx, lx_, hy, ly, hz, lz, hw, lw;
                splith(v.x, hx, lx_); splith(v.y, hy, ly);
                splith(v.z, hz, lz);  splith(v.w, hw, lw);
                *reinterpret_cast<uint32_t*>(Chi + (size_t)r0 * ldp + col)       = packh2(hx, hy);
                *reinterpret_cast<uint32_t*>(Clo + (size_t)r0 * ldp + col)       = packh2(lx_, ly);
                *reinterpret_cast<uint32_t*>(Chi + (size_t)(r0 + 8) * ldp + col) = packh2(hz, hw);
                *reinterpret_cast<uint32_t*>(Clo + (size_t)(r0 + 8) * ldp + col) = packh2(lz, lw);
            }
        }
    }
}

// ---------------- per-token q/k/v build -> fp16 hi/lo planes --------------
__global__ void build_qkv_kernel(const int* __restrict__ idx,
                                 const float* __restrict__ cosp, const float* __restrict__ sinp,
                                 const float* __restrict__ vg, const float* __restrict__ vetab)
{
    int row = blockIdx.x;
    int h    = threadIdx.x >> 5;
    int lane = threadIdx.x & 31;
    const float* cosr = cosp + (size_t)row * (DR_ / 2);
    const float* sinr = sinp + (size_t)row * (DR_ / 2);

    float gv = g_xn[(size_t)row * C_ + lane] * vg[lane * H_ + h];
    gv = warp_sum(gv);
    float gate = 2.0f / (1.0f + __expf(-gv));

    int r16 = (lane < 16) ? lane : lane - 16;
    float c = cosr[r16], s = sinr[r16];
    size_t base = (size_t)row * C_ + h * 64;

    // k
    float kn = g_kv[(size_t)row * KVW + h * 96 + lane];
    const float* dro = g_down + (size_t)row * DOWNW + 512;
    float kr = (lane < 16) ? (dro[lane] * c + dro[lane + 16] * s)
                           : (-dro[lane - 16] * s + dro[lane] * c);
    float ssk = warp_sum(kn * kn + kr * kr);
    float rk = rsqrtf(ssk * (1.0f / 64.0f) + EPS_);
    __half hh_, ll_;
    splith(kn * rk, hh_, ll_);  g_k_h[base + lane]      = hh_; g_k_l[base + lane]      = ll_;
    splith(kr * rk, hh_, ll_);  g_k_h[base + lane + 32] = hh_; g_k_l[base + lane + 32] = ll_;

    // q (pre-scaled by 1/sqrt(HD) = 0.125)
    const float* qp = g_qpre + (size_t)row * C_ + h * 64;
    float qn = qp[lane];
    float qr = (lane < 16) ? (qp[32 + lane] * c + qp[48 + lane] * s)
                           : (-qp[16 + lane] * s + qp[32 + lane] * c);
    float ssq = warp_sum(qn * qn + qr * qr);
    float rq = rsqrtf(ssq * (1.0f / 64.0f) + EPS_) * 0.125f;
    splith(qn * rq, hh_, ll_);  g_q_h[base + lane]      = hh_; g_q_l[base + lane]      = ll_;
    splith(qr * rq, hh_, ll_);  g_q_h[base + lane + 32] = hh_; g_q_l[base + lane + 32] = ll_;

    // v
    int tok = idx[row];
    const float* ver = vetab + (size_t)tok * C_ + h * 64;
    const float* kvv = g_kv + (size_t)row * KVW + h * 96 + 32;
    splith(kvv[lane]      + gate * ver[lane],      hh_, ll_);
    g_v_h[base + lane]      = hh_; g_v_l[base + lane]      = ll_;
    splith(kvv[lane + 32] + gate * ver[lane + 32], hh_, ll_);
    g_v_h[base + lane + 32] = hh_; g_v_l[base + lane + 32] = ll_;
}

// ---------------- tensor-core causal flash attention ----------------------
__global__ __launch_bounds__(128) void attn_mma()
{
    extern __shared__ __align__(1024) char dsm[];
    uint32_t smb = smem_u32(dsm);
    int tid = threadIdx.x;
    int wid = tid >> 5, lane = tid & 31;
    int q0 = blockIdx.x * 64;
    int hh = blockIdx.y;
    int b  = blockIdx.z;
    int t4 = lane & 3, g = lane >> 2;

#pragma unroll
    for (int j = 0; j < 4; j++) {
        int idxq = tid + j * 128;
        int r = idxq >> 3, ch = idxq & 7;
        uint32_t off = (uint32_t)(r * 128 + ch * 16);
        off ^= (off >> 3) & 0x70;
        size_t src = (size_t)(b * T_ + q0 + r) * C_ + hh * 64 + ch * 8;
        CP16(smb + off,        g_q_h + src);
        CP16(smb + 8192 + off, g_q_l + src);
    }
    CPCOMMIT(); CPWAITG(0);
    __syncthreads();

    int arow0 = wid * 16 + (lane & 15);
    int akof  = (lane & 16);
    uint32_t qh[4][4], ql[4][4];
#pragma unroll
    for (int ks = 0; ks < 4; ks++) {
        uint32_t off = (uint32_t)(arow0 * 128 + ks * 32 + akof);
        off ^= (off >> 3) & 0x70;
        ldsm_x4(qh[ks], smb + off);
        ldsm_x4(ql[ks], smb + 8192 + off);
    }

    float4 oacc[8];
#pragma unroll
    for (int i = 0; i < 8; i++) oacc[i] = make_float4(0.f, 0.f, 0.f, 0.f);
    float mrow0 = -1e30f, mrow1 = -1e30f, lrow0 = 0.f, lrow1 = 0.f;

    for (int k0 = 0; k0 <= q0; k0 += 64) {
#pragma unroll
        for (int j = 0; j < 4; j++) {
            int idxq = tid + j * 128;
            int r = idxq >> 3, ch = idxq & 7;
            uint32_t off = (uint32_t)(r * 128 + ch * 16);
            off ^= (off >> 3) & 0x70;
            size_t src = (size_t)(b * T_ + k0 + r) * C_ + hh * 64 + ch * 8;
            CP16(smb + 16384 + off, g_k_h + src);
            CP16(smb + 24576 + off, g_k_l + src);
            CP16(smb + 32768 + off, g_v_h + src);
            CP16(smb + 40960 + off, g_v_l + src);
        }
        CPCOMMIT(); CPWAITG(0);
        __syncthreads();

        float4 sacc[8];
#pragma unroll
        for (int i = 0; i < 8; i++) sacc[i] = make_float4(0.f, 0.f, 0.f, 0.f);
#pragma unroll
        for (int ks = 0; ks < 4; ks++) {
#pragma unroll
            for (int njp = 0; njp < 4; njp++) {
                uint32_t kh[4], kl[4];
                uint32_t off = (uint32_t)(((lane & 15) + njp * 16) * 128 + ks * 32 + akof);
                off ^= (off >> 3) & 0x70;
                ldsm_x4(kh, smb + 16384 + off);
                ldsm_x4(kl, smb + 24576 + off);
                mma16816(sacc[2 * njp],     qh[ks], kh[0], kh[2]);
                mma16816(sacc[2 * njp + 1], qh[ks], kh[1], kh[3]);
                mma16816(sacc[2 * njp],     qh[ks], kl[0], kl[2]);
                mma16816(sacc[2 * njp + 1], qh[ks], kl[1], kl[3]);
                mma16816(sacc[2 * njp],     ql[ks], kh[0], kh[2]);
                mma16816(sacc[2 * njp + 1], ql[ks], kh[1], kh[3]);
            }
        }

        if (k0 == q0) {
            int qiA = wid * 16 + g, qiB = qiA + 8;
#pragma unroll
            for (int nj = 0; nj < 8; nj++) {
                int ki = nj * 8 + t4 * 2;
                if (ki     > qiA) sacc[nj].x = -1e30f;
                if (ki + 1 > qiA) sacc[nj].y = -1e30f;
                if (ki     > qiB) sacc[nj].z = -1e30f;
                if (ki + 1 > qiB) sacc[nj].w = -1e30f;
            }
        }

        float mx0 = -1e30f, mx1 = -1e30f;
#pragma unroll
        for (int nj = 0; nj < 8; nj++) {
            mx0 = fmaxf(mx0, fmaxf(sacc[nj].x, sacc[nj].y));
            mx1 = fmaxf(mx1, fmaxf(sacc[nj].z, sacc[nj].w));
        }
        mx0 = fmaxf(mx0, __shfl_xor_sync(0xffffffffu, mx0, 1));
        mx0 = fmaxf(mx0, __shfl_xor_sync(0xffffffffu, mx0, 2));
        mx1 = fmaxf(mx1, __shfl_xor_sync(0xffffffffu, mx1, 1));
        mx1 = fmaxf(mx1, __shfl_xor_sync(0xffffffffu, mx1, 2));
        float mn0 = fmaxf(mrow0, mx0), mn1 = fmaxf(mrow1, mx1);
        float c0 = __expf(mrow0 - mn0), c1 = __expf(mrow1 - mn1);
        float sum0 = 0.f, sum1 = 0.f;
#pragma unroll
        for (int nj = 0; nj < 8; nj++) {
            sacc[nj].x = __expf(sacc[nj].x - mn0);
            sacc[nj].y = __expf(sacc[nj].y - mn0);
            sacc[nj].z = __expf(sacc[nj].z - mn1);
            sacc[nj].w = __expf(sacc[nj].w - mn1);
            sum0 += sacc[nj].x + sacc[nj].y;
            sum1 += sacc[nj].z + sacc[nj].w;
        }
        sum0 += __shfl_xor_sync(0xffffffffu, sum0, 1);
        sum0 += __shfl_xor_sync(0xffffffffu, sum0, 2);
        sum1 += __shfl_xor_sync(0xffffffffu, sum1, 1);
        sum1 += __shfl_xor_sync(0xffffffffu, sum1, 2);
        lrow0 = lrow0 * c0 + sum0;
        lrow1 = lrow1 * c1 + sum1;
        mrow0 = mn0; mrow1 = mn1;
#pragma unroll
        for (int nd = 0; nd < 8; nd++) {
            oacc[nd].x *= c0; oacc[nd].y *= c0;
            oacc[nd].z *= c1; oacc[nd].w *= c1;
        }

#pragma unroll
        for (int kk = 0; kk < 4; kk++) {
            __half h0,l0,h1,l1,h2,l2,h3,l3,h4,l4,h5,l5,h6,l6,h7,l7;
            splith(sacc[2*kk].x, h0, l0);   splith(sacc[2*kk].y, h1, l1);
            splith(sacc[2*kk].z, h2, l2);   splith(sacc[2*kk].w, h3, l3);
            splith(sacc[2*kk+1].x, h4, l4); splith(sacc[2*kk+1].y, h5, l5);
            splith(sacc[2*kk+1].z, h6, l6); splith(sacc[2*kk+1].w, h7, l7);
            uint32_t ah[4] = { packh2(h0,h1), packh2(h2,h3), packh2(h4,h5), packh2(h6,h7) };
            uint32_t al[4] = { packh2(l0,l1), packh2(l2,l3), packh2(l4,l5), packh2(l6,l7) };
#pragma unroll
            for (int ndp = 0; ndp < 4; ndp++) {
                uint32_t vh[4], vl[4];
                uint32_t off = (uint32_t)((kk * 16 + (lane & 15)) * 128 + ndp * 32 + akof);
                off ^= (off >> 3) & 0x70;
                ldsm_x4t(vh, smb + 32768 + off);
                ldsm_x4t(vl, smb + 40960 + off);
                mma16816(oacc[2 * ndp],     ah, vh[0], vh[1]);
                mma16816(oacc[2 * ndp + 1], ah, vh[2], vh[3]);
                mma16816(oacc[2 * ndp],     ah, vl[0], vl[1]);
                mma16816(oacc[2 * ndp + 1], ah, vl[2], vl[3]);
                mma16816(oacc[2 * ndp],     al, vh[0], vh[1]);
                mma16816(oacc[2 * ndp + 1], al, vh[2], vh[3]);
            }
        }
        __syncthreads();
    }

    float inv0 = 1.0f / lrow0, inv1 = 1.0f / lrow1;
    int r0 = q0 + wid * 16 + g, r1 = r0 + 8;
    size_t b0 = (size_t)(b * T_ + r0) * C_ + hh * 64;
    size_t b1 = (size_t)(b * T_ + r1) * C_ + hh * 64;
#pragma unroll
    for (int nd = 0; nd < 8; nd++) {
        int d = nd * 8 + t4 * 2;
        __half hx, lx_, hy, ly;
        splith(oacc[nd].x * inv0, hx, lx_);
        splith(oacc[nd].y * inv0, hy, ly);
        *reinterpret_cast<uint32_t*>(g_y_h + b0 + d) = packh2(hx, hy);
        *reinterpret_cast<uint32_t*>(g_y_l + b0 + d) = packh2(lx_, ly);
        splith(oacc[nd].z * inv1, hx, lx_);
        splith(oacc[nd].w * inv1, hy, ly);
        *reinterpret_cast<uint32_t*>(g_y_h + b1 + d) = packh2(hx, hy);
        *reinterpret_cast<uint32_t*>(g_y_l + b1 + d) = packh2(lx_, ly);
    }
}

// ---------------- host orchestration ----------------
extern "C" void kernel_launch(void* const* d_in, const int* in_sizes, int n_in,
                              void* d_out, int out_size)
{
    (void)in_sizes; (void)n_in; (void)out_size;
    const int*   idx  = (const int*)  d_in[0];
    const float* cosp = (const float*)d_in[1];
    const float* sinp = (const float*)d_in[2];
    const float* wte  = (const float*)d_in[3];
    const float* vemb = (const float*)d_in[4];
    const float* wd   = (const float*)d_in[5];
    const float* wukv = (const float*)d_in[6];
    const float* wuq  = (const float*)d_in[7];
    const float* vg   = (const float*)d_in[8];
    const float* ap   = (const float*)d_in[9];
    const float* fc   = (const float*)d_in[10];
    const float* pj   = (const float*)d_in[11];
    const float* lr   = (const float*)d_in[12];
    const float* lx   = (const float*)d_in[13];
    const float* lmh  = (const float*)d_in[14];
    float* out = (float*)d_out;

    float *px, *pdown, *pkv, *pqpre;
    cudaGetSymbolAddress((void**)&px,    g_x);
    cudaGetSymbolAddress((void**)&pdown, g_down);
    cudaGetSymbolAddress((void**)&pkv,   g_kv);
    cudaGetSymbolAddress((void**)&pqpre, g_qpre);

    __half *wd_h, *wd_l, *wukv_h, *wukv_l, *wuq_h, *wuq_l, *ap_h, *ap_l;
    __half *fc_h, *fc_l, *pj_h, *pj_l, *lmh_h, *lmh_l;
    __half *xn_h, *xn_l, *dn_h, *dn_l, *y_h, *y_l, *h_h, *h_l;
    cudaGetSymbolAddress((void**)&wd_h,   g_wd_h);   cudaGetSymbolAddress((void**)&wd_l,   g_wd_l);
    cudaGetSymbolAddress((void**)&wukv_h, g_wukv_h); cudaGetSymbolAddress((void**)&wukv_l, g_wukv_l);
    cudaGetSymbolAddress((void**)&wuq_h,  g_wuq_h);  cudaGetSymbolAddress((void**)&wuq_l,  g_wuq_l);
    cudaGetSymbolAddress((void**)&ap_h,   g_ap_h);   cudaGetSymbolAddress((void**)&ap_l,   g_ap_l);
    cudaGetSymbolAddress((void**)&fc_h,   g_fc_h);   cudaGetSymbolAddress((void**)&fc_l,   g_fc_l);
    cudaGetSymbolAddress((void**)&pj_h,   g_pj_h);   cudaGetSymbolAddress((void**)&pj_l,   g_pj_l);
    cudaGetSymbolAddress((void**)&lmh_h,  g_lmh_h);  cudaGetSymbolAddress((void**)&lmh_l,  g_lmh_l);
    cudaGetSymbolAddress((void**)&xn_h,   g_xn_h);   cudaGetSymbolAddress((void**)&xn_l,   g_xn_l);
    cudaGetSymbolAddress((void**)&dn_h,   g_dn_h);   cudaGetSymbolAddress((void**)&dn_l,   g_dn_l);
    cudaGetSymbolAddress((void**)&y_h,    g_y_h);    cudaGetSymbolAddress((void**)&y_l,    g_y_l);
    cudaGetSymbolAddress((void**)&h_h,    g_h_h);    cudaGetSymbolAddress((void**)&h_l,    g_h_l);

    const int SMEMSZ = 3 * STG4;   // 96 KB
    cudaFuncSetAttribute(gemm_h4, cudaFuncAttributeMaxDynamicSharedMemorySize, SMEMSZ);
    const int ASM = 49152;         // 48 KB
    cudaFuncSetAttribute(attn_mma, cudaFuncAttributeMaxDynamicSharedMemorySize, ASM);

    // ---- split weights ----
    wsplit_pad<<<2048, 256>>>(wd, wd_h, wd_l, DOWNW, WDP, (long)L_ * C_ * WDP);
    wsplit8<<<2048, 256>>>((const float4*)wukv, (uint4*)wukv_h, (uint4*)wukv_l, (long)L_ * DC_ * KVW / 8);
    wsplit8<<<2048, 256>>>((const float4*)wuq,  (uint4*)wuq_h,  (uint4*)wuq_l,  (long)L_ * DC1_ * C_ / 8);
    wsplit8<<<2048, 256>>>((const float4*)ap,   (uint4*)ap_h,   (uint4*)ap_l,   (long)L_ * C_ * C_ / 8);
    wsplit8<<<2048, 256>>>((const float4*)fc,   (uint4*)fc_h,   (uint4*)fc_l,   (long)L_ * C_ * 4 * C_ / 8);
    wsplit8<<<2048, 256>>>((const float4*)pj,   (uint4*)pj_h,   (uint4*)pj_l,   (long)L_ * 4 * C_ * C_ / 8);
    wsplit8<<<2048, 256>>>((const float4*)lmh,  (uint4*)lmh_h,  (uint4*)lmh_l,  (long)C_ * V_ / 8);

    const int GM = NTOK / 128;     // 16 m-blocks

    embed_kernel<<<NTOK, 256>>>(idx, wte);

    for (int l = 0; l < L_; l++) {
        mix_norm_kernel<<<NTOK, 256>>>(lr, lx, l);

        gemm_h4<<<dim3(GM, WDP / 128), 256, SMEMSZ>>>(
            xn_h, xn_l, wd_h + (size_t)l * C_ * WDP, wd_l + (size_t)l * C_ * WDP,
            pdown, nullptr, dn_h, dn_l,
            DOWNW, C_, C_, WDP, DOWNW, DOWNW, 0, 3);

        gemm_h4<<<dim3(GM, KVW / 128), 256, SMEMSZ>>>(
            dn_h, dn_l, wukv_h + (size_t)l * DC_ * KVW, wukv_l + (size_t)l * DC_ * KVW,
            pkv, nullptr, nullptr, nullptr,
            KVW, DC_, DOWNW, KVW, KVW, 0, 0, 3);

        gemm_h4<<<dim3(GM, C_ / 128), 256, SMEMSZ>>>(
            dn_h + DC_, dn_l + DC_, wuq_h + (size_t)l * DC1_ * C_, wuq_l + (size_t)l * DC1_ * C_,
            pqpre, nullptr, nullptr, nullptr,
            C_, DC1_, DOWNW, C_, C_, 0, 0, 3);

        build_qkv_kernel<<<NTOK, 512>>>(idx, cosp, sinp,
                                        vg + (size_t)l * 32 * H_,
                                        vemb + (size_t)l * V_ * C_);

        attn_mma<<<dim3(T_ / 64, H_, B_), 128, ASM>>>();

        gemm_h4<<<dim3(GM, C_ / 128), 256, SMEMSZ>>>(
            y_h, y_l, ap_h + (size_t)l * C_ * C_, ap_l + (size_t)l * C_ * C_,
            px, px, nullptr, nullptr,
            C_, C_, C_, C_, C_, 0, 0, 3);

        mix_norm_kernel<<<NTOK, 256>>>(nullptr, nullptr, 0);

        gemm_h4<<<dim3(GM, 4 * C_ / 128), 256, SMEMSZ>>>(
            xn_h, xn_l, fc_h + (size_t)l * C_ * 4 * C_, fc_l + (size_t)l * C_ * 4 * C_,
            nullptr, nullptr, h_h, h_l,
            4 * C_, C_, C_, 4 * C_, 0, 4 * C_, 2, 3);

        gemm_h4<<<dim3(GM, C_ / 128), 256, SMEMSZ>>>(
            h_h, h_l, pj_h + (size_t)l * 4 * C_ * C_, pj_l + (size_t)l * 4 * C_ * C_,
            px, px, nullptr, nullptr,
            C_, 4 * C_, 4 * C_, C_, C_, 0, 0, 3);
    }

    mix_norm_kernel<<<NTOK, 256>>>(nullptr, nullptr, 0);
    // out = softcap(xn @ lm_head), 2-term (activation-residual term dropped)
    gemm_h4<<<dim3(GM, V_ / 128), 256, SMEMSZ>>>(
        xn_h, xn_l, lmh_h, lmh_l,
        out, nullptr, nullptr, nullptr,
        V_, C_, C_, V_, V_, 0, 1, 2);
}

// round 10
// speedup vs baseline: 1.7120x; 1.0223x over previous
#include <cuda_runtime.h>
#include <cuda_fp16.h>
#include <math.h>
#include <stdint.h>

// ---------------- problem constants ----------------
#define B_    2
#define T_    1024
#define C_    1024
#define H_    16
#define HD_   64
#define DC_   256
#define DC1_  256
#define DR_   32
#define DN_   32
#define V_    32000
#define L_    4
#define NTOK  (B_*T_)             // 2048
#define DOWNW (DC_+DC1_+DR_)      // 544
#define WDP   640                 // padded wd output width
#define KVW   (H_*(DN_+HD_))      // 1536
#define EPS_  1.1920929e-07f

// ---------------- fp32 scratch ----------------
__device__ float g_x   [NTOK*C_];
__device__ float g_x0  [NTOK*C_];
__device__ float g_xn  [NTOK*C_];
__device__ float g_down[NTOK*DOWNW];
__device__ float g_kv  [NTOK*KVW];
__device__ float g_qpre[NTOK*C_];

// ---------------- fp16 hi/lo planes ----------------
__device__ __half g_wd_h  [L_*C_*WDP],    g_wd_l  [L_*C_*WDP];
__device__ __half g_wukv_h[L_*DC_*KVW],   g_wukv_l[L_*DC_*KVW];
__device__ __half g_wuq_h [L_*DC1_*C_],   g_wuq_l [L_*DC1_*C_];
__device__ __half g_ap_h  [L_*C_*C_],     g_ap_l  [L_*C_*C_];
__device__ __half g_fc_h  [L_*C_*4*C_],   g_fc_l  [L_*C_*4*C_];
__device__ __half g_pj_h  [L_*4*C_*C_],   g_pj_l  [L_*4*C_*C_];
__device__ __half g_lmh_h [C_*V_],        g_lmh_l [C_*V_];
__device__ __half g_xn_h  [NTOK*C_],      g_xn_l  [NTOK*C_];
__device__ __half g_dn_h  [NTOK*DOWNW],   g_dn_l  [NTOK*DOWNW];
__device__ __half g_y_h   [NTOK*C_],      g_y_l   [NTOK*C_];
__device__ __half g_h_h   [NTOK*4*C_],    g_h_l   [NTOK*4*C_];
// attention operand planes (q pre-scaled by 0.125)
__device__ __half g_q_h   [NTOK*C_],      g_q_l   [NTOK*C_];
__device__ __half g_k_h   [NTOK*C_],      g_k_l   [NTOK*C_];
__device__ __half g_v_h   [NTOK*C_],      g_v_l   [NTOK*C_];

// ---------------- helpers ----------------
__device__ __forceinline__ uint32_t smem_u32(const void* p) {
    uint32_t a;
    asm("{ .reg .u64 t; cvta.to.shared.u64 t, %1; cvt.u32.u64 %0, t; }" : "=r"(a) : "l"(p));
    return a;
}
__device__ __forceinline__ float warp_sum(float v) {
    v += __shfl_xor_sync(0xffffffffu, v, 16);
    v += __shfl_xor_sync(0xffffffffu, v, 8);
    v += __shfl_xor_sync(0xffffffffu, v, 4);
    v += __shfl_xor_sync(0xffffffffu, v, 2);
    v += __shfl_xor_sync(0xffffffffu, v, 1);
    return v;
}
__device__ __forceinline__ float block_sum(float v) {
    __shared__ float sh[32];
    int lane = threadIdx.x & 31, wid = threadIdx.x >> 5;
    v = warp_sum(v);
    if (lane == 0) sh[wid] = v;
    __syncthreads();
    int nw = blockDim.x >> 5;
    if (wid == 0) {
        float t = (lane < nw) ? sh[lane] : 0.f;
        t = warp_sum(t);
        if (lane == 0) sh[0] = t;
    }
    __syncthreads();
    return sh[0];
}
__device__ __forceinline__ void splith(float x, __half& hi, __half& lo) {
    hi = __float2half_rn(x);
    lo = __float2half_rn(x - __half2float(hi));
}
__device__ __forceinline__ uint32_t packh2(__half a, __half b) {
    return (uint32_t)__half_as_ushort(a) | ((uint32_t)__half_as_ushort(b) << 16);
}

// ---------------- mma / ldmatrix / cp.async wrappers ----------------
__device__ __forceinline__ void ldsm_x4(uint32_t* r, uint32_t addr) {
    asm volatile("ldmatrix.sync.aligned.m8n8.x4.shared.b16 {%0,%1,%2,%3}, [%4];"
                 : "=r"(r[0]), "=r"(r[1]), "=r"(r[2]), "=r"(r[3]) : "r"(addr));
}
__device__ __forceinline__ void ldsm_x4t(uint32_t* r, uint32_t addr) {
    asm volatile("ldmatrix.sync.aligned.m8n8.x4.trans.shared.b16 {%0,%1,%2,%3}, [%4];"
                 : "=r"(r[0]), "=r"(r[1]), "=r"(r[2]), "=r"(r[3]) : "r"(addr));
}
__device__ __forceinline__ void mma16816(float4& d, const uint32_t* a, uint32_t b0, uint32_t b1) {
    asm volatile(
        "mma.sync.aligned.m16n8k16.row.col.f32.f16.f16.f32 "
        "{%0,%1,%2,%3},{%4,%5,%6,%7},{%8,%9},{%0,%1,%2,%3};"
        : "+f"(d.x), "+f"(d.y), "+f"(d.z), "+f"(d.w)
        : "r"(a[0]), "r"(a[1]), "r"(a[2]), "r"(a[3]), "r"(b0), "r"(b1));
}
#define CP16(dst, src) \
    asm volatile("cp.async.cg.shared.global [%0], [%1], 16;" :: "r"(dst), "l"(src) : "memory")
#define CPCOMMIT() asm volatile("cp.async.commit_group;" ::: "memory")
#define CPWAITG(n) asm volatile("cp.async.wait_group " #n ";" ::: "memory")

// ---------------- fast vectorized split: 8 floats/thread ----------------
__global__ void wsplit8(const float4* __restrict__ src,
                        uint4* __restrict__ hi, uint4* __restrict__ lo, long n8)
{
    long stride = (long)gridDim.x * blockDim.x;
    for (long i = (long)blockIdx.x * blockDim.x + threadIdx.x; i < n8; i += stride) {
        float4 f0 = src[2 * i];
        float4 f1 = src[2 * i + 1];
        __half h0,l0,h1,l1,h2,l2,h3,l3,h4,l4,h5,l5,h6,l6,h7,l7;
        splith(f0.x,h0,l0); splith(f0.y,h1,l1); splith(f0.z,h2,l2); splith(f0.w,h3,l3);
        splith(f1.x,h4,l4); splith(f1.y,h5,l5); splith(f1.z,h6,l6); splith(f1.w,h7,l7);
        hi[i] = make_uint4(packh2(h0,h1), packh2(h2,h3), packh2(h4,h5), packh2(h6,h7));
        lo[i] = make_uint4(packh2(l0,l1), packh2(l2,l3), packh2(l4,l5), packh2(l6,l7));
    }
}

// ---------------- padded split, vectorized (wd only) --------------------
// dst rows WDP=640 floats (160 float4), src rows DOWNW=544 floats (136 float4).
__global__ void wsplit_pad4(const float* __restrict__ src,
                            uint2* __restrict__ hi, uint2* __restrict__ lo, int n4)
{
    int stride = gridDim.x * blockDim.x;
    for (int i = blockIdx.x * blockDim.x + threadIdx.x; i < n4; i += stride) {
        int row = i / (WDP / 4);
        int c4  = i - row * (WDP / 4);
        float4 f = make_float4(0.f, 0.f, 0.f, 0.f);
        if (c4 < DOWNW / 4)
            f = *reinterpret_cast<const float4*>(src + (size_t)row * DOWNW + c4 * 4);
        __half h0,l0,h1,l1,h2,l2,h3,l3;
        splith(f.x,h0,l0); splith(f.y,h1,l1); splith(f.z,h2,l2); splith(f.w,h3,l3);
        hi[i] = make_uint2(packh2(h0,h1), packh2(h2,h3));
        lo[i] = make_uint2(packh2(l0,l1), packh2(l2,l3));
    }
}

// ---------------- embedding + rmsnorm ----------------
__global__ void embed_kernel(const int* __restrict__ idx, const float* __restrict__ wte) {
    int row = blockIdx.x;
    int tok = idx[row];
    const float* src = wte + (size_t)tok * C_;
    float s = 0.f;
    for (int i = threadIdx.x; i < C_; i += blockDim.x) { float v = src[i]; s += v * v; }
    s = block_sum(s);
    float r = rsqrtf(s * (1.0f / C_) + EPS_);
    for (int i = threadIdx.x; i < C_; i += blockDim.x) {
        float v = src[i] * r;
        g_x [(size_t)row * C_ + i] = v;
        g_x0[(size_t)row * C_ + i] = v;
    }
}

__global__ void mix_norm_kernel(const float* lr, const float* lx, int layer) {
    int row = blockIdx.x;
    float a = lr ? lr[layer] : 1.0f;
    float b = lx ? lx[layer] : 0.0f;
    float*       xr  = g_x  + (size_t)row * C_;
    const float* x0r = g_x0 + (size_t)row * C_;
    float s = 0.f;
    for (int i = threadIdx.x; i < C_; i += blockDim.x) {
        float v = a * xr[i] + b * x0r[i];
        xr[i] = v;
        s += v * v;
    }
    s = block_sum(s);
    float r = rsqrtf(s * (1.0f / C_) + EPS_);
    for (int i = threadIdx.x; i < C_; i += blockDim.x) {
        float v = xr[i] * r;
        g_xn[(size_t)row * C_ + i] = v;
        __half h, l;
        splith(v, h, l);
        g_xn_h[(size_t)row * C_ + i] = h;
        g_xn_l[(size_t)row * C_ + i] = l;
    }
}

// ---------------- 3xFP16 tensor-core GEMM v5 (single-sync pipeline) -----
#define STG4 32768
__global__ __launch_bounds__(256, 2) void gemm_h4(
    const __half* __restrict__ Ah, const __half* __restrict__ Al,
    const __half* __restrict__ Bh, const __half* __restrict__ Bl,
    float* __restrict__ C, const float* __restrict__ D,
    __half* __restrict__ Chi, __half* __restrict__ Clo,
    int N, int K, int lda, int ldb, int ldc, int ldp, int mode, int nterms)
{
    extern __shared__ __align__(1024) char sm[];
    int tid = threadIdx.x;
    int wid = tid >> 5, lane = tid & 31;
    int warp_m = wid >> 2, warp_n = wid & 3;
    int m0 = blockIdx.x * 128, n0 = blockIdx.y * 128;
    uint32_t smb = smem_u32(sm);

    float4 acc[4][4];
#pragma unroll
    for (int i = 0; i < 4; i++)
#pragma unroll
        for (int j = 0; j < 4; j++) acc[i][j] = make_float4(0.f, 0.f, 0.f, 0.f);

    int a_m   = tid >> 3;
    int a_hl  = (tid >> 2) & 1;
    int a_j   = tid & 3;
    int b_k0  = tid >> 4;
    int b_j   = tid & 15;
    const __half* Asel = a_hl ? Al : Ah;

    int arow0 = warp_m * 64 + (lane & 15);
    int akof  = (lane & 16);
    int bkr   = (lane & 15);
    int bco   = warp_n * 64 + ((lane >> 4) << 4);
    int ksrot = wid & 1;     // per-warp ks rotation (destagger stalls)

    int nk = K >> 5;

    auto issue = [&](int kt, int stg) {
        uint32_t sA = smb + stg * STG4;
        uint32_t sB = sA + 16384;
#pragma unroll
        for (int r = 0; r < 4; r++) {
            int m = a_m + r * 32;
            uint32_t off = (uint32_t)(m * 128 + a_hl * 64 + a_j * 16);
            off ^= (off >> 3) & 0x70;
            const __half* src = Asel + (size_t)(m0 + m) * lda + kt * 32 + a_j * 8;
            CP16(sA + off, src);
        }
#pragma unroll
        for (int r = 0; r < 4; r++) {
            int k = b_k0 + (r & 1) * 16;
            const __half* Bp = (r < 2) ? Bh : Bl;
            uint32_t off = ((uint32_t)(k * 256 + b_j * 16)) ^ ((uint32_t)(k & 7) << 4);
            off += (r < 2) ? 0u : 8192u;
            const __half* src = Bp + (size_t)(kt * 32 + k) * ldb + n0 + b_j * 8;
            CP16(sB + off, src);
        }
        CPCOMMIT();
    };

    issue(0, 0);
    issue(1, 1);

    for (int kt = 0; kt < nk; kt++) {
        if (kt == nk - 1) { CPWAITG(0); } else { CPWAITG(1); }
        __syncthreads();
        // overlap next-stage cp.async with the mma phase (3-stage safe:
        // write (kt+2)%3, read kt%3, in-flight (kt+1)%3 all distinct)
        if (kt + 2 < nk) issue(kt + 2, (kt + 2) % 3);

        int s = kt % 3;
        uint32_t sA  = smb + s * STG4;
        uint32_t sBh = sA + 16384;
        uint32_t sBl = sA + 24576;
#pragma unroll
        for (int ks0 = 0; ks0 < 2; ks0++) {
            int ks = ks0 ^ ksrot;
            uint32_t af[4][4], bh[2][4], bl[2][4];
            // load all hi/lo B + hi A up front for ILP
#pragma unroll
            for (int mi = 0; mi < 4; mi++) {
                uint32_t oh = (uint32_t)((arow0 + mi * 16) * 128 + ks * 32 + akof);
                oh ^= (oh >> 3) & 0x70;
                ldsm_x4(af[mi], sA + oh);
            }
#pragma unroll
            for (int nj = 0; nj < 2; nj++) {
                int krow = ks * 16 + bkr;
                uint32_t off = (uint32_t)(krow * 256 + bco + nj * 32) ^ ((uint32_t)(krow & 7) << 4);
                ldsm_x4t(bh[nj], sBh + off);
                ldsm_x4t(bl[nj], sBl + off);
            }
            // term 1: ahi * bhi
#pragma unroll
            for (int mi = 0; mi < 4; mi++)
#pragma unroll
                for (int ni = 0; ni < 4; ni++)
                    mma16816(acc[mi][ni], af[mi], bh[ni >> 1][(ni & 1) * 2], bh[ni >> 1][(ni & 1) * 2 + 1]);
            // term 2: ahi * blo
#pragma unroll
            for (int mi = 0; mi < 4; mi++)
#pragma unroll
                for (int ni = 0; ni < 4; ni++)
                    mma16816(acc[mi][ni], af[mi], bl[ni >> 1][(ni & 1) * 2], bl[ni >> 1][(ni & 1) * 2 + 1]);
            if (nterms == 3) {
                // term 3: alo * bhi (reuse af regs)
#pragma unroll
                for (int mi = 0; mi < 4; mi++) {
                    uint32_t ol = (uint32_t)((arow0 + mi * 16) * 128 + ks * 32 + akof + 64);
                    ol ^= (ol >> 3) & 0x70;
                    ldsm_x4(af[mi], sA + ol);
                }
#pragma unroll
                for (int mi = 0; mi < 4; mi++)
#pragma unroll
                    for (int ni = 0; ni < 4; ni++)
                        mma16816(acc[mi][ni], af[mi], bh[ni >> 1][(ni & 1) * 2], bh[ni >> 1][(ni & 1) * 2 + 1]);
            }
        }
    }

    int g = lane >> 2, t4 = lane & 3;
#pragma unroll
    for (int mi = 0; mi < 4; mi++) {
        int r0 = m0 + warp_m * 64 + mi * 16 + g;
#pragma unroll
        for (int ni = 0; ni < 4; ni++) {
            int col = n0 + warp_n * 32 + ni * 8 + 2 * t4;
            if (col >= N) continue;
            float4 v = acc[mi][ni];
            if (D) {
                float2 d0 = *reinterpret_cast<const float2*>(D + (size_t)r0 * ldc + col);
                float2 d1 = *reinterpret_cast<const float2*>(D + (size_t)(r0 + 8) * ldc + col);
                v.x += d0.x; v.y += d0.y; v.z += d1.x; v.w += d1.y;
            }
            if (mode == 1) {
                v.x = 15.0f * tanhf(v.x * (1.f / 15.f));
                v.y = 15.0f * tanhf(v.y * (1.f / 15.f));
                v.z = 15.0f * tanhf(v.z * (1.f / 15.f));
                v.w = 15.0f * tanhf(v.w * (1.f / 15.f));
            } else if (mode == 2) {
                v.x = (v.x > 0.f) ? v.x * v.x : 0.f;
                v.y = (v.y > 0.f) ? v.y * v.y : 0.f;
                v.z = (v.z > 0.f) ? v.z * v.z : 0.f;
                v.w = (v.w > 0.f) ? v.w * v.w : 0.f;
            }
            if (C) {
                *reinterpret_cast<float2*>(C + (size_t)r0 * ldc + col) = make_float2(v.x, v.y);
                *reinterpret_cast<float2*>(C + (size_t)(r0 + 8) * ldc + col) = make_float2(v.z, v.w);
            }
            if (Chi) {
                __half hx, lx_, hy, ly, hz, lz, hw, lw;
                splith(v.x, hx, lx_); splith(v.y, hy, ly);
                splith(v.z, hz, lz);  splith(v.w, hw, lw);
                *reinterpret_cast<uint32_t*>(Chi + (size_t)r0 * ldp + col)       = packh2(hx, hy);
                *reinterpret_cast<uint32_t*>(Clo + (size_t)r0 * ldp + col)       = packh2(lx_, ly);
                *reinterpret_cast<uint32_t*>(Chi + (size_t)(r0 + 8) * ldp + col) = packh2(hz, hw);
                *reinterpret_cast<uint32_t*>(Clo + (size_t)(r0 + 8) * ldp + col) = packh2(lz, lw);
            }
        }
    }
}

// ---------------- per-token q/k/v build -> fp16 hi/lo planes --------------
__global__ void build_qkv_kernel(const int* __restrict__ idx,
                                 const float* __restrict__ cosp, const float* __restrict__ sinp,
                                 const float* __restrict__ vg, const float* __restrict__ vetab)
{
    int row = blockIdx.x;
    int h    = threadIdx.x >> 5;
    int lane = threadIdx.x & 31;
    const float* cosr = cosp + (size_t)row * (DR_ / 2);
    const float* sinr = sinp + (size_t)row * (DR_ / 2);

    float gv = g_xn[(size_t)row * C_ + lane] * vg[lane * H_ + h];
    gv = warp_sum(gv);
    float gate = 2.0f / (1.0f + __expf(-gv));

    int r16 = (lane < 16) ? lane : lane - 16;
    float c = cosr[r16], s = sinr[r16];
    size_t base = (size_t)row * C_ + h * 64;

    float kn = g_kv[(size_t)row * KVW + h * 96 + lane];
    const float* dro = g_down + (size_t)row * DOWNW + 512;
    float kr = (lane < 16) ? (dro[lane] * c + dro[lane + 16] * s)
                           : (-dro[lane - 16] * s + dro[lane] * c);
    float ssk = warp_sum(kn * kn + kr * kr);
    float rk = rsqrtf(ssk * (1.0f / 64.0f) + EPS_);
    __half hh_, ll_;
    splith(kn * rk, hh_, ll_);  g_k_h[base + lane]      = hh_; g_k_l[base + lane]      = ll_;
    splith(kr * rk, hh_, ll_);  g_k_h[base + lane + 32] = hh_; g_k_l[base + lane + 32] = ll_;

    const float* qp = g_qpre + (size_t)row * C_ + h * 64;
    float qn = qp[lane];
    float qr = (lane < 16) ? (qp[32 + lane] * c + qp[48 + lane] * s)
                           : (-qp[16 + lane] * s + qp[32 + lane] * c);
    float ssq = warp_sum(qn * qn + qr * qr);
    float rq = rsqrtf(ssq * (1.0f / 64.0f) + EPS_) * 0.125f;
    splith(qn * rq, hh_, ll_);  g_q_h[base + lane]      = hh_; g_q_l[base + lane]      = ll_;
    splith(qr * rq, hh_, ll_);  g_q_h[base + lane + 32] = hh_; g_q_l[base + lane + 32] = ll_;

    int tok = idx[row];
    const float* ver = vetab + (size_t)tok * C_ + h * 64;
    const float* kvv = g_kv + (size_t)row * KVW + h * 96 + 32;
    splith(kvv[lane]      + gate * ver[lane],      hh_, ll_);
    g_v_h[base + lane]      = hh_; g_v_l[base + lane]      = ll_;
    splith(kvv[lane + 32] + gate * ver[lane + 32], hh_, ll_);
    g_v_h[base + lane + 32] = hh_; g_v_l[base + lane + 32] = ll_;
}

// ---------------- tensor-core causal flash attention ----------------------
__global__ __launch_bounds__(128) void attn_mma()
{
    extern __shared__ __align__(1024) char dsm[];
    uint32_t smb = smem_u32(dsm);
    int tid = threadIdx.x;
    int wid = tid >> 5, lane = tid & 31;
    int q0 = blockIdx.x * 64;
    int hh = blockIdx.y;
    int b  = blockIdx.z;
    int t4 = lane & 3, g = lane >> 2;

#pragma unroll
    for (int j = 0; j < 4; j++) {
        int idxq = tid + j * 128;
        int r = idxq >> 3, ch = idxq & 7;
        uint32_t off = (uint32_t)(r * 128 + ch * 16);
        off ^= (off >> 3) & 0x70;
        size_t src = (size_t)(b * T_ + q0 + r) * C_ + hh * 64 + ch * 8;
        CP16(smb + off,        g_q_h + src);
        CP16(smb + 8192 + off, g_q_l + src);
    }
    CPCOMMIT(); CPWAITG(0);
    __syncthreads();

    int arow0 = wid * 16 + (lane & 15);
    int akof  = (lane & 16);
    uint32_t qh[4][4], ql[4][4];
#pragma unroll
    for (int ks = 0; ks < 4; ks++) {
        uint32_t off = (uint32_t)(arow0 * 128 + ks * 32 + akof);
        off ^= (off >> 3) & 0x70;
        ldsm_x4(qh[ks], smb + off);
        ldsm_x4(ql[ks], smb + 8192 + off);
    }

    float4 oacc[8];
#pragma unroll
    for (int i = 0; i < 8; i++) oacc[i] = make_float4(0.f, 0.f, 0.f, 0.f);
    float mrow0 = -1e30f, mrow1 = -1e30f, lrow0 = 0.f, lrow1 = 0.f;

    for (int k0 = 0; k0 <= q0; k0 += 64) {
#pragma unroll
        for (int j = 0; j < 4; j++) {
            int idxq = tid + j * 128;
            int r = idxq >> 3, ch = idxq & 7;
            uint32_t off = (uint32_t)(r * 128 + ch * 16);
            off ^= (off >> 3) & 0x70;
            size_t src = (size_t)(b * T_ + k0 + r) * C_ + hh * 64 + ch * 8;
            CP16(smb + 16384 + off, g_k_h + src);
            CP16(smb + 24576 + off, g_k_l + src);
            CP16(smb + 32768 + off, g_v_h + src);
            CP16(smb + 40960 + off, g_v_l + src);
        }
        CPCOMMIT(); CPWAITG(0);
        __syncthreads();

        float4 sacc[8];
#pragma unroll
        for (int i = 0; i < 8; i++) sacc[i] = make_float4(0.f, 0.f, 0.f, 0.f);
#pragma unroll
        for (int ks = 0; ks < 4; ks++) {
#pragma unroll
            for (int njp = 0; njp < 4; njp++) {
                uint32_t kh[4], kl[4];
                uint32_t off = (uint32_t)(((lane & 15) + njp * 16) * 128 + ks * 32 + akof);
                off ^= (off >> 3) & 0x70;
                ldsm_x4(kh, smb + 16384 + off);
                ldsm_x4(kl, smb + 24576 + off);
                mma16816(sacc[2 * njp],     qh[ks], kh[0], kh[2]);
                mma16816(sacc[2 * njp + 1], qh[ks], kh[1], kh[3]);
                mma16816(sacc[2 * njp],     qh[ks], kl[0], kl[2]);
                mma16816(sacc[2 * njp + 1], qh[ks], kl[1], kl[3]);
                mma16816(sacc[2 * njp],     ql[ks], kh[0], kh[2]);
                mma16816(sacc[2 * njp + 1], ql[ks], kh[1], kh[3]);
            }
        }

        if (k0 == q0) {
            int qiA = wid * 16 + g, qiB = qiA + 8;
#pragma unroll
            for (int nj = 0; nj < 8; nj++) {
                int ki = nj * 8 + t4 * 2;
                if (ki     > qiA) sacc[nj].x = -1e30f;
                if (ki + 1 > qiA) sacc[nj].y = -1e30f;
                if (ki     > qiB) sacc[nj].z = -1e30f;
                if (ki + 1 > qiB) sacc[nj].w = -1e30f;
            }
        }

        float mx0 = -1e30f, mx1 = -1e30f;
#pragma unroll
        for (int nj = 0; nj < 8; nj++) {
            mx0 = fmaxf(mx0, fmaxf(sacc[nj].x, sacc[nj].y));
            mx1 = fmaxf(mx1, fmaxf(sacc[nj].z, sacc[nj].w));
        }
        mx0 = fmaxf(mx0, __shfl_xor_sync(0xffffffffu, mx0, 1));
        mx0 = fmaxf(mx0, __shfl_xor_sync(0xffffffffu, mx0, 2));
        mx1 = fmaxf(mx1, __shfl_xor_sync(0xffffffffu, mx1, 1));
        mx1 = fmaxf(mx1, __shfl_xor_sync(0xffffffffu, mx1, 2));
        float mn0 = fmaxf(mrow0, mx0), mn1 = fmaxf(mrow1, mx1);
        float c0 = __expf(mrow0 - mn0), c1 = __expf(mrow1 - mn1);
        float sum0 = 0.f, sum1 = 0.f;
#pragma unroll
        for (int nj = 0; nj < 8; nj++) {
            sacc[nj].x = __expf(sacc[nj].x - mn0);
            sacc[nj].y = __expf(sacc[nj].y - mn0);
            sacc[nj].z = __expf(sacc[nj].z - mn1);
            sacc[nj].w = __expf(sacc[nj].w - mn1);
            sum0 += sacc[nj].x + sacc[nj].y;
            sum1 += sacc[nj].z + sacc[nj].w;
        }
        sum0 += __shfl_xor_sync(0xffffffffu, sum0, 1);
        sum0 += __shfl_xor_sync(0xffffffffu, sum0, 2);
        sum1 += __shfl_xor_sync(0xffffffffu, sum1, 1);
        sum1 += __shfl_xor_sync(0xffffffffu, sum1, 2);
        lrow0 = lrow0 * c0 + sum0;
        lrow1 = lrow1 * c1 + sum1;
        mrow0 = mn0; mrow1 = mn1;
#pragma unroll
        for (int nd = 0; nd < 8; nd++) {
            oacc[nd].x *= c0; oacc[nd].y *= c0;
            oacc[nd].z *= c1; oacc[nd].w *= c1;
        }

#pragma unroll
        for (int kk = 0; kk < 4; kk++) {
            __half h0,l0,h1,l1,h2,l2,h3,l3,h4,l4,h5,l5,h6,l6,h7,l7;
            splith(sacc[2*kk].x, h0, l0);   splith(sacc[2*kk].y, h1, l1);
            splith(sacc[2*kk].z, h2, l2);   splith(sacc[2*kk].w, h3, l3);
            splith(sacc[2*kk+1].x, h4, l4); splith(sacc[2*kk+1].y, h5, l5);
            splith(sacc[2*kk+1].z, h6, l6); splith(sacc[2*kk+1].w, h7, l7);
            uint32_t ah[4] = { packh2(h0,h1), packh2(h2,h3), packh2(h4,h5), packh2(h6,h7) };
            uint32_t al[4] = { packh2(l0,l1), packh2(l2,l3), packh2(l4,l5), packh2(l6,l7) };
#pragma unroll
            for (int ndp = 0; ndp < 4; ndp++) {
                uint32_t vh[4], vl[4];
                uint32_t off = (uint32_t)((kk * 16 + (lane & 15)) * 128 + ndp * 32 + akof);
                off ^= (off >> 3) & 0x70;
                ldsm_x4t(vh, smb + 32768 + off);
                ldsm_x4t(vl, smb + 40960 + off);
                mma16816(oacc[2 * ndp],     ah, vh[0], vh[1]);
                mma16816(oacc[2 * ndp + 1], ah, vh[2], vh[3]);
                mma16816(oacc[2 * ndp],     ah, vl[0], vl[1]);
                mma16816(oacc[2 * ndp + 1], ah, vl[2], vl[3]);
                mma16816(oacc[2 * ndp],     al, vh[0], vh[1]);
                mma16816(oacc[2 * ndp + 1], al, vh[2], vh[3]);
            }
        }
        __syncthreads();
    }

    float inv0 = 1.0f / lrow0, inv1 = 1.0f / lrow1;
    int r0 = q0 + wid * 16 + g, r1 = r0 + 8;
    size_t b0 = (size_t)(b * T_ + r0) * C_ + hh * 64;
    size_t b1 = (size_t)(b * T_ + r1) * C_ + hh * 64;
#pragma unroll
    for (int nd = 0; nd < 8; nd++) {
        int d = nd * 8 + t4 * 2;
        __half hx, lx_, hy, ly;
        splith(oacc[nd].x * inv0, hx, lx_);
        splith(oacc[nd].y * inv0, hy, ly);
        *reinterpret_cast<uint32_t*>(g_y_h + b0 + d) = packh2(hx, hy);
        *reinterpret_cast<uint32_t*>(g_y_l + b0 + d) = packh2(lx_, ly);
        splith(oacc[nd].z * inv1, hx, lx_);
        splith(oacc[nd].w * inv1, hy, ly);
        *reinterpret_cast<uint32_t*>(g_y_h + b1 + d) = packh2(hx, hy);
        *reinterpret_cast<uint32_t*>(g_y_l + b1 + d) = packh2(lx_, ly);
    }
}

// ---------------- host orchestration ----------------
extern "C" void kernel_launch(void* const* d_in, const int* in_sizes, int n_in,
                              void* d_out, int out_size)
{
    (void)in_sizes; (void)n_in; (void)out_size;
    const int*   idx  = (const int*)  d_in[0];
    const float* cosp = (const float*)d_in[1];
    const float* sinp = (const float*)d_in[2];
    const float* wte  = (const float*)d_in[3];
    const float* vemb = (const float*)d_in[4];
    const float* wd   = (const float*)d_in[5];
    const float* wukv = (const float*)d_in[6];
    const float* wuq  = (const float*)d_in[7];
    const float* vg   = (const float*)d_in[8];
    const float* ap   = (const float*)d_in[9];
    const float* fc   = (const float*)d_in[10];
    const float* pj   = (const float*)d_in[11];
    const float* lr   = (const float*)d_in[12];
    const float* lx   = (const float*)d_in[13];
    const float* lmh  = (const float*)d_in[14];
    float* out = (float*)d_out;

    float *px, *pdown, *pkv, *pqpre;
    cudaGetSymbolAddress((void**)&px,    g_x);
    cudaGetSymbolAddress((void**)&pdown, g_down);
    cudaGetSymbolAddress((void**)&pkv,   g_kv);
    cudaGetSymbolAddress((void**)&pqpre, g_qpre);

    __half *wd_h, *wd_l, *wukv_h, *wukv_l, *wuq_h, *wuq_l, *ap_h, *ap_l;
    __half *fc_h, *fc_l, *pj_h, *pj_l, *lmh_h, *lmh_l;
    __half *xn_h, *xn_l, *dn_h, *dn_l, *y_h, *y_l, *h_h, *h_l;
    cudaGetSymbolAddress((void**)&wd_h,   g_wd_h);   cudaGetSymbolAddress((void**)&wd_l,   g_wd_l);
    cudaGetSymbolAddress((void**)&wukv_h, g_wukv_h); cudaGetSymbolAddress((void**)&wukv_l, g_wukv_l);
    cudaGetSymbolAddress((void**)&wuq_h,  g_wuq_h);  cudaGetSymbolAddress((void**)&wuq_l,  g_wuq_l);
    cudaGetSymbolAddress((void**)&ap_h,   g_ap_h);   cudaGetSymbolAddress((void**)&ap_l,   g_ap_l);
    cudaGetSymbolAddress((void**)&fc_h,   g_fc_h);   cudaGetSymbolAddress((void**)&fc_l,   g_fc_l);
    cudaGetSymbolAddress((void**)&pj_h,   g_pj_h);   cudaGetSymbolAddress((void**)&pj_l,   g_pj_l);
    cudaGetSymbolAddress((void**)&lmh_h,  g_lmh_h);  cudaGetSymbolAddress((void**)&lmh_l,  g_lmh_l);
    cudaGetSymbolAddress((void**)&xn_h,   g_xn_h);   cudaGetSymbolAddress((void**)&xn_l,   g_xn_l);
    cudaGetSymbolAddress((void**)&dn_h,   g_dn_h);   cudaGetSymbolAddress((void**)&dn_l,   g_dn_l);
    cudaGetSymbolAddress((void**)&y_h,    g_y_h);    cudaGetSymbolAddress((void**)&y_l,    g_y_l);
    cudaGetSymbolAddress((void**)&h_h,    g_h_h);    cudaGetSymbolAddress((void**)&h_l,    g_h_l);

    const int SMEMSZ = 3 * STG4;   // 96 KB
    cudaFuncSetAttribute(gemm_h4, cudaFuncAttributeMaxDynamicSharedMemorySize, SMEMSZ);
    const int ASM = 49152;         // 48 KB
    cudaFuncSetAttribute(attn_mma, cudaFuncAttributeMaxDynamicSharedMemorySize, ASM);

    const int GM = NTOK / 128;     // 16 m-blocks

    // ---- early splits: only those needed before the first GEMM ----
    // (keeps launch #6 == gemm_h4(down) so ncu -s 5 -c 1 profiles the GEMM)
    wsplit_pad4<<<2048, 256>>>(wd, (uint2*)wd_h, (uint2*)wd_l, L_ * C_ * WDP / 4);
    wsplit8<<<2048, 256>>>((const float4*)wukv, (uint4*)wukv_h, (uint4*)wukv_l, (long)L_ * DC_ * KVW / 8);
    wsplit8<<<2048, 256>>>((const float4*)wuq,  (uint4*)wuq_h,  (uint4*)wuq_l,  (long)L_ * DC1_ * C_ / 8);

    embed_kernel<<<NTOK, 256>>>(idx, wte);
    mix_norm_kernel<<<NTOK, 256>>>(lr, lx, 0);

    // launch #6: down GEMM (layer 0)
    gemm_h4<<<dim3(GM, WDP / 128), 256, SMEMSZ>>>(
        xn_h, xn_l, wd_h, wd_l,
        pdown, nullptr, dn_h, dn_l,
        DOWNW, C_, C_, WDP, DOWNW, DOWNW, 0, 3);

    // ---- remaining splits (consumed later in layer 0) ----
    wsplit8<<<2048, 256>>>((const float4*)ap,   (uint4*)ap_h,   (uint4*)ap_l,   (long)L_ * C_ * C_ / 8);
    wsplit8<<<2048, 256>>>((const float4*)fc,   (uint4*)fc_h,   (uint4*)fc_l,   (long)L_ * C_ * 4 * C_ / 8);
    wsplit8<<<2048, 256>>>((const float4*)pj,   (uint4*)pj_h,   (uint4*)pj_l,   (long)L_ * 4 * C_ * C_ / 8);
    wsplit8<<<2048, 256>>>((const float4*)lmh,  (uint4*)lmh_h,  (uint4*)lmh_l,  (long)C_ * V_ / 8);

    for (int l = 0; l < L_; l++) {
        if (l > 0) {
            mix_norm_kernel<<<NTOK, 256>>>(lr, lx, l);
            gemm_h4<<<dim3(GM, WDP / 128), 256, SMEMSZ>>>(
                xn_h, xn_l, wd_h + (size_t)l * C_ * WDP, wd_l + (size_t)l * C_ * WDP,
                pdown, nullptr, dn_h, dn_l,
                DOWNW, C_, C_, WDP, DOWNW, DOWNW, 0, 3);
        }

        gemm_h4<<<dim3(GM, KVW / 128), 256, SMEMSZ>>>(
            dn_h, dn_l, wukv_h + (size_t)l * DC_ * KVW, wukv_l + (size_t)l * DC_ * KVW,
            pkv, nullptr, nullptr, nullptr,
            KVW, DC_, DOWNW, KVW, KVW, 0, 0, 3);

        gemm_h4<<<dim3(GM, C_ / 128), 256, SMEMSZ>>>(
            dn_h + DC_, dn_l + DC_, wuq_h + (size_t)l * DC1_ * C_, wuq_l + (size_t)l * DC1_ * C_,
            pqpre, nullptr, nullptr, nullptr,
            C_, DC1_, DOWNW, C_, C_, 0, 0, 3);

        build_qkv_kernel<<<NTOK, 512>>>(idx, cosp, sinp,
                                        vg + (size_t)l * 32 * H_,
                                        vemb + (size_t)l * V_ * C_);

        attn_mma<<<dim3(T_ / 64, H_, B_), 128, ASM>>>();

        gemm_h4<<<dim3(GM, C_ / 128), 256, SMEMSZ>>>(
            y_h, y_l, ap_h + (size_t)l * C_ * C_, ap_l + (size_t)l * C_ * C_,
            px, px, nullptr, nullptr,
            C_, C_, C_, C_, C_, 0, 0, 3);

        mix_norm_kernel<<<NTOK, 256>>>(nullptr, nullptr, 0);

        gemm_h4<<<dim3(GM, 4 * C_ / 128), 256, SMEMSZ>>>(
            xn_h, xn_l, fc_h + (size_t)l * C_ * 4 * C_, fc_l + (size_t)l * C_ * 4 * C_,
            nullptr, nullptr, h_h, h_l,
            4 * C_, C_, C_, 4 * C_, 0, 4 * C_, 2, 3);

        gemm_h4<<<dim3(GM, C_ / 128), 256, SMEMSZ>>>(
            h_h, h_l, pj_h + (size_t)l * 4 * C_ * C_, pj_l + (size_t)l * 4 * C_ * C_,
            px, px, nullptr, nullptr,
            C_, 4 * C_, 4 * C_, C_, C_, 0, 0, 3);
    }

    mix_norm_kernel<<<NTOK, 256>>>(nullptr, nullptr, 0);
    // out = softcap(xn @ lm_head), 2-term
    gemm_h4<<<dim3(GM, V_ / 128), 256, SMEMSZ>>>(
        xn_h, xn_l, lmh_h, lmh_l,
        out, nullptr, nullptr, nullptr,
        V_, C_, C_, V_, V_, 0, 1, 2);
}

// round 11
// speedup vs baseline: 1.7286x; 1.0097x over previous
#include <cuda_runtime.h>
#include <cuda_fp16.h>
#include <math.h>
#include <stdint.h>

// ---------------- problem constants ----------------
#define B_    2
#define T_    1024
#define C_    1024
#define H_    16
#define HD_   64
#define DC_   256
#define DC1_  256
#define DR_   32
#define DN_   32
#define V_    32000
#define L_    4
#define NTOK  (B_*T_)             // 2048
#define DOWNW (DC_+DC1_+DR_)      // 544
#define WDP   640                 // padded wd output width
#define KVW   (H_*(DN_+HD_))      // 1536
#define EPS_  1.1920929e-07f

// ---------------- fp32 scratch ----------------
__device__ float g_x   [NTOK*C_];
__device__ float g_x0  [NTOK*C_];
__device__ float g_xn  [NTOK*C_];
__device__ float g_down[NTOK*DOWNW];
__device__ float g_kv  [NTOK*KVW];
__device__ float g_qpre[NTOK*C_];

// ---------------- fp16 hi/lo planes ----------------
__device__ __half g_wd_h  [L_*C_*WDP],    g_wd_l  [L_*C_*WDP];
__device__ __half g_wukv_h[L_*DC_*KVW],   g_wukv_l[L_*DC_*KVW];
__device__ __half g_wuq_h [L_*DC1_*C_],   g_wuq_l [L_*DC1_*C_];
__device__ __half g_ap_h  [L_*C_*C_],     g_ap_l  [L_*C_*C_];
__device__ __half g_fc_h  [L_*C_*4*C_],   g_fc_l  [L_*C_*4*C_];
__device__ __half g_pj_h  [L_*4*C_*C_],   g_pj_l  [L_*4*C_*C_];
__device__ __half g_lmh_h [C_*V_],        g_lmh_l [C_*V_];
__device__ __half g_xn_h  [NTOK*C_],      g_xn_l  [NTOK*C_];
__device__ __half g_dn_h  [NTOK*DOWNW],   g_dn_l  [NTOK*DOWNW];
__device__ __half g_y_h   [NTOK*C_],      g_y_l   [NTOK*C_];
__device__ __half g_h_h   [NTOK*4*C_],    g_h_l   [NTOK*4*C_];
// attention operand planes (q pre-scaled by 0.125)
__device__ __half g_q_h   [NTOK*C_],      g_q_l   [NTOK*C_];
__device__ __half g_k_h   [NTOK*C_],      g_k_l   [NTOK*C_];
__device__ __half g_v_h   [NTOK*C_],      g_v_l   [NTOK*C_];

// ---------------- helpers ----------------
__device__ __forceinline__ uint32_t smem_u32(const void* p) {
    uint32_t a;
    asm("{ .reg .u64 t; cvta.to.shared.u64 t, %1; cvt.u32.u64 %0, t; }" : "=r"(a) : "l"(p));
    return a;
}
__device__ __forceinline__ float warp_sum(float v) {
    v += __shfl_xor_sync(0xffffffffu, v, 16);
    v += __shfl_xor_sync(0xffffffffu, v, 8);
    v += __shfl_xor_sync(0xffffffffu, v, 4);
    v += __shfl_xor_sync(0xffffffffu, v, 2);
    v += __shfl_xor_sync(0xffffffffu, v, 1);
    return v;
}
__device__ __forceinline__ float block_sum(float v) {
    __shared__ float sh[32];
    int lane = threadIdx.x & 31, wid = threadIdx.x >> 5;
    v = warp_sum(v);
    if (lane == 0) sh[wid] = v;
    __syncthreads();
    int nw = blockDim.x >> 5;
    if (wid == 0) {
        float t = (lane < nw) ? sh[lane] : 0.f;
        t = warp_sum(t);
        if (lane == 0) sh[0] = t;
    }
    __syncthreads();
    return sh[0];
}
__device__ __forceinline__ void splith(float x, __half& hi, __half& lo) {
    hi = __float2half_rn(x);
    lo = __float2half_rn(x - __half2float(hi));
}
__device__ __forceinline__ uint32_t packh2(__half a, __half b) {
    return (uint32_t)__half_as_ushort(a) | ((uint32_t)__half_as_ushort(b) << 16);
}
// pair split: returns packed hi (u32) and packed lo (u32)
__device__ __forceinline__ void splith2(float x, float y, uint32_t& hi, uint32_t& lo) {
    __half2 hh = __float22half2_rn(make_float2(x, y));
    float2 back = __half22float2(hh);
    __half2 ll = __float22half2_rn(make_float2(x - back.x, y - back.y));
    hi = *reinterpret_cast<uint32_t*>(&hh);
    lo = *reinterpret_cast<uint32_t*>(&ll);
}

// ---------------- mma / ldmatrix / cp.async wrappers ----------------
__device__ __forceinline__ void ldsm_x4(uint32_t* r, uint32_t addr) {
    asm volatile("ldmatrix.sync.aligned.m8n8.x4.shared.b16 {%0,%1,%2,%3}, [%4];"
                 : "=r"(r[0]), "=r"(r[1]), "=r"(r[2]), "=r"(r[3]) : "r"(addr));
}
__device__ __forceinline__ void ldsm_x4t(uint32_t* r, uint32_t addr) {
    asm volatile("ldmatrix.sync.aligned.m8n8.x4.trans.shared.b16 {%0,%1,%2,%3}, [%4];"
                 : "=r"(r[0]), "=r"(r[1]), "=r"(r[2]), "=r"(r[3]) : "r"(addr));
}
__device__ __forceinline__ void mma16816(float4& d, const uint32_t* a, uint32_t b0, uint32_t b1) {
    asm volatile(
        "mma.sync.aligned.m16n8k16.row.col.f32.f16.f16.f32 "
        "{%0,%1,%2,%3},{%4,%5,%6,%7},{%8,%9},{%0,%1,%2,%3};"
        : "+f"(d.x), "+f"(d.y), "+f"(d.z), "+f"(d.w)
        : "r"(a[0]), "r"(a[1]), "r"(a[2]), "r"(a[3]), "r"(b0), "r"(b1));
}
#define CP16(dst, src) \
    asm volatile("cp.async.cg.shared.global [%0], [%1], 16;" :: "r"(dst), "l"(src) : "memory")
#define CPCOMMIT() asm volatile("cp.async.commit_group;" ::: "memory")
#define CPWAITG(n) asm volatile("cp.async.wait_group " #n ";" ::: "memory")

// ---------------- split: 16 floats/thread, exact grid ----------------
__global__ void wsplit16(const float4* __restrict__ src,
                         uint4* __restrict__ hi, uint4* __restrict__ lo, long n16)
{
    long i = (long)blockIdx.x * blockDim.x + threadIdx.x;
    if (i >= n16) return;
    float4 f0 = src[4 * i];
    float4 f1 = src[4 * i + 1];
    float4 f2 = src[4 * i + 2];
    float4 f3 = src[4 * i + 3];
    uint4 h0, l0, h1, l1;
    splith2(f0.x, f0.y, h0.x, l0.x); splith2(f0.z, f0.w, h0.y, l0.y);
    splith2(f1.x, f1.y, h0.z, l0.z); splith2(f1.z, f1.w, h0.w, l0.w);
    splith2(f2.x, f2.y, h1.x, l1.x); splith2(f2.z, f2.w, h1.y, l1.y);
    splith2(f3.x, f3.y, h1.z, l1.z); splith2(f3.z, f3.w, h1.w, l1.w);
    hi[2 * i] = h0; hi[2 * i + 1] = h1;
    lo[2 * i] = l0; lo[2 * i + 1] = l1;
}

// ---------------- padded split, vectorized (wd only) --------------------
__global__ void wsplit_pad4(const float* __restrict__ src,
                            uint2* __restrict__ hi, uint2* __restrict__ lo, int n4)
{
    int stride = gridDim.x * blockDim.x;
    for (int i = blockIdx.x * blockDim.x + threadIdx.x; i < n4; i += stride) {
        int row = i / (WDP / 4);
        int c4  = i - row * (WDP / 4);
        float4 f = make_float4(0.f, 0.f, 0.f, 0.f);
        if (c4 < DOWNW / 4)
            f = *reinterpret_cast<const float4*>(src + (size_t)row * DOWNW + c4 * 4);
        uint2 h, l;
        splith2(f.x, f.y, h.x, l.x);
        splith2(f.z, f.w, h.y, l.y);
        hi[i] = h; lo[i] = l;
    }
}

// ---------------- embedding + rmsnorm ----------------
__global__ void embed_kernel(const int* __restrict__ idx, const float* __restrict__ wte) {
    int row = blockIdx.x;
    int tok = idx[row];
    const float* src = wte + (size_t)tok * C_;
    float s = 0.f;
    for (int i = threadIdx.x; i < C_; i += blockDim.x) { float v = src[i]; s += v * v; }
    s = block_sum(s);
    float r = rsqrtf(s * (1.0f / C_) + EPS_);
    for (int i = threadIdx.x; i < C_; i += blockDim.x) {
        float v = src[i] * r;
        g_x [(size_t)row * C_ + i] = v;
        g_x0[(size_t)row * C_ + i] = v;
    }
}

__global__ void mix_norm_kernel(const float* lr, const float* lx, int layer) {
    int row = blockIdx.x;
    float a = lr ? lr[layer] : 1.0f;
    float b = lx ? lx[layer] : 0.0f;
    float*       xr  = g_x  + (size_t)row * C_;
    const float* x0r = g_x0 + (size_t)row * C_;
    float s = 0.f;
    for (int i = threadIdx.x; i < C_; i += blockDim.x) {
        float v = a * xr[i] + b * x0r[i];
        xr[i] = v;
        s += v * v;
    }
    s = block_sum(s);
    float r = rsqrtf(s * (1.0f / C_) + EPS_);
    for (int i = threadIdx.x; i < C_; i += blockDim.x) {
        float v = xr[i] * r;
        g_xn[(size_t)row * C_ + i] = v;
        __half h, l;
        splith(v, h, l);
        g_xn_h[(size_t)row * C_ + i] = h;
        g_xn_l[(size_t)row * C_ + i] = l;
    }
}

// ---------------- 3xFP16 tensor-core GEMM v5 (single-sync pipeline) -----
#define STG4 32768
__global__ __launch_bounds__(256, 2) void gemm_h4(
    const __half* __restrict__ Ah, const __half* __restrict__ Al,
    const __half* __restrict__ Bh, const __half* __restrict__ Bl,
    float* __restrict__ C, const float* __restrict__ D,
    __half* __restrict__ Chi, __half* __restrict__ Clo,
    int N, int K, int lda, int ldb, int ldc, int ldp, int mode, int nterms)
{
    extern __shared__ __align__(1024) char sm[];
    int tid = threadIdx.x;
    int wid = tid >> 5, lane = tid & 31;
    int warp_m = wid >> 2, warp_n = wid & 3;
    int m0 = blockIdx.x * 128, n0 = blockIdx.y * 128;
    uint32_t smb = smem_u32(sm);

    float4 acc[4][4];
#pragma unroll
    for (int i = 0; i < 4; i++)
#pragma unroll
        for (int j = 0; j < 4; j++) acc[i][j] = make_float4(0.f, 0.f, 0.f, 0.f);

    int a_m   = tid >> 3;
    int a_hl  = (tid >> 2) & 1;
    int a_j   = tid & 3;
    int b_k0  = tid >> 4;
    int b_j   = tid & 15;
    const __half* Asel = a_hl ? Al : Ah;

    int arow0 = warp_m * 64 + (lane & 15);
    int akof  = (lane & 16);
    int bkr   = (lane & 15);
    int bco   = warp_n * 64 + ((lane >> 4) << 4);
    int ksrot = wid & 1;

    int nk = K >> 5;

    auto issue = [&](int kt, int stg) {
        uint32_t sA = smb + stg * STG4;
        uint32_t sB = sA + 16384;
#pragma unroll
        for (int r = 0; r < 4; r++) {
            int m = a_m + r * 32;
            uint32_t off = (uint32_t)(m * 128 + a_hl * 64 + a_j * 16);
            off ^= (off >> 3) & 0x70;
            const __half* src = Asel + (size_t)(m0 + m) * lda + kt * 32 + a_j * 8;
            CP16(sA + off, src);
        }
#pragma unroll
        for (int r = 0; r < 4; r++) {
            int k = b_k0 + (r & 1) * 16;
            const __half* Bp = (r < 2) ? Bh : Bl;
            uint32_t off = ((uint32_t)(k * 256 + b_j * 16)) ^ ((uint32_t)(k & 7) << 4);
            off += (r < 2) ? 0u : 8192u;
            const __half* src = Bp + (size_t)(kt * 32 + k) * ldb + n0 + b_j * 8;
            CP16(sB + off, src);
        }
        CPCOMMIT();
    };

    issue(0, 0);
    issue(1, 1);

    for (int kt = 0; kt < nk; kt++) {
        if (kt == nk - 1) { CPWAITG(0); } else { CPWAITG(1); }
        __syncthreads();
        if (kt + 2 < nk) issue(kt + 2, (kt + 2) % 3);

        int s = kt % 3;
        uint32_t sA  = smb + s * STG4;
        uint32_t sBh = sA + 16384;
        uint32_t sBl = sA + 24576;
#pragma unroll
        for (int ks0 = 0; ks0 < 2; ks0++) {
            int ks = ks0 ^ ksrot;
            uint32_t af[4][4], bh[2][4], bl[2][4];
#pragma unroll
            for (int mi = 0; mi < 4; mi++) {
                uint32_t oh = (uint32_t)((arow0 + mi * 16) * 128 + ks * 32 + akof);
                oh ^= (oh >> 3) & 0x70;
                ldsm_x4(af[mi], sA + oh);
            }
#pragma unroll
            for (int nj = 0; nj < 2; nj++) {
                int krow = ks * 16 + bkr;
                uint32_t off = (uint32_t)(krow * 256 + bco + nj * 32) ^ ((uint32_t)(krow & 7) << 4);
                ldsm_x4t(bh[nj], sBh + off);
                ldsm_x4t(bl[nj], sBl + off);
            }
#pragma unroll
            for (int mi = 0; mi < 4; mi++)
#pragma unroll
                for (int ni = 0; ni < 4; ni++)
                    mma16816(acc[mi][ni], af[mi], bh[ni >> 1][(ni & 1) * 2], bh[ni >> 1][(ni & 1) * 2 + 1]);
#pragma unroll
            for (int mi = 0; mi < 4; mi++)
#pragma unroll
                for (int ni = 0; ni < 4; ni++)
                    mma16816(acc[mi][ni], af[mi], bl[ni >> 1][(ni & 1) * 2], bl[ni >> 1][(ni & 1) * 2 + 1]);
            if (nterms == 3) {
#pragma unroll
                for (int mi = 0; mi < 4; mi++) {
                    uint32_t ol = (uint32_t)((arow0 + mi * 16) * 128 + ks * 32 + akof + 64);
                    ol ^= (ol >> 3) & 0x70;
                    ldsm_x4(af[mi], sA + ol);
                }
#pragma unroll
                for (int mi = 0; mi < 4; mi++)
#pragma unroll
                    for (int ni = 0; ni < 4; ni++)
                        mma16816(acc[mi][ni], af[mi], bh[ni >> 1][(ni & 1) * 2], bh[ni >> 1][(ni & 1) * 2 + 1]);
            }
        }
    }

    int g = lane >> 2, t4 = lane & 3;
#pragma unroll
    for (int mi = 0; mi < 4; mi++) {
        int r0 = m0 + warp_m * 64 + mi * 16 + g;
#pragma unroll
        for (int ni = 0; ni < 4; ni++) {
            int col = n0 + warp_n * 32 + ni * 8 + 2 * t4;
            if (col >= N) continue;
            float4 v = acc[mi][ni];
            if (D) {
                float2 d0 = *reinterpret_cast<const float2*>(D + (size_t)r0 * ldc + col);
                float2 d1 = *reinterpret_cast<const float2*>(D + (size_t)(r0 + 8) * ldc + col);
                v.x += d0.x; v.y += d0.y; v.z += d1.x; v.w += d1.y;
            }
            if (mode == 1) {
                v.x = 15.0f * tanhf(v.x * (1.f / 15.f));
                v.y = 15.0f * tanhf(v.y * (1.f / 15.f));
                v.z = 15.0f * tanhf(v.z * (1.f / 15.f));
                v.w = 15.0f * tanhf(v.w * (1.f / 15.f));
            } else if (mode == 2) {
                v.x = (v.x > 0.f) ? v.x * v.x : 0.f;
                v.y = (v.y > 0.f) ? v.y * v.y : 0.f;
                v.z = (v.z > 0.f) ? v.z * v.z : 0.f;
                v.w = (v.w > 0.f) ? v.w * v.w : 0.f;
            }
            if (C) {
                *reinterpret_cast<float2*>(C + (size_t)r0 * ldc + col) = make_float2(v.x, v.y);
                *reinterpret_cast<float2*>(C + (size_t)(r0 + 8) * ldc + col) = make_float2(v.z, v.w);
            }
            if (Chi) {
                uint32_t ph0, pl0, ph1, pl1;
                splith2(v.x, v.y, ph0, pl0);
                splith2(v.z, v.w, ph1, pl1);
                *reinterpret_cast<uint32_t*>(Chi + (size_t)r0 * ldp + col)       = ph0;
                *reinterpret_cast<uint32_t*>(Clo + (size_t)r0 * ldp + col)       = pl0;
                *reinterpret_cast<uint32_t*>(Chi + (size_t)(r0 + 8) * ldp + col) = ph1;
                *reinterpret_cast<uint32_t*>(Clo + (size_t)(r0 + 8) * ldp + col) = pl1;
            }
        }
    }
}

// ---------------- per-token q/k/v build -> fp16 hi/lo planes --------------
__global__ void build_qkv_kernel(const int* __restrict__ idx,
                                 const float* __restrict__ cosp, const float* __restrict__ sinp,
                                 const float* __restrict__ vg, const float* __restrict__ vetab)
{
    int row = blockIdx.x;
    int h    = threadIdx.x >> 5;
    int lane = threadIdx.x & 31;
    const float* cosr = cosp + (size_t)row * (DR_ / 2);
    const float* sinr = sinp + (size_t)row * (DR_ / 2);

    float gv = g_xn[(size_t)row * C_ + lane] * vg[lane * H_ + h];
    gv = warp_sum(gv);
    float gate = 2.0f / (1.0f + __expf(-gv));

    int r16 = (lane < 16) ? lane : lane - 16;
    float c = cosr[r16], s = sinr[r16];
    size_t base = (size_t)row * C_ + h * 64;

    float kn = g_kv[(size_t)row * KVW + h * 96 + lane];
    const float* dro = g_down + (size_t)row * DOWNW + 512;
    float kr = (lane < 16) ? (dro[lane] * c + dro[lane + 16] * s)
                           : (-dro[lane - 16] * s + dro[lane] * c);
    float ssk = warp_sum(kn * kn + kr * kr);
    float rk = rsqrtf(ssk * (1.0f / 64.0f) + EPS_);
    __half hh_, ll_;
    splith(kn * rk, hh_, ll_);  g_k_h[base + lane]      = hh_; g_k_l[base + lane]      = ll_;
    splith(kr * rk, hh_, ll_);  g_k_h[base + lane + 32] = hh_; g_k_l[base + lane + 32] = ll_;

    const float* qp = g_qpre + (size_t)row * C_ + h * 64;
    float qn = qp[lane];
    float qr = (lane < 16) ? (qp[32 + lane] * c + qp[48 + lane] * s)
                           : (-qp[16 + lane] * s + qp[32 + lane] * c);
    float ssq = warp_sum(qn * qn + qr * qr);
    float rq = rsqrtf(ssq * (1.0f / 64.0f) + EPS_) * 0.125f;
    splith(qn * rq, hh_, ll_);  g_q_h[base + lane]      = hh_; g_q_l[base + lane]      = ll_;
    splith(qr * rq, hh_, ll_);  g_q_h[base + lane + 32] = hh_; g_q_l[base + lane + 32] = ll_;

    int tok = idx[row];
    const float* ver = vetab + (size_t)tok * C_ + h * 64;
    const float* kvv = g_kv + (size_t)row * KVW + h * 96 + 32;
    splith(kvv[lane]      + gate * ver[lane],      hh_, ll_);
    g_v_h[base + lane]      = hh_; g_v_l[base + lane]      = ll_;
    splith(kvv[lane + 32] + gate * ver[lane + 32], hh_, ll_);
    g_v_h[base + lane + 32] = hh_; g_v_l[base + lane + 32] = ll_;
}

// ---------------- tensor-core causal flash attention (double-buffered) ----
// smem: Qhi@0 Qlo@8192; KV stage st (st=0,1) at 16384+st*32768:
//   Khi+0 Klo+8192 Vhi+16384 Vlo+24576. Total 81920 bytes.
__global__ __launch_bounds__(128) void attn_mma()
{
    extern __shared__ __align__(1024) char dsm[];
    uint32_t smb = smem_u32(dsm);
    int tid = threadIdx.x;
    int wid = tid >> 5, lane = tid & 31;
    int q0 = blockIdx.x * 64;
    int hh = blockIdx.y;
    int b  = blockIdx.z;
    int t4 = lane & 3, g = lane >> 2;

    // ---- load Q tile ----
#pragma unroll
    for (int j = 0; j < 4; j++) {
        int idxq = tid + j * 128;
        int r = idxq >> 3, ch = idxq & 7;
        uint32_t off = (uint32_t)(r * 128 + ch * 16);
        off ^= (off >> 3) & 0x70;
        size_t src = (size_t)(b * T_ + q0 + r) * C_ + hh * 64 + ch * 8;
        CP16(smb + off,        g_q_h + src);
        CP16(smb + 8192 + off, g_q_l + src);
    }
    CPCOMMIT();

    auto issueKV = [&](int k0, int st) {
        uint32_t base = smb + 16384 + st * 32768;
#pragma unroll
        for (int j = 0; j < 4; j++) {
            int idxq = tid + j * 128;
            int r = idxq >> 3, ch = idxq & 7;
            uint32_t off = (uint32_t)(r * 128 + ch * 16);
            off ^= (off >> 3) & 0x70;
            size_t src = (size_t)(b * T_ + k0 + r) * C_ + hh * 64 + ch * 8;
            CP16(base + off,         g_k_h + src);
            CP16(base + 8192 + off,  g_k_l + src);
            CP16(base + 16384 + off, g_v_h + src);
            CP16(base + 24576 + off, g_v_l + src);
        }
        CPCOMMIT();
    };

    int nt = q0 / 64 + 1;
    issueKV(0, 0);

    // wait for Q (groups pending: Q, KV0 -> wait until <=1 leaves Q done)
    CPWAITG(1);
    __syncthreads();

    int arow0 = wid * 16 + (lane & 15);
    int akof  = (lane & 16);
    uint32_t qh[4][4], ql[4][4];
#pragma unroll
    for (int ks = 0; ks < 4; ks++) {
        uint32_t off = (uint32_t)(arow0 * 128 + ks * 32 + akof);
        off ^= (off >> 3) & 0x70;
        ldsm_x4(qh[ks], smb + off);
        ldsm_x4(ql[ks], smb + 8192 + off);
    }

    float4 oacc[8];
#pragma unroll
    for (int i = 0; i < 8; i++) oacc[i] = make_float4(0.f, 0.f, 0.f, 0.f);
    float mrow0 = -1e30f, mrow1 = -1e30f, lrow0 = 0.f, lrow1 = 0.f;

    for (int t = 0; t < nt; t++) {
        if (t + 1 < nt) { issueKV((t + 1) * 64, (t + 1) & 1); CPWAITG(1); }
        else            { CPWAITG(0); }
        __syncthreads();

        uint32_t kb = smb + 16384 + (t & 1) * 32768;

        float4 sacc[8];
#pragma unroll
        for (int i = 0; i < 8; i++) sacc[i] = make_float4(0.f, 0.f, 0.f, 0.f);
#pragma unroll
        for (int ks = 0; ks < 4; ks++) {
#pragma unroll
            for (int njp = 0; njp < 4; njp++) {
                uint32_t kh[4], kl[4];
                uint32_t off = (uint32_t)(((lane & 15) + njp * 16) * 128 + ks * 32 + akof);
                off ^= (off >> 3) & 0x70;
                ldsm_x4(kh, kb + off);
                ldsm_x4(kl, kb + 8192 + off);
                mma16816(sacc[2 * njp],     qh[ks], kh[0], kh[2]);
                mma16816(sacc[2 * njp + 1], qh[ks], kh[1], kh[3]);
                mma16816(sacc[2 * njp],     qh[ks], kl[0], kl[2]);
                mma16816(sacc[2 * njp + 1], qh[ks], kl[1], kl[3]);
                mma16816(sacc[2 * njp],     ql[ks], kh[0], kh[2]);
                mma16816(sacc[2 * njp + 1], ql[ks], kh[1], kh[3]);
            }
        }

        if (t == nt - 1) {
            int qiA = wid * 16 + g, qiB = qiA + 8;
#pragma unroll
            for (int nj = 0; nj < 8; nj++) {
                int ki = nj * 8 + t4 * 2;
                if (ki     > qiA) sacc[nj].x = -1e30f;
                if (ki + 1 > qiA) sacc[nj].y = -1e30f;
                if (ki     > qiB) sacc[nj].z = -1e30f;
                if (ki + 1 > qiB) sacc[nj].w = -1e30f;
            }
        }

        float mx0 = -1e30f, mx1 = -1e30f;
#pragma unroll
        for (int nj = 0; nj < 8; nj++) {
            mx0 = fmaxf(mx0, fmaxf(sacc[nj].x, sacc[nj].y));
            mx1 = fmaxf(mx1, fmaxf(sacc[nj].z, sacc[nj].w));
        }
        mx0 = fmaxf(mx0, __shfl_xor_sync(0xffffffffu, mx0, 1));
        mx0 = fmaxf(mx0, __shfl_xor_sync(0xffffffffu, mx0, 2));
        mx1 = fmaxf(mx1, __shfl_xor_sync(0xffffffffu, mx1, 1));
        mx1 = fmaxf(mx1, __shfl_xor_sync(0xffffffffu, mx1, 2));
        float mn0 = fmaxf(mrow0, mx0), mn1 = fmaxf(mrow1, mx1);
        float c0 = __expf(mrow0 - mn0), c1 = __expf(mrow1 - mn1);
        float sum0 = 0.f, sum1 = 0.f;
#pragma unroll
        for (int nj = 0; nj < 8; nj++) {
            sacc[nj].x = __expf(sacc[nj].x - mn0);
            sacc[nj].y = __expf(sacc[nj].y - mn0);
            sacc[nj].z = __expf(sacc[nj].z - mn1);
            sacc[nj].w = __expf(sacc[nj].w - mn1);
            sum0 += sacc[nj].x + sacc[nj].y;
            sum1 += sacc[nj].z + sacc[nj].w;
        }
        sum0 += __shfl_xor_sync(0xffffffffu, sum0, 1);
        sum0 += __shfl_xor_sync(0xffffffffu, sum0, 2);
        sum1 += __shfl_xor_sync(0xffffffffu, sum1, 1);
        sum1 += __shfl_xor_sync(0xffffffffu, sum1, 2);
        lrow0 = lrow0 * c0 + sum0;
        lrow1 = lrow1 * c1 + sum1;
        mrow0 = mn0; mrow1 = mn1;
#pragma unroll
        for (int nd = 0; nd < 8; nd++) {
            oacc[nd].x *= c0; oacc[nd].y *= c0;
            oacc[nd].z *= c1; oacc[nd].w *= c1;
        }

#pragma unroll
        for (int kk = 0; kk < 4; kk++) {
            uint32_t ah[4], al[4];
            splith2(sacc[2*kk].x,   sacc[2*kk].y,   ah[0], al[0]);
            splith2(sacc[2*kk].z,   sacc[2*kk].w,   ah[1], al[1]);
            splith2(sacc[2*kk+1].x, sacc[2*kk+1].y, ah[2], al[2]);
            splith2(sacc[2*kk+1].z, sacc[2*kk+1].w, ah[3], al[3]);
#pragma unroll
            for (int ndp = 0; ndp < 4; ndp++) {
                uint32_t vh[4], vl[4];
                uint32_t off = (uint32_t)((kk * 16 + (lane & 15)) * 128 + ndp * 32 + akof);
                off ^= (off >> 3) & 0x70;
                ldsm_x4t(vh, kb + 16384 + off);
                ldsm_x4t(vl, kb + 24576 + off);
                mma16816(oacc[2 * ndp],     ah, vh[0], vh[1]);
                mma16816(oacc[2 * ndp + 1], ah, vh[2], vh[3]);
                mma16816(oacc[2 * ndp],     ah, vl[0], vl[1]);
                mma16816(oacc[2 * ndp + 1], ah, vl[2], vl[3]);
                mma16816(oacc[2 * ndp],     al, vh[0], vh[1]);
                mma16816(oacc[2 * ndp + 1], al, vh[2], vh[3]);
            }
        }
        __syncthreads();
    }

    float inv0 = 1.0f / lrow0, inv1 = 1.0f / lrow1;
    int r0 = q0 + wid * 16 + g, r1 = r0 + 8;
    size_t b0 = (size_t)(b * T_ + r0) * C_ + hh * 64;
    size_t b1 = (size_t)(b * T_ + r1) * C_ + hh * 64;
#pragma unroll
    for (int nd = 0; nd < 8; nd++) {
        int d = nd * 8 + t4 * 2;
        uint32_t ph, pl;
        splith2(oacc[nd].x * inv0, oacc[nd].y * inv0, ph, pl);
        *reinterpret_cast<uint32_t*>(g_y_h + b0 + d) = ph;
        *reinterpret_cast<uint32_t*>(g_y_l + b0 + d) = pl;
        splith2(oacc[nd].z * inv1, oacc[nd].w * inv1, ph, pl);
        *reinterpret_cast<uint32_t*>(g_y_h + b1 + d) = ph;
        *reinterpret_cast<uint32_t*>(g_y_l + b1 + d) = pl;
    }
}

// ---------------- host orchestration ----------------
extern "C" void kernel_launch(void* const* d_in, const int* in_sizes, int n_in,
                              void* d_out, int out_size)
{
    (void)in_sizes; (void)n_in; (void)out_size;
    const int*   idx  = (const int*)  d_in[0];
    const float* cosp = (const float*)d_in[1];
    const float* sinp = (const float*)d_in[2];
    const float* wte  = (const float*)d_in[3];
    const float* vemb = (const float*)d_in[4];
    const float* wd   = (const float*)d_in[5];
    const float* wukv = (const float*)d_in[6];
    const float* wuq  = (const float*)d_in[7];
    const float* vg   = (const float*)d_in[8];
    const float* ap   = (const float*)d_in[9];
    const float* fc   = (const float*)d_in[10];
    const float* pj   = (const float*)d_in[11];
    const float* lr   = (const float*)d_in[12];
    const float* lx   = (const float*)d_in[13];
    const float* lmh  = (const float*)d_in[14];
    float* out = (float*)d_out;

    float *px, *pdown, *pkv, *pqpre;
    cudaGetSymbolAddress((void**)&px,    g_x);
    cudaGetSymbolAddress((void**)&pdown, g_down);
    cudaGetSymbolAddress((void**)&pkv,   g_kv);
    cudaGetSymbolAddress((void**)&pqpre, g_qpre);

    __half *wd_h, *wd_l, *wukv_h, *wukv_l, *wuq_h, *wuq_l, *ap_h, *ap_l;
    __half *fc_h, *fc_l, *pj_h, *pj_l, *lmh_h, *lmh_l;
    __half *xn_h, *xn_l, *dn_h, *dn_l, *y_h, *y_l, *h_h, *h_l;
    cudaGetSymbolAddress((void**)&wd_h,   g_wd_h);   cudaGetSymbolAddress((void**)&wd_l,   g_wd_l);
    cudaGetSymbolAddress((void**)&wukv_h, g_wukv_h); cudaGetSymbolAddress((void**)&wukv_l, g_wukv_l);
    cudaGetSymbolAddress((void**)&wuq_h,  g_wuq_h);  cudaGetSymbolAddress((void**)&wuq_l,  g_wuq_l);
    cudaGetSymbolAddress((void**)&ap_h,   g_ap_h);   cudaGetSymbolAddress((void**)&ap_l,   g_ap_l);
    cudaGetSymbolAddress((void**)&fc_h,   g_fc_h);   cudaGetSymbolAddress((void**)&fc_l,   g_fc_l);
    cudaGetSymbolAddress((void**)&pj_h,   g_pj_h);   cudaGetSymbolAddress((void**)&pj_l,   g_pj_l);
    cudaGetSymbolAddress((void**)&lmh_h,  g_lmh_h);  cudaGetSymbolAddress((void**)&lmh_l,  g_lmh_l);
    cudaGetSymbolAddress((void**)&xn_h,   g_xn_h);   cudaGetSymbolAddress((void**)&xn_l,   g_xn_l);
    cudaGetSymbolAddress((void**)&dn_h,   g_dn_h);   cudaGetSymbolAddress((void**)&dn_l,   g_dn_l);
    cudaGetSymbolAddress((void**)&y_h,    g_y_h);    cudaGetSymbolAddress((void**)&y_l,    g_y_l);
    cudaGetSymbolAddress((void**)&h_h,    g_h_h);    cudaGetSymbolAddress((void**)&h_l,    g_h_l);

    const int SMEMSZ = 3 * STG4;   // 96 KB
    cudaFuncSetAttribute(gemm_h4, cudaFuncAttributeMaxDynamicSharedMemorySize, SMEMSZ);
    const int ASM = 81920;         // 80 KB (Q 16K + 2 KV stages of 32K)
    cudaFuncSetAttribute(attn_mma, cudaFuncAttributeMaxDynamicSharedMemorySize, ASM);

    const int GM = NTOK / 128;     // 16 m-blocks

    // ---- early splits (needed before the first GEMM) ----
    wsplit_pad4<<<2048, 256>>>(wd, (uint2*)wd_h, (uint2*)wd_l, L_ * C_ * WDP / 4);
    wsplit16<<<(int)((long)L_ * DC_ * KVW / 16 / 256), 256>>>(
        (const float4*)wukv, (uint4*)wukv_h, (uint4*)wukv_l, (long)L_ * DC_ * KVW / 16);
    wsplit16<<<(int)((long)L_ * DC1_ * C_ / 16 / 256), 256>>>(
        (const float4*)wuq, (uint4*)wuq_h, (uint4*)wuq_l, (long)L_ * DC1_ * C_ / 16);

    embed_kernel<<<NTOK, 256>>>(idx, wte);
    mix_norm_kernel<<<NTOK, 256>>>(lr, lx, 0);

    // launch #6: down GEMM (layer 0)
    gemm_h4<<<dim3(GM, WDP / 128), 256, SMEMSZ>>>(
        xn_h, xn_l, wd_h, wd_l,
        pdown, nullptr, dn_h, dn_l,
        DOWNW, C_, C_, WDP, DOWNW, DOWNW, 0, 3);

    // ---- remaining splits ----
    wsplit16<<<(int)((long)L_ * C_ * C_ / 16 / 256), 256>>>(
        (const float4*)ap, (uint4*)ap_h, (uint4*)ap_l, (long)L_ * C_ * C_ / 16);
    wsplit16<<<(int)((long)L_ * C_ * 4 * C_ / 16 / 256), 256>>>(
        (const float4*)fc, (uint4*)fc_h, (uint4*)fc_l, (long)L_ * C_ * 4 * C_ / 16);
    wsplit16<<<(int)((long)L_ * 4 * C_ * C_ / 16 / 256), 256>>>(
        (const float4*)pj, (uint4*)pj_h, (uint4*)pj_l, (long)L_ * 4 * C_ * C_ / 16);
    wsplit16<<<(int)((long)C_ * V_ / 16 / 256), 256>>>(
        (const float4*)lmh, (uint4*)lmh_h, (uint4*)lmh_l, (long)C_ * V_ / 16);

    for (int l = 0; l < L_; l++) {
        if (l > 0) {
            mix_norm_kernel<<<NTOK, 256>>>(lr, lx, l);
            gemm_h4<<<dim3(GM, WDP / 128), 256, SMEMSZ>>>(
                xn_h, xn_l, wd_h + (size_t)l * C_ * WDP, wd_l + (size_t)l * C_ * WDP,
                pdown, nullptr, dn_h, dn_l,
                DOWNW, C_, C_, WDP, DOWNW, DOWNW, 0, 3);
        }

        gemm_h4<<<dim3(GM, KVW / 128), 256, SMEMSZ>>>(
            dn_h, dn_l, wukv_h + (size_t)l * DC_ * KVW, wukv_l + (size_t)l * DC_ * KVW,
            pkv, nullptr, nullptr, nullptr,
            KVW, DC_, DOWNW, KVW, KVW, 0, 0, 3);

        gemm_h4<<<dim3(GM, C_ / 128), 256, SMEMSZ>>>(
            dn_h + DC_, dn_l + DC_, wuq_h + (size_t)l * DC1_ * C_, wuq_l + (size_t)l * DC1_ * C_,
            pqpre, nullptr, nullptr, nullptr,
            C_, DC1_, DOWNW, C_, C_, 0, 0, 3);

        build_qkv_kernel<<<NTOK, 512>>>(idx, cosp, sinp,
                                        vg + (size_t)l * 32 * H_,
                                        vemb + (size_t)l * V_ * C_);

        attn_mma<<<dim3(T_ / 64, H_, B_), 128, ASM>>>();

        gemm_h4<<<dim3(GM, C_ / 128), 256, SMEMSZ>>>(
            y_h, y_l, ap_h + (size_t)l * C_ * C_, ap_l + (size_t)l * C_ * C_,
            px, px, nullptr, nullptr,
            C_, C_, C_, C_, C_, 0, 0, 3);

        mix_norm_kernel<<<NTOK, 256>>>(nullptr, nullptr, 0);

        gemm_h4<<<dim3(GM, 4 * C_ / 128), 256, SMEMSZ>>>(
            xn_h, xn_l, fc_h + (size_t)l * C_ * 4 * C_, fc_l + (size_t)l * C_ * 4 * C_,
            nullptr, nullptr, h_h, h_l,
            4 * C_, C_, C_, 4 * C_, 0, 4 * C_, 2, 3);

        gemm_h4<<<dim3(GM, C_ / 128), 256, SMEMSZ>>>(
            h_h, h_l, pj_h + (size_t)l * 4 * C_ * C_, pj_l + (size_t)l * 4 * C_ * C_,
            px, px, nullptr, nullptr,
            C_, 4 * C_, 4 * C_, C_, C_, 0, 0, 3);
    }

    mix_norm_kernel<<<NTOK, 256>>>(nullptr, nullptr, 0);
    // out = softcap(xn @ lm_head), 2-term
    gemm_h4<<<dim3(GM, V_ / 128), 256, SMEMSZ>>>(
        xn_h, xn_l, lmh_h, lmh_l,
        out, nullptr, nullptr, nullptr,
        V_, C_, C_, V_, V_, 0, 1, 2);
}

// round 12
// speedup vs baseline: 1.7771x; 1.0280x over previous
#include <cuda_runtime.h>
#include <cuda_fp16.h>
#include <math.h>
#include <stdint.h>

// ---------------- problem constants ----------------
#define B_    2
#define T_    1024
#define C_    1024
#define H_    16
#define HD_   64
#define DC_   256
#define DC1_  256
#define DR_   32
#define DN_   32
#define V_    32000
#define L_    4
#define NTOK  (B_*T_)             // 2048
#define DOWNW (DC_+DC1_+DR_)      // 544
#define WDP   640                 // padded wd output width
#define KVW   (H_*(DN_+HD_))      // 1536
#define EPS_  1.1920929e-07f

// ---------------- fp32 scratch ----------------
__device__ float g_x   [NTOK*C_];
__device__ float g_x0  [NTOK*C_];
__device__ float g_xn  [NTOK*C_];
__device__ float g_down[NTOK*DOWNW];
__device__ float g_kv  [NTOK*KVW];
__device__ float g_qpre[NTOK*C_];

// ---------------- fp16 hi/lo planes ----------------
__device__ __half g_wd_h  [L_*C_*WDP],    g_wd_l  [L_*C_*WDP];
__device__ __half g_wukv_h[L_*DC_*KVW],   g_wukv_l[L_*DC_*KVW];
__device__ __half g_wuq_h [L_*DC1_*C_],   g_wuq_l [L_*DC1_*C_];
__device__ __half g_ap_h  [L_*C_*C_],     g_ap_l  [L_*C_*C_];
__device__ __half g_fc_h  [L_*C_*4*C_],   g_fc_l  [L_*C_*4*C_];
__device__ __half g_pj_h  [L_*4*C_*C_],   g_pj_l  [L_*4*C_*C_];
__device__ __half g_lmh_h [C_*V_],        g_lmh_l [C_*V_];
__device__ __half g_xn_h  [NTOK*C_],      g_xn_l  [NTOK*C_];
__device__ __half g_dn_h  [NTOK*DOWNW],   g_dn_l  [NTOK*DOWNW];
__device__ __half g_y_h   [NTOK*C_],      g_y_l   [NTOK*C_];
__device__ __half g_h_h   [NTOK*4*C_],    g_h_l   [NTOK*4*C_];
__device__ __half g_q_h   [NTOK*C_],      g_q_l   [NTOK*C_];
__device__ __half g_k_h   [NTOK*C_],      g_k_l   [NTOK*C_];
__device__ __half g_v_h   [NTOK*C_],      g_v_l   [NTOK*C_];

// ---------------- helpers ----------------
__device__ __forceinline__ uint32_t smem_u32(const void* p) {
    uint32_t a;
    asm("{ .reg .u64 t; cvta.to.shared.u64 t, %1; cvt.u32.u64 %0, t; }" : "=r"(a) : "l"(p));
    return a;
}
__device__ __forceinline__ float warp_sum(float v) {
    v += __shfl_xor_sync(0xffffffffu, v, 16);
    v += __shfl_xor_sync(0xffffffffu, v, 8);
    v += __shfl_xor_sync(0xffffffffu, v, 4);
    v += __shfl_xor_sync(0xffffffffu, v, 2);
    v += __shfl_xor_sync(0xffffffffu, v, 1);
    return v;
}
__device__ __forceinline__ float block_sum(float v) {
    __shared__ float sh[32];
    int lane = threadIdx.x & 31, wid = threadIdx.x >> 5;
    v = warp_sum(v);
    if (lane == 0) sh[wid] = v;
    __syncthreads();
    int nw = blockDim.x >> 5;
    if (wid == 0) {
        float t = (lane < nw) ? sh[lane] : 0.f;
        t = warp_sum(t);
        if (lane == 0) sh[0] = t;
    }
    __syncthreads();
    return sh[0];
}
__device__ __forceinline__ void splith(float x, __half& hi, __half& lo) {
    hi = __float2half_rn(x);
    lo = __float2half_rn(x - __half2float(hi));
}
__device__ __forceinline__ uint32_t packh2(__half a, __half b) {
    return (uint32_t)__half_as_ushort(a) | ((uint32_t)__half_as_ushort(b) << 16);
}
__device__ __forceinline__ void splith2(float x, float y, uint32_t& hi, uint32_t& lo) {
    __half2 hh = __float22half2_rn(make_float2(x, y));
    float2 back = __half22float2(hh);
    __half2 ll = __float22half2_rn(make_float2(x - back.x, y - back.y));
    hi = *reinterpret_cast<uint32_t*>(&hh);
    lo = *reinterpret_cast<uint32_t*>(&ll);
}

// ---------------- mma / ldmatrix / cp.async wrappers ----------------
__device__ __forceinline__ void ldsm_x4(uint32_t* r, uint32_t addr) {
    asm volatile("ldmatrix.sync.aligned.m8n8.x4.shared.b16 {%0,%1,%2,%3}, [%4];"
                 : "=r"(r[0]), "=r"(r[1]), "=r"(r[2]), "=r"(r[3]) : "r"(addr));
}
__device__ __forceinline__ void ldsm_x4t(uint32_t* r, uint32_t addr) {
    asm volatile("ldmatrix.sync.aligned.m8n8.x4.trans.shared.b16 {%0,%1,%2,%3}, [%4];"
                 : "=r"(r[0]), "=r"(r[1]), "=r"(r[2]), "=r"(r[3]) : "r"(addr));
}
__device__ __forceinline__ void mma16816(float4& d, const uint32_t* a, uint32_t b0, uint32_t b1) {
    asm volatile(
        "mma.sync.aligned.m16n8k16.row.col.f32.f16.f16.f32 "
        "{%0,%1,%2,%3},{%4,%5,%6,%7},{%8,%9},{%0,%1,%2,%3};"
        : "+f"(d.x), "+f"(d.y), "+f"(d.z), "+f"(d.w)
        : "r"(a[0]), "r"(a[1]), "r"(a[2]), "r"(a[3]), "r"(b0), "r"(b1));
}
#define CP16(dst, src) \
    asm volatile("cp.async.cg.shared.global [%0], [%1], 16;" :: "r"(dst), "l"(src) : "memory")
#define CPCOMMIT() asm volatile("cp.async.commit_group;" ::: "memory")
#define CPWAITG(n) asm volatile("cp.async.wait_group " #n ";" ::: "memory")

// ---------------- split: 16 floats/thread, exact grid ----------------
__global__ void wsplit16(const float4* __restrict__ src,
                         uint4* __restrict__ hi, uint4* __restrict__ lo, long n16)
{
    long i = (long)blockIdx.x * blockDim.x + threadIdx.x;
    if (i >= n16) return;
    float4 f0 = src[4 * i];
    float4 f1 = src[4 * i + 1];
    float4 f2 = src[4 * i + 2];
    float4 f3 = src[4 * i + 3];
    uint4 h0, l0, h1, l1;
    splith2(f0.x, f0.y, h0.x, l0.x); splith2(f0.z, f0.w, h0.y, l0.y);
    splith2(f1.x, f1.y, h0.z, l0.z); splith2(f1.z, f1.w, h0.w, l0.w);
    splith2(f2.x, f2.y, h1.x, l1.x); splith2(f2.z, f2.w, h1.y, l1.y);
    splith2(f3.x, f3.y, h1.z, l1.z); splith2(f3.z, f3.w, h1.w, l1.w);
    hi[2 * i] = h0; hi[2 * i + 1] = h1;
    lo[2 * i] = l0; lo[2 * i + 1] = l1;
}

// ---------------- padded split, vectorized (wd only) --------------------
__global__ void wsplit_pad4(const float* __restrict__ src,
                            uint2* __restrict__ hi, uint2* __restrict__ lo, int n4)
{
    int stride = gridDim.x * blockDim.x;
    for (int i = blockIdx.x * blockDim.x + threadIdx.x; i < n4; i += stride) {
        int row = i / (WDP / 4);
        int c4  = i - row * (WDP / 4);
        float4 f = make_float4(0.f, 0.f, 0.f, 0.f);
        if (c4 < DOWNW / 4)
            f = *reinterpret_cast<const float4*>(src + (size_t)row * DOWNW + c4 * 4);
        uint2 h, l;
        splith2(f.x, f.y, h.x, l.x);
        splith2(f.z, f.w, h.y, l.y);
        hi[i] = h; lo[i] = l;
    }
}

// ---------------- embedding + rmsnorm ----------------
__global__ void embed_kernel(const int* __restrict__ idx, const float* __restrict__ wte) {
    int row = blockIdx.x;
    int tok = idx[row];
    const float* src = wte + (size_t)tok * C_;
    float s = 0.f;
    for (int i = threadIdx.x; i < C_; i += blockDim.x) { float v = src[i]; s += v * v; }
    s = block_sum(s);
    float r = rsqrtf(s * (1.0f / C_) + EPS_);
    for (int i = threadIdx.x; i < C_; i += blockDim.x) {
        float v = src[i] * r;
        g_x [(size_t)row * C_ + i] = v;
        g_x0[(size_t)row * C_ + i] = v;
    }
}

__global__ void mix_norm_kernel(const float* lr, const float* lx, int layer) {
    int row = blockIdx.x;
    float a = lr ? lr[layer] : 1.0f;
    float b = lx ? lx[layer] : 0.0f;
    float*       xr  = g_x  + (size_t)row * C_;
    const float* x0r = g_x0 + (size_t)row * C_;
    float s = 0.f;
    for (int i = threadIdx.x; i < C_; i += blockDim.x) {
        float v = a * xr[i] + b * x0r[i];
        xr[i] = v;
        s += v * v;
    }
    s = block_sum(s);
    float r = rsqrtf(s * (1.0f / C_) + EPS_);
    for (int i = threadIdx.x; i < C_; i += blockDim.x) {
        float v = xr[i] * r;
        g_xn[(size_t)row * C_ + i] = v;
        __half h, l;
        splith(v, h, l);
        g_xn_h[(size_t)row * C_ + i] = h;
        g_xn_l[(size_t)row * C_ + i] = l;
    }
}

// ---------------- 3xFP16 tensor-core GEMM v6 (templated M-tile) ----------
// MT = 128 or 64. 256 thr / 8 warps (2x4); warp tile (MT/2)x32.
template<int MT>
__global__ __launch_bounds__(256, 2) void gemm_h4(
    const __half* __restrict__ Ah, const __half* __restrict__ Al,
    const __half* __restrict__ Bh, const __half* __restrict__ Bl,
    float* __restrict__ C, const float* __restrict__ D,
    __half* __restrict__ Chi, __half* __restrict__ Clo,
    int N, int K, int lda, int ldb, int ldc, int ldp, int mode, int nterms)
{
    constexpr int MI  = MT / 32;           // m-frags per warp (4 or 2)
    constexpr int APB = MT * 128;          // A plane bytes per stage
    constexpr int STG = APB + 16384;       // stage bytes

    extern __shared__ __align__(1024) char sm[];
    int tid = threadIdx.x;
    int wid = tid >> 5, lane = tid & 31;
    int warp_m = wid >> 2, warp_n = wid & 3;
    int m0 = blockIdx.x * MT, n0 = blockIdx.y * 128;
    uint32_t smb = smem_u32(sm);

    float4 acc[MI][4];
#pragma unroll
    for (int i = 0; i < MI; i++)
#pragma unroll
        for (int j = 0; j < 4; j++) acc[i][j] = make_float4(0.f, 0.f, 0.f, 0.f);

    int a_m   = tid >> 3;
    int a_hl  = (tid >> 2) & 1;
    int a_j   = tid & 3;
    int b_k0  = tid >> 4;
    int b_j   = tid & 15;
    const __half* Asel = a_hl ? Al : Ah;

    int arow0 = warp_m * (MT / 2) + (lane & 15);
    int akof  = (lane & 16);
    int bkr   = (lane & 15);
    int bco   = warp_n * 64 + ((lane >> 4) << 4);
    int ksrot = wid & 1;

    int nk = K >> 5;

    auto issue = [&](int kt, int stg) {
        uint32_t sA = smb + stg * STG;
        uint32_t sB = sA + APB;
#pragma unroll
        for (int r = 0; r < MT / 32; r++) {
            int m = a_m + r * 32;
            uint32_t off = (uint32_t)(m * 128 + a_hl * 64 + a_j * 16);
            off ^= (off >> 3) & 0x70;
            const __half* src = Asel + (size_t)(m0 + m) * lda + kt * 32 + a_j * 8;
            CP16(sA + off, src);
        }
#pragma unroll
        for (int r = 0; r < 4; r++) {
            int k = b_k0 + (r & 1) * 16;
            const __half* Bp = (r < 2) ? Bh : Bl;
            uint32_t off = ((uint32_t)(k * 256 + b_j * 16)) ^ ((uint32_t)(k & 7) << 4);
            off += (r < 2) ? 0u : 8192u;
            const __half* src = Bp + (size_t)(kt * 32 + k) * ldb + n0 + b_j * 8;
            CP16(sB + off, src);
        }
        CPCOMMIT();
    };

    issue(0, 0);
    issue(1, 1);

    for (int kt = 0; kt < nk; kt++) {
        if (kt == nk - 1) { CPWAITG(0); } else { CPWAITG(1); }
        __syncthreads();
        if (kt + 2 < nk) issue(kt + 2, (kt + 2) % 3);

        int s = kt % 3;
        uint32_t sA  = smb + s * STG;
        uint32_t sBh = sA + APB;
        uint32_t sBl = sBh + 8192;
#pragma unroll
        for (int ks0 = 0; ks0 < 2; ks0++) {
            int ks = ks0 ^ ksrot;
            uint32_t af[MI][4], bh[2][4], bl[2][4];
#pragma unroll
            for (int mi = 0; mi < MI; mi++) {
                uint32_t oh = (uint32_t)((arow0 + mi * 16) * 128 + ks * 32 + akof);
                oh ^= (oh >> 3) & 0x70;
                ldsm_x4(af[mi], sA + oh);
            }
#pragma unroll
            for (int nj = 0; nj < 2; nj++) {
                int krow = ks * 16 + bkr;
                uint32_t off = (uint32_t)(krow * 256 + bco + nj * 32) ^ ((uint32_t)(krow & 7) << 4);
                ldsm_x4t(bh[nj], sBh + off);
                ldsm_x4t(bl[nj], sBl + off);
            }
#pragma unroll
            for (int mi = 0; mi < MI; mi++)
#pragma unroll
                for (int ni = 0; ni < 4; ni++)
                    mma16816(acc[mi][ni], af[mi], bh[ni >> 1][(ni & 1) * 2], bh[ni >> 1][(ni & 1) * 2 + 1]);
#pragma unroll
            for (int mi = 0; mi < MI; mi++)
#pragma unroll
                for (int ni = 0; ni < 4; ni++)
                    mma16816(acc[mi][ni], af[mi], bl[ni >> 1][(ni & 1) * 2], bl[ni >> 1][(ni & 1) * 2 + 1]);
            if (nterms == 3) {
#pragma unroll
                for (int mi = 0; mi < MI; mi++) {
                    uint32_t ol = (uint32_t)((arow0 + mi * 16) * 128 + ks * 32 + akof + 64);
                    ol ^= (ol >> 3) & 0x70;
                    ldsm_x4(af[mi], sA + ol);
                }
#pragma unroll
                for (int mi = 0; mi < MI; mi++)
#pragma unroll
                    for (int ni = 0; ni < 4; ni++)
                        mma16816(acc[mi][ni], af[mi], bh[ni >> 1][(ni & 1) * 2], bh[ni >> 1][(ni & 1) * 2 + 1]);
            }
        }
    }

    int g = lane >> 2, t4 = lane & 3;
#pragma unroll
    for (int mi = 0; mi < MI; mi++) {
        int r0 = m0 + warp_m * (MT / 2) + mi * 16 + g;
#pragma unroll
        for (int ni = 0; ni < 4; ni++) {
            int col = n0 + warp_n * 32 + ni * 8 + 2 * t4;
            if (col >= N) continue;
            float4 v = acc[mi][ni];
            if (D) {
                float2 d0 = *reinterpret_cast<const float2*>(D + (size_t)r0 * ldc + col);
                float2 d1 = *reinterpret_cast<const float2*>(D + (size_t)(r0 + 8) * ldc + col);
                v.x += d0.x; v.y += d0.y; v.z += d1.x; v.w += d1.y;
            }
            if (mode == 1) {
                v.x = 15.0f * tanhf(v.x * (1.f / 15.f));
                v.y = 15.0f * tanhf(v.y * (1.f / 15.f));
                v.z = 15.0f * tanhf(v.z * (1.f / 15.f));
                v.w = 15.0f * tanhf(v.w * (1.f / 15.f));
            } else if (mode == 2) {
                v.x = (v.x > 0.f) ? v.x * v.x : 0.f;
                v.y = (v.y > 0.f) ? v.y * v.y : 0.f;
                v.z = (v.z > 0.f) ? v.z * v.z : 0.f;
                v.w = (v.w > 0.f) ? v.w * v.w : 0.f;
            }
            if (C) {
                *reinterpret_cast<float2*>(C + (size_t)r0 * ldc + col) = make_float2(v.x, v.y);
                *reinterpret_cast<float2*>(C + (size_t)(r0 + 8) * ldc + col) = make_float2(v.z, v.w);
            }
            if (Chi) {
                uint32_t ph0, pl0, ph1, pl1;
                splith2(v.x, v.y, ph0, pl0);
                splith2(v.z, v.w, ph1, pl1);
                *reinterpret_cast<uint32_t*>(Chi + (size_t)r0 * ldp + col)       = ph0;
                *reinterpret_cast<uint32_t*>(Clo + (size_t)r0 * ldp + col)       = pl0;
                *reinterpret_cast<uint32_t*>(Chi + (size_t)(r0 + 8) * ldp + col) = ph1;
                *reinterpret_cast<uint32_t*>(Clo + (size_t)(r0 + 8) * ldp + col) = pl1;
            }
        }
    }
}

// ---------------- per-token q/k/v build -> fp16 hi/lo planes --------------
__global__ void build_qkv_kernel(const int* __restrict__ idx,
                                 const float* __restrict__ cosp, const float* __restrict__ sinp,
                                 const float* __restrict__ vg, const float* __restrict__ vetab)
{
    int row = blockIdx.x;
    int h    = threadIdx.x >> 5;
    int lane = threadIdx.x & 31;
    const float* cosr = cosp + (size_t)row * (DR_ / 2);
    const float* sinr = sinp + (size_t)row * (DR_ / 2);

    float gv = g_xn[(size_t)row * C_ + lane] * vg[lane * H_ + h];
    gv = warp_sum(gv);
    float gate = 2.0f / (1.0f + __expf(-gv));

    int r16 = (lane < 16) ? lane : lane - 16;
    float c = cosr[r16], s = sinr[r16];
    size_t base = (size_t)row * C_ + h * 64;

    float kn = g_kv[(size_t)row * KVW + h * 96 + lane];
    const float* dro = g_down + (size_t)row * DOWNW + 512;
    float kr = (lane < 16) ? (dro[lane] * c + dro[lane + 16] * s)
                           : (-dro[lane - 16] * s + dro[lane] * c);
    float ssk = warp_sum(kn * kn + kr * kr);
    float rk = rsqrtf(ssk * (1.0f / 64.0f) + EPS_);
    __half hh_, ll_;
    splith(kn * rk, hh_, ll_);  g_k_h[base + lane]      = hh_; g_k_l[base + lane]      = ll_;
    splith(kr * rk, hh_, ll_);  g_k_h[base + lane + 32] = hh_; g_k_l[base + lane + 32] = ll_;

    const float* qp = g_qpre + (size_t)row * C_ + h * 64;
    float qn = qp[lane];
    float qr = (lane < 16) ? (qp[32 + lane] * c + qp[48 + lane] * s)
                           : (-qp[16 + lane] * s + qp[32 + lane] * c);
    float ssq = warp_sum(qn * qn + qr * qr);
    float rq = rsqrtf(ssq * (1.0f / 64.0f) + EPS_) * 0.125f;
    splith(qn * rq, hh_, ll_);  g_q_h[base + lane]      = hh_; g_q_l[base + lane]      = ll_;
    splith(qr * rq, hh_, ll_);  g_q_h[base + lane + 32] = hh_; g_q_l[base + lane + 32] = ll_;

    int tok = idx[row];
    const float* ver = vetab + (size_t)tok * C_ + h * 64;
    const float* kvv = g_kv + (size_t)row * KVW + h * 96 + 32;
    splith(kvv[lane]      + gate * ver[lane],      hh_, ll_);
    g_v_h[base + lane]      = hh_; g_v_l[base + lane]      = ll_;
    splith(kvv[lane + 32] + gate * ver[lane + 32], hh_, ll_);
    g_v_h[base + lane + 32] = hh_; g_v_l[base + lane + 32] = ll_;
}

// ---------------- tensor-core causal flash attention (double-buffered) ----
// Block order reversed: heavy q-blocks scheduled first.
__global__ __launch_bounds__(128) void attn_mma()
{
    extern __shared__ __align__(1024) char dsm[];
    uint32_t smb = smem_u32(dsm);
    int tid = threadIdx.x;
    int wid = tid >> 5, lane = tid & 31;
    int q0 = (gridDim.x - 1 - blockIdx.x) * 64;   // heavy blocks first
    int hh = blockIdx.y;
    int b  = blockIdx.z;
    int t4 = lane & 3, g = lane >> 2;

#pragma unroll
    for (int j = 0; j < 4; j++) {
        int idxq = tid + j * 128;
        int r = idxq >> 3, ch = idxq & 7;
        uint32_t off = (uint32_t)(r * 128 + ch * 16);
        off ^= (off >> 3) & 0x70;
        size_t src = (size_t)(b * T_ + q0 + r) * C_ + hh * 64 + ch * 8;
        CP16(smb + off,        g_q_h + src);
        CP16(smb + 8192 + off, g_q_l + src);
    }
    CPCOMMIT();

    auto issueKV = [&](int k0, int st) {
        uint32_t base = smb + 16384 + st * 32768;
#pragma unroll
        for (int j = 0; j < 4; j++) {
            int idxq = tid + j * 128;
            int r = idxq >> 3, ch = idxq & 7;
            uint32_t off = (uint32_t)(r * 128 + ch * 16);
            off ^= (off >> 3) & 0x70;
            size_t src = (size_t)(b * T_ + k0 + r) * C_ + hh * 64 + ch * 8;
            CP16(base + off,         g_k_h + src);
            CP16(base + 8192 + off,  g_k_l + src);
            CP16(base + 16384 + off, g_v_h + src);
            CP16(base + 24576 + off, g_v_l + src);
        }
        CPCOMMIT();
    };

    int nt = q0 / 64 + 1;
    issueKV(0, 0);

    CPWAITG(1);
    __syncthreads();

    int arow0 = wid * 16 + (lane & 15);
    int akof  = (lane & 16);
    uint32_t qh[4][4], ql[4][4];
#pragma unroll
    for (int ks = 0; ks < 4; ks++) {
        uint32_t off = (uint32_t)(arow0 * 128 + ks * 32 + akof);
        off ^= (off >> 3) & 0x70;
        ldsm_x4(qh[ks], smb + off);
        ldsm_x4(ql[ks], smb + 8192 + off);
    }

    float4 oacc[8];
#pragma unroll
    for (int i = 0; i < 8; i++) oacc[i] = make_float4(0.f, 0.f, 0.f, 0.f);
    float mrow0 = -1e30f, mrow1 = -1e30f, lrow0 = 0.f, lrow1 = 0.f;

    for (int t = 0; t < nt; t++) {
        if (t + 1 < nt) { issueKV((t + 1) * 64, (t + 1) & 1); CPWAITG(1); }
        else            { CPWAITG(0); }
        __syncthreads();

        uint32_t kb = smb + 16384 + (t & 1) * 32768;

        float4 sacc[8];
#pragma unroll
        for (int i = 0; i < 8; i++) sacc[i] = make_float4(0.f, 0.f, 0.f, 0.f);
#pragma unroll
        for (int ks = 0; ks < 4; ks++) {
#pragma unroll
            for (int njp = 0; njp < 4; njp++) {
                uint32_t kh[4], kl[4];
                uint32_t off = (uint32_t)(((lane & 15) + njp * 16) * 128 + ks * 32 + akof);
                off ^= (off >> 3) & 0x70;
                ldsm_x4(kh, kb + off);
                ldsm_x4(kl, kb + 8192 + off);
                mma16816(sacc[2 * njp],     qh[ks], kh[0], kh[2]);
                mma16816(sacc[2 * njp + 1], qh[ks], kh[1], kh[3]);
                mma16816(sacc[2 * njp],     qh[ks], kl[0], kl[2]);
                mma16816(sacc[2 * njp + 1], qh[ks], kl[1], kl[3]);
                mma16816(sacc[2 * njp],     ql[ks], kh[0], kh[2]);
                mma16816(sacc[2 * njp + 1], ql[ks], kh[1], kh[3]);
            }
        }

        if (t == nt - 1) {
            int qiA = wid * 16 + g, qiB = qiA + 8;
#pragma unroll
            for (int nj = 0; nj < 8; nj++) {
                int ki = nj * 8 + t4 * 2;
                if (ki     > qiA) sacc[nj].x = -1e30f;
                if (ki + 1 > qiA) sacc[nj].y = -1e30f;
                if (ki     > qiB) sacc[nj].z = -1e30f;
                if (ki + 1 > qiB) sacc[nj].w = -1e30f;
            }
        }

        float mx0 = -1e30f, mx1 = -1e30f;
#pragma unroll
        for (int nj = 0; nj < 8; nj++) {
            mx0 = fmaxf(mx0, fmaxf(sacc[nj].x, sacc[nj].y));
            mx1 = fmaxf(mx1, fmaxf(sacc[nj].z, sacc[nj].w));
        }
        mx0 = fmaxf(mx0, __shfl_xor_sync(0xffffffffu, mx0, 1));
        mx0 = fmaxf(mx0, __shfl_xor_sync(0xffffffffu, mx0, 2));
        mx1 = fmaxf(mx1, __shfl_xor_sync(0xffffffffu, mx1, 1));
        mx1 = fmaxf(mx1, __shfl_xor_sync(0xffffffffu, mx1, 2));
        float mn0 = fmaxf(mrow0, mx0), mn1 = fmaxf(mrow1, mx1);
        float c0 = __expf(mrow0 - mn0), c1 = __expf(mrow1 - mn1);
        float sum0 = 0.f, sum1 = 0.f;
#pragma unroll
        for (int nj = 0; nj < 8; nj++) {
            sacc[nj].x = __expf(sacc[nj].x - mn0);
            sacc[nj].y = __expf(sacc[nj].y - mn0);
            sacc[nj].z = __expf(sacc[nj].z - mn1);
            sacc[nj].w = __expf(sacc[nj].w - mn1);
            sum0 += sacc[nj].x + sacc[nj].y;
            sum1 += sacc[nj].z + sacc[nj].w;
        }
        sum0 += __shfl_xor_sync(0xffffffffu, sum0, 1);
        sum0 += __shfl_xor_sync(0xffffffffu, sum0, 2);
        sum1 += __shfl_xor_sync(0xffffffffu, sum1, 1);
        sum1 += __shfl_xor_sync(0xffffffffu, sum1, 2);
        lrow0 = lrow0 * c0 + sum0;
        lrow1 = lrow1 * c1 + sum1;
        mrow0 = mn0; mrow1 = mn1;
#pragma unroll
        for (int nd = 0; nd < 8; nd++) {
            oacc[nd].x *= c0; oacc[nd].y *= c0;
            oacc[nd].z *= c1; oacc[nd].w *= c1;
        }

#pragma unroll
        for (int kk = 0; kk < 4; kk++) {
            uint32_t ah[4], al[4];
            splith2(sacc[2*kk].x,   sacc[2*kk].y,   ah[0], al[0]);
            splith2(sacc[2*kk].z,   sacc[2*kk].w,   ah[1], al[1]);
            splith2(sacc[2*kk+1].x, sacc[2*kk+1].y, ah[2], al[2]);
            splith2(sacc[2*kk+1].z, sacc[2*kk+1].w, ah[3], al[3]);
#pragma unroll
            for (int ndp = 0; ndp < 4; ndp++) {
                uint32_t vh[4], vl[4];
                uint32_t off = (uint32_t)((kk * 16 + (lane & 15)) * 128 + ndp * 32 + akof);
                off ^= (off >> 3) & 0x70;
                ldsm_x4t(vh, kb + 16384 + off);
                ldsm_x4t(vl, kb + 24576 + off);
                mma16816(oacc[2 * ndp],     ah, vh[0], vh[1]);
                mma16816(oacc[2 * ndp + 1], ah, vh[2], vh[3]);
                mma16816(oacc[2 * ndp],     ah, vl[0], vl[1]);
                mma16816(oacc[2 * ndp + 1], ah, vl[2], vl[3]);
                mma16816(oacc[2 * ndp],     al, vh[0], vh[1]);
                mma16816(oacc[2 * ndp + 1], al, vh[2], vh[3]);
            }
        }
        __syncthreads();
    }

    float inv0 = 1.0f / lrow0, inv1 = 1.0f / lrow1;
    int r0 = q0 + wid * 16 + g, r1 = r0 + 8;
    size_t b0 = (size_t)(b * T_ + r0) * C_ + hh * 64;
    size_t b1 = (size_t)(b * T_ + r1) * C_ + hh * 64;
#pragma unroll
    for (int nd = 0; nd < 8; nd++) {
        int d = nd * 8 + t4 * 2;
        uint32_t ph, pl;
        splith2(oacc[nd].x * inv0, oacc[nd].y * inv0, ph, pl);
        *reinterpret_cast<uint32_t*>(g_y_h + b0 + d) = ph;
        *reinterpret_cast<uint32_t*>(g_y_l + b0 + d) = pl;
        splith2(oacc[nd].z * inv1, oacc[nd].w * inv1, ph, pl);
        *reinterpret_cast<uint32_t*>(g_y_h + b1 + d) = ph;
        *reinterpret_cast<uint32_t*>(g_y_l + b1 + d) = pl;
    }
}

// ---------------- host orchestration ----------------
extern "C" void kernel_launch(void* const* d_in, const int* in_sizes, int n_in,
                              void* d_out, int out_size)
{
    (void)in_sizes; (void)n_in; (void)out_size;
    const int*   idx  = (const int*)  d_in[0];
    const float* cosp = (const float*)d_in[1];
    const float* sinp = (const float*)d_in[2];
    const float* wte  = (const float*)d_in[3];
    const float* vemb = (const float*)d_in[4];
    const float* wd   = (const float*)d_in[5];
    const float* wukv = (const float*)d_in[6];
    const float* wuq  = (const float*)d_in[7];
    const float* vg   = (const float*)d_in[8];
    const float* ap   = (const float*)d_in[9];
    const float* fc   = (const float*)d_in[10];
    const float* pj   = (const float*)d_in[11];
    const float* lr   = (const float*)d_in[12];
    const float* lx   = (const float*)d_in[13];
    const float* lmh  = (const float*)d_in[14];
    float* out = (float*)d_out;

    float *px, *pdown, *pkv, *pqpre;
    cudaGetSymbolAddress((void**)&px,    g_x);
    cudaGetSymbolAddress((void**)&pdown, g_down);
    cudaGetSymbolAddress((void**)&pkv,   g_kv);
    cudaGetSymbolAddress((void**)&pqpre, g_qpre);

    __half *wd_h, *wd_l, *wukv_h, *wukv_l, *wuq_h, *wuq_l, *ap_h, *ap_l;
    __half *fc_h, *fc_l, *pj_h, *pj_l, *lmh_h, *lmh_l;
    __half *xn_h, *xn_l, *dn_h, *dn_l, *y_h, *y_l, *h_h, *h_l;
    cudaGetSymbolAddress((void**)&wd_h,   g_wd_h);   cudaGetSymbolAddress((void**)&wd_l,   g_wd_l);
    cudaGetSymbolAddress((void**)&wukv_h, g_wukv_h); cudaGetSymbolAddress((void**)&wukv_l, g_wukv_l);
    cudaGetSymbolAddress((void**)&wuq_h,  g_wuq_h);  cudaGetSymbolAddress((void**)&wuq_l,  g_wuq_l);
    cudaGetSymbolAddress((void**)&ap_h,   g_ap_h);   cudaGetSymbolAddress((void**)&ap_l,   g_ap_l);
    cudaGetSymbolAddress((void**)&fc_h,   g_fc_h);   cudaGetSymbolAddress((void**)&fc_l,   g_fc_l);
    cudaGetSymbolAddress((void**)&pj_h,   g_pj_h);   cudaGetSymbolAddress((void**)&pj_l,   g_pj_l);
    cudaGetSymbolAddress((void**)&lmh_h,  g_lmh_h);  cudaGetSymbolAddress((void**)&lmh_l,  g_lmh_l);
    cudaGetSymbolAddress((void**)&xn_h,   g_xn_h);   cudaGetSymbolAddress((void**)&xn_l,   g_xn_l);
    cudaGetSymbolAddress((void**)&dn_h,   g_dn_h);   cudaGetSymbolAddress((void**)&dn_l,   g_dn_l);
    cudaGetSymbolAddress((void**)&y_h,    g_y_h);    cudaGetSymbolAddress((void**)&y_l,    g_y_l);
    cudaGetSymbolAddress((void**)&h_h,    g_h_h);    cudaGetSymbolAddress((void**)&h_l,    g_h_l);

    const int SM128 = 3 * (128 * 128 + 16384);   // 96 KB
    const int SM64  = 3 * (64 * 128 + 16384);    // 72 KB
    cudaFuncSetAttribute(gemm_h4<128>, cudaFuncAttributeMaxDynamicSharedMemorySize, SM128);
    cudaFuncSetAttribute(gemm_h4<64>,  cudaFuncAttributeMaxDynamicSharedMemorySize, SM64);
    const int ASM = 81920;
    cudaFuncSetAttribute(attn_mma, cudaFuncAttributeMaxDynamicSharedMemorySize, ASM);

    const int GM1 = NTOK / 128;   // 16
    const int GM2 = NTOK / 64;    // 32

    // ---- early splits ----
    wsplit_pad4<<<2048, 256>>>(wd, (uint2*)wd_h, (uint2*)wd_l, L_ * C_ * WDP / 4);
    wsplit16<<<(int)((long)L_ * DC_ * KVW / 16 / 256), 256>>>(
        (const float4*)wukv, (uint4*)wukv_h, (uint4*)wukv_l, (long)L_ * DC_ * KVW / 16);
    wsplit16<<<(int)((long)L_ * DC1_ * C_ / 16 / 256), 256>>>(
        (const float4*)wuq, (uint4*)wuq_h, (uint4*)wuq_l, (long)L_ * DC1_ * C_ / 16);

    embed_kernel<<<NTOK, 256>>>(idx, wte);
    mix_norm_kernel<<<NTOK, 256>>>(lr, lx, 0);

    // down GEMM (layer 0), MT=64: grid 32x5 = 160
    gemm_h4<64><<<dim3(GM2, WDP / 128), 256, SM64>>>(
        xn_h, xn_l, wd_h, wd_l,
        pdown, nullptr, dn_h, dn_l,
        DOWNW, C_, C_, WDP, DOWNW, DOWNW, 0, 3);

    // ---- remaining splits ----
    wsplit16<<<(int)((long)L_ * C_ * C_ / 16 / 256), 256>>>(
        (const float4*)ap, (uint4*)ap_h, (uint4*)ap_l, (long)L_ * C_ * C_ / 16);
    wsplit16<<<(int)((long)L_ * C_ * 4 * C_ / 16 / 256), 256>>>(
        (const float4*)fc, (uint4*)fc_h, (uint4*)fc_l, (long)L_ * C_ * 4 * C_ / 16);
    wsplit16<<<(int)((long)L_ * 4 * C_ * C_ / 16 / 256), 256>>>(
        (const float4*)pj, (uint4*)pj_h, (uint4*)pj_l, (long)L_ * 4 * C_ * C_ / 16);
    wsplit16<<<(int)((long)C_ * V_ / 16 / 256), 256>>>(
        (const float4*)lmh, (uint4*)lmh_h, (uint4*)lmh_l, (long)C_ * V_ / 16);

    for (int l = 0; l < L_; l++) {
        if (l > 0) {
            mix_norm_kernel<<<NTOK, 256>>>(lr, lx, l);
            gemm_h4<64><<<dim3(GM2, WDP / 128), 256, SM64>>>(
                xn_h, xn_l, wd_h + (size_t)l * C_ * WDP, wd_l + (size_t)l * C_ * WDP,
                pdown, nullptr, dn_h, dn_l,
                DOWNW, C_, C_, WDP, DOWNW, DOWNW, 0, 3);
        }

        // kv: MT=128, grid 16x12 = 192
        gemm_h4<128><<<dim3(GM1, KVW / 128), 256, SM128>>>(
            dn_h, dn_l, wukv_h + (size_t)l * DC_ * KVW, wukv_l + (size_t)l * DC_ * KVW,
            pkv, nullptr, nullptr, nullptr,
            KVW, DC_, DOWNW, KVW, KVW, 0, 0, 3);

        // qpre: MT=64, grid 32x8 = 256
        gemm_h4<64><<<dim3(GM2, C_ / 128), 256, SM64>>>(
            dn_h + DC_, dn_l + DC_, wuq_h + (size_t)l * DC1_ * C_, wuq_l + (size_t)l * DC1_ * C_,
            pqpre, nullptr, nullptr, nullptr,
            C_, DC1_, DOWNW, C_, C_, 0, 0, 3);

        build_qkv_kernel<<<NTOK, 512>>>(idx, cosp, sinp,
                                        vg + (size_t)l * 32 * H_,
                                        vemb + (size_t)l * V_ * C_);

        attn_mma<<<dim3(T_ / 64, H_, B_), 128, ASM>>>();

        // ap: MT=64, grid 32x8 = 256
        gemm_h4<64><<<dim3(GM2, C_ / 128), 256, SM64>>>(
            y_h, y_l, ap_h + (size_t)l * C_ * C_, ap_l + (size_t)l * C_ * C_,
            px, px, nullptr, nullptr,
            C_, C_, C_, C_, C_, 0, 0, 3);

        mix_norm_kernel<<<NTOK, 256>>>(nullptr, nullptr, 0);

        // fc: MT=128, grid 16x32 = 512
        gemm_h4<128><<<dim3(GM1, 4 * C_ / 128), 256, SM128>>>(
            xn_h, xn_l, fc_h + (size_t)l * C_ * 4 * C_, fc_l + (size_t)l * C_ * 4 * C_,
            nullptr, nullptr, h_h, h_l,
            4 * C_, C_, C_, 4 * C_, 0, 4 * C_, 2, 3);

        // pj: MT=64, grid 32x8 = 256
        gemm_h4<64><<<dim3(GM2, C_ / 128), 256, SM64>>>(
            h_h, h_l, pj_h + (size_t)l * 4 * C_ * C_, pj_l + (size_t)l * 4 * C_ * C_,
            px, px, nullptr, nullptr,
            C_, 4 * C_, 4 * C_, C_, C_, 0, 0, 3);
    }

    mix_norm_kernel<<<NTOK, 256>>>(nullptr, nullptr, 0);
    // lm_head: MT=128, grid 16x250 = 4000, 2-term
    gemm_h4<128><<<dim3(GM1, V_ / 128), 256, SM128>>>(
        xn_h, xn_l, lmh_h, lmh_l,
        out, nullptr, nullptr, nullptr,
        V_, C_, C_, V_, V_, 0, 1, 2);
}

// round 13
// speedup vs baseline: 1.7979x; 1.0117x over previous
#include <cuda_runtime.h>
#include <cuda_fp16.h>
#include <math.h>
#include <stdint.h>

// ---------------- problem constants ----------------
#define B_    2
#define T_    1024
#define C_    1024
#define H_    16
#define HD_   64
#define DC_   256
#define DC1_  256
#define DR_   32
#define DN_   32
#define V_    32000
#define L_    4
#define NTOK  (B_*T_)             // 2048
#define DOWNW (DC_+DC1_+DR_)      // 544
#define WDP   640                 // padded wd output width
#define KVW   (H_*(DN_+HD_))      // 1536
#define EPS_  1.1920929e-07f

// ---------------- fp32 scratch ----------------
__device__ float g_x   [NTOK*C_];
__device__ float g_x0  [NTOK*C_];
__device__ float g_xn  [NTOK*C_];
__device__ float g_down[NTOK*DOWNW];
__device__ float g_kv  [NTOK*KVW];
__device__ float g_qpre[NTOK*C_];

// ---------------- fp16 hi/lo planes ----------------
__device__ __half g_wd_h  [L_*C_*WDP],    g_wd_l  [L_*C_*WDP];
__device__ __half g_wukv_h[L_*DC_*KVW],   g_wukv_l[L_*DC_*KVW];
__device__ __half g_wuq_h [L_*DC1_*C_],   g_wuq_l [L_*DC1_*C_];
__device__ __half g_ap_h  [L_*C_*C_],     g_ap_l  [L_*C_*C_];
__device__ __half g_fc_h  [L_*C_*4*C_],   g_fc_l  [L_*C_*4*C_];
__device__ __half g_pj_h  [L_*4*C_*C_],   g_pj_l  [L_*4*C_*C_];
__device__ __half g_lmh_h [C_*V_],        g_lmh_l [C_*V_];
__device__ __half g_xn_h  [NTOK*C_],      g_xn_l  [NTOK*C_];
__device__ __half g_dn_h  [NTOK*DOWNW],   g_dn_l  [NTOK*DOWNW];
__device__ __half g_y_h   [NTOK*C_],      g_y_l   [NTOK*C_];
__device__ __half g_h_h   [NTOK*4*C_],    g_h_l   [NTOK*4*C_];
__device__ __half g_q_h   [NTOK*C_],      g_q_l   [NTOK*C_];
__device__ __half g_k_h   [NTOK*C_],      g_k_l   [NTOK*C_];
__device__ __half g_v_h   [NTOK*C_],      g_v_l   [NTOK*C_];

// ---------------- helpers ----------------
__device__ __forceinline__ uint32_t smem_u32(const void* p) {
    uint32_t a;
    asm("{ .reg .u64 t; cvta.to.shared.u64 t, %1; cvt.u32.u64 %0, t; }" : "=r"(a) : "l"(p));
    return a;
}
__device__ __forceinline__ float warp_sum(float v) {
    v += __shfl_xor_sync(0xffffffffu, v, 16);
    v += __shfl_xor_sync(0xffffffffu, v, 8);
    v += __shfl_xor_sync(0xffffffffu, v, 4);
    v += __shfl_xor_sync(0xffffffffu, v, 2);
    v += __shfl_xor_sync(0xffffffffu, v, 1);
    return v;
}
__device__ __forceinline__ float block_sum(float v) {
    __shared__ float sh[32];
    int lane = threadIdx.x & 31, wid = threadIdx.x >> 5;
    v = warp_sum(v);
    if (lane == 0) sh[wid] = v;
    __syncthreads();
    int nw = blockDim.x >> 5;
    if (wid == 0) {
        float t = (lane < nw) ? sh[lane] : 0.f;
        t = warp_sum(t);
        if (lane == 0) sh[0] = t;
    }
    __syncthreads();
    return sh[0];
}
__device__ __forceinline__ void splith(float x, __half& hi, __half& lo) {
    hi = __float2half_rn(x);
    lo = __float2half_rn(x - __half2float(hi));
}
__device__ __forceinline__ uint32_t packh2(__half a, __half b) {
    return (uint32_t)__half_as_ushort(a) | ((uint32_t)__half_as_ushort(b) << 16);
}
__device__ __forceinline__ void splith2(float x, float y, uint32_t& hi, uint32_t& lo) {
    __half2 hh = __float22half2_rn(make_float2(x, y));
    float2 back = __half22float2(hh);
    __half2 ll = __float22half2_rn(make_float2(x - back.x, y - back.y));
    hi = *reinterpret_cast<uint32_t*>(&hh);
    lo = *reinterpret_cast<uint32_t*>(&ll);
}

// ---------------- mma / ldmatrix / cp.async wrappers ----------------
__device__ __forceinline__ void ldsm_x4(uint32_t* r, uint32_t addr) {
    asm volatile("ldmatrix.sync.aligned.m8n8.x4.shared.b16 {%0,%1,%2,%3}, [%4];"
                 : "=r"(r[0]), "=r"(r[1]), "=r"(r[2]), "=r"(r[3]) : "r"(addr));
}
__device__ __forceinline__ void ldsm_x4t(uint32_t* r, uint32_t addr) {
    asm volatile("ldmatrix.sync.aligned.m8n8.x4.trans.shared.b16 {%0,%1,%2,%3}, [%4];"
                 : "=r"(r[0]), "=r"(r[1]), "=r"(r[2]), "=r"(r[3]) : "r"(addr));
}
__device__ __forceinline__ void mma16816(float4& d, const uint32_t* a, uint32_t b0, uint32_t b1) {
    asm volatile(
        "mma.sync.aligned.m16n8k16.row.col.f32.f16.f16.f32 "
        "{%0,%1,%2,%3},{%4,%5,%6,%7},{%8,%9},{%0,%1,%2,%3};"
        : "+f"(d.x), "+f"(d.y), "+f"(d.z), "+f"(d.w)
        : "r"(a[0]), "r"(a[1]), "r"(a[2]), "r"(a[3]), "r"(b0), "r"(b1));
}
#define CP16(dst, src) \
    asm volatile("cp.async.cg.shared.global [%0], [%1], 16;" :: "r"(dst), "l"(src) : "memory")
#define CPCOMMIT() asm volatile("cp.async.commit_group;" ::: "memory")
#define CPWAITG(n) asm volatile("cp.async.wait_group " #n ";" ::: "memory")

// ---------------- split: 16 floats/thread, exact grid ----------------
__global__ void wsplit16(const float4* __restrict__ src,
                         uint4* __restrict__ hi, uint4* __restrict__ lo, long n16)
{
    long i = (long)blockIdx.x * blockDim.x + threadIdx.x;
    if (i >= n16) return;
    float4 f0 = src[4 * i];
    float4 f1 = src[4 * i + 1];
    float4 f2 = src[4 * i + 2];
    float4 f3 = src[4 * i + 3];
    uint4 h0, l0, h1, l1;
    splith2(f0.x, f0.y, h0.x, l0.x); splith2(f0.z, f0.w, h0.y, l0.y);
    splith2(f1.x, f1.y, h0.z, l0.z); splith2(f1.z, f1.w, h0.w, l0.w);
    splith2(f2.x, f2.y, h1.x, l1.x); splith2(f2.z, f2.w, h1.y, l1.y);
    splith2(f3.x, f3.y, h1.z, l1.z); splith2(f3.z, f3.w, h1.w, l1.w);
    hi[2 * i] = h0; hi[2 * i + 1] = h1;
    lo[2 * i] = l0; lo[2 * i + 1] = l1;
}

// ---------------- padded split, vectorized (wd only) --------------------
__global__ void wsplit_pad4(const float* __restrict__ src,
                            uint2* __restrict__ hi, uint2* __restrict__ lo, int n4)
{
    int stride = gridDim.x * blockDim.x;
    for (int i = blockIdx.x * blockDim.x + threadIdx.x; i < n4; i += stride) {
        int row = i / (WDP / 4);
        int c4  = i - row * (WDP / 4);
        float4 f = make_float4(0.f, 0.f, 0.f, 0.f);
        if (c4 < DOWNW / 4)
            f = *reinterpret_cast<const float4*>(src + (size_t)row * DOWNW + c4 * 4);
        uint2 h, l;
        splith2(f.x, f.y, h.x, l.x);
        splith2(f.z, f.w, h.y, l.y);
        hi[i] = h; lo[i] = l;
    }
}

// ---------------- embedding + rmsnorm ----------------
__global__ void embed_kernel(const int* __restrict__ idx, const float* __restrict__ wte) {
    int row = blockIdx.x;
    int tok = idx[row];
    const float* src = wte + (size_t)tok * C_;
    float s = 0.f;
    for (int i = threadIdx.x; i < C_; i += blockDim.x) { float v = src[i]; s += v * v; }
    s = block_sum(s);
    float r = rsqrtf(s * (1.0f / C_) + EPS_);
    for (int i = threadIdx.x; i < C_; i += blockDim.x) {
        float v = src[i] * r;
        g_x [(size_t)row * C_ + i] = v;
        g_x0[(size_t)row * C_ + i] = v;
    }
}

__global__ void mix_norm_kernel(const float* lr, const float* lx, int layer) {
    int row = blockIdx.x;
    float a = lr ? lr[layer] : 1.0f;
    float b = lx ? lx[layer] : 0.0f;
    float*       xr  = g_x  + (size_t)row * C_;
    const float* x0r = g_x0 + (size_t)row * C_;
    float s = 0.f;
    for (int i = threadIdx.x; i < C_; i += blockDim.x) {
        float v = a * xr[i] + b * x0r[i];
        xr[i] = v;
        s += v * v;
    }
    s = block_sum(s);
    float r = rsqrtf(s * (1.0f / C_) + EPS_);
    for (int i = threadIdx.x; i < C_; i += blockDim.x) {
        float v = xr[i] * r;
        g_xn[(size_t)row * C_ + i] = v;
        __half h, l;
        splith(v, h, l);
        g_xn_h[(size_t)row * C_ + i] = h;
        g_xn_l[(size_t)row * C_ + i] = l;
    }
}

// ---------------- 3xFP16 tensor-core GEMM v6 (templated M-tile) ----------
template<int MT>
__global__ __launch_bounds__(256, 2) void gemm_h4(
    const __half* __restrict__ Ah, const __half* __restrict__ Al,
    const __half* __restrict__ Bh, const __half* __restrict__ Bl,
    float* __restrict__ C, const float* __restrict__ D,
    __half* __restrict__ Chi, __half* __restrict__ Clo,
    int N, int K, int lda, int ldb, int ldc, int ldp, int mode, int nterms)
{
    constexpr int MI  = MT / 32;
    constexpr int APB = MT * 128;
    constexpr int STG = APB + 16384;

    extern __shared__ __align__(1024) char sm[];
    int tid = threadIdx.x;
    int wid = tid >> 5, lane = tid & 31;
    int warp_m = wid >> 2, warp_n = wid & 3;
    int m0 = blockIdx.x * MT, n0 = blockIdx.y * 128;
    uint32_t smb = smem_u32(sm);

    float4 acc[MI][4];
#pragma unroll
    for (int i = 0; i < MI; i++)
#pragma unroll
        for (int j = 0; j < 4; j++) acc[i][j] = make_float4(0.f, 0.f, 0.f, 0.f);

    int a_m   = tid >> 3;
    int a_hl  = (tid >> 2) & 1;
    int a_j   = tid & 3;
    int b_k0  = tid >> 4;
    int b_j   = tid & 15;
    const __half* Asel = a_hl ? Al : Ah;

    int arow0 = warp_m * (MT / 2) + (lane & 15);
    int akof  = (lane & 16);
    int bkr   = (lane & 15);
    int bco   = warp_n * 64 + ((lane >> 4) << 4);
    int ksrot = wid & 1;

    int nk = K >> 5;

    auto issue = [&](int kt, int stg) {
        uint32_t sA = smb + stg * STG;
        uint32_t sB = sA + APB;
#pragma unroll
        for (int r = 0; r < MT / 32; r++) {
            int m = a_m + r * 32;
            uint32_t off = (uint32_t)(m * 128 + a_hl * 64 + a_j * 16);
            off ^= (off >> 3) & 0x70;
            const __half* src = Asel + (size_t)(m0 + m) * lda + kt * 32 + a_j * 8;
            CP16(sA + off, src);
        }
#pragma unroll
        for (int r = 0; r < 4; r++) {
            int k = b_k0 + (r & 1) * 16;
            const __half* Bp = (r < 2) ? Bh : Bl;
            uint32_t off = ((uint32_t)(k * 256 + b_j * 16)) ^ ((uint32_t)(k & 7) << 4);
            off += (r < 2) ? 0u : 8192u;
            const __half* src = Bp + (size_t)(kt * 32 + k) * ldb + n0 + b_j * 8;
            CP16(sB + off, src);
        }
        CPCOMMIT();
    };

    issue(0, 0);
    issue(1, 1);

    for (int kt = 0; kt < nk; kt++) {
        if (kt == nk - 1) { CPWAITG(0); } else { CPWAITG(1); }
        __syncthreads();
        if (kt + 2 < nk) issue(kt + 2, (kt + 2) % 3);

        int s = kt % 3;
        uint32_t sA  = smb + s * STG;
        uint32_t sBh = sA + APB;
        uint32_t sBl = sBh + 8192;
#pragma unroll
        for (int ks0 = 0; ks0 < 2; ks0++) {
            int ks = ks0 ^ ksrot;
            uint32_t af[MI][4], bh[2][4], bl[2][4];
#pragma unroll
            for (int mi = 0; mi < MI; mi++) {
                uint32_t oh = (uint32_t)((arow0 + mi * 16) * 128 + ks * 32 + akof);
                oh ^= (oh >> 3) & 0x70;
                ldsm_x4(af[mi], sA + oh);
            }
#pragma unroll
            for (int nj = 0; nj < 2; nj++) {
                int krow = ks * 16 + bkr;
                uint32_t off = (uint32_t)(krow * 256 + bco + nj * 32) ^ ((uint32_t)(krow & 7) << 4);
                ldsm_x4t(bh[nj], sBh + off);
                ldsm_x4t(bl[nj], sBl + off);
            }
#pragma unroll
            for (int mi = 0; mi < MI; mi++)
#pragma unroll
                for (int ni = 0; ni < 4; ni++)
                    mma16816(acc[mi][ni], af[mi], bh[ni >> 1][(ni & 1) * 2], bh[ni >> 1][(ni & 1) * 2 + 1]);
#pragma unroll
            for (int mi = 0; mi < MI; mi++)
#pragma unroll
                for (int ni = 0; ni < 4; ni++)
                    mma16816(acc[mi][ni], af[mi], bl[ni >> 1][(ni & 1) * 2], bl[ni >> 1][(ni & 1) * 2 + 1]);
            if (nterms == 3) {
#pragma unroll
                for (int mi = 0; mi < MI; mi++) {
                    uint32_t ol = (uint32_t)((arow0 + mi * 16) * 128 + ks * 32 + akof + 64);
                    ol ^= (ol >> 3) & 0x70;
                    ldsm_x4(af[mi], sA + ol);
                }
#pragma unroll
                for (int mi = 0; mi < MI; mi++)
#pragma unroll
                    for (int ni = 0; ni < 4; ni++)
                        mma16816(acc[mi][ni], af[mi], bh[ni >> 1][(ni & 1) * 2], bh[ni >> 1][(ni & 1) * 2 + 1]);
            }
        }
    }

    int g = lane >> 2, t4 = lane & 3;
#pragma unroll
    for (int mi = 0; mi < MI; mi++) {
        int r0 = m0 + warp_m * (MT / 2) + mi * 16 + g;
#pragma unroll
        for (int ni = 0; ni < 4; ni++) {
            int col = n0 + warp_n * 32 + ni * 8 + 2 * t4;
            if (col >= N) continue;
            float4 v = acc[mi][ni];
            if (D) {
                float2 d0 = *reinterpret_cast<const float2*>(D + (size_t)r0 * ldc + col);
                float2 d1 = *reinterpret_cast<const float2*>(D + (size_t)(r0 + 8) * ldc + col);
                v.x += d0.x; v.y += d0.y; v.z += d1.x; v.w += d1.y;
            }
            if (mode == 1) {
                v.x = 15.0f * tanhf(v.x * (1.f / 15.f));
                v.y = 15.0f * tanhf(v.y * (1.f / 15.f));
                v.z = 15.0f * tanhf(v.z * (1.f / 15.f));
                v.w = 15.0f * tanhf(v.w * (1.f / 15.f));
            } else if (mode == 2) {
                v.x = (v.x > 0.f) ? v.x * v.x : 0.f;
                v.y = (v.y > 0.f) ? v.y * v.y : 0.f;
                v.z = (v.z > 0.f) ? v.z * v.z : 0.f;
                v.w = (v.w > 0.f) ? v.w * v.w : 0.f;
            }
            if (C) {
                *reinterpret_cast<float2*>(C + (size_t)r0 * ldc + col) = make_float2(v.x, v.y);
                *reinterpret_cast<float2*>(C + (size_t)(r0 + 8) * ldc + col) = make_float2(v.z, v.w);
            }
            if (Chi) {
                uint32_t ph0, pl0, ph1, pl1;
                splith2(v.x, v.y, ph0, pl0);
                splith2(v.z, v.w, ph1, pl1);
                *reinterpret_cast<uint32_t*>(Chi + (size_t)r0 * ldp + col)       = ph0;
                *reinterpret_cast<uint32_t*>(Clo + (size_t)r0 * ldp + col)       = pl0;
                *reinterpret_cast<uint32_t*>(Chi + (size_t)(r0 + 8) * ldp + col) = ph1;
                *reinterpret_cast<uint32_t*>(Clo + (size_t)(r0 + 8) * ldp + col) = pl1;
            }
        }
    }
}

// ---------------- per-token q/k/v build -> fp16 hi/lo planes --------------
__global__ void build_qkv_kernel(const int* __restrict__ idx,
                                 const float* __restrict__ cosp, const float* __restrict__ sinp,
                                 const float* __restrict__ vg, const float* __restrict__ vetab)
{
    int row = blockIdx.x;
    int h    = threadIdx.x >> 5;
    int lane = threadIdx.x & 31;
    const float* cosr = cosp + (size_t)row * (DR_ / 2);
    const float* sinr = sinp + (size_t)row * (DR_ / 2);

    float gv = g_xn[(size_t)row * C_ + lane] * vg[lane * H_ + h];
    gv = warp_sum(gv);
    float gate = 2.0f / (1.0f + __expf(-gv));

    int r16 = (lane < 16) ? lane : lane - 16;
    float c = cosr[r16], s = sinr[r16];
    size_t base = (size_t)row * C_ + h * 64;

    float kn = g_kv[(size_t)row * KVW + h * 96 + lane];
    const float* dro = g_down + (size_t)row * DOWNW + 512;
    float kr = (lane < 16) ? (dro[lane] * c + dro[lane + 16] * s)
                           : (-dro[lane - 16] * s + dro[lane] * c);
    float ssk = warp_sum(kn * kn + kr * kr);
    float rk = rsqrtf(ssk * (1.0f / 64.0f) + EPS_);
    __half hh_, ll_;
    splith(kn * rk, hh_, ll_);  g_k_h[base + lane]      = hh_; g_k_l[base + lane]      = ll_;
    splith(kr * rk, hh_, ll_);  g_k_h[base + lane + 32] = hh_; g_k_l[base + lane + 32] = ll_;

    const float* qp = g_qpre + (size_t)row * C_ + h * 64;
    float qn = qp[lane];
    float qr = (lane < 16) ? (qp[32 + lane] * c + qp[48 + lane] * s)
                           : (-qp[16 + lane] * s + qp[32 + lane] * c);
    float ssq = warp_sum(qn * qn + qr * qr);
    float rq = rsqrtf(ssq * (1.0f / 64.0f) + EPS_) * 0.125f;
    splith(qn * rq, hh_, ll_);  g_q_h[base + lane]      = hh_; g_q_l[base + lane]      = ll_;
    splith(qr * rq, hh_, ll_);  g_q_h[base + lane + 32] = hh_; g_q_l[base + lane + 32] = ll_;

    int tok = idx[row];
    const float* ver = vetab + (size_t)tok * C_ + h * 64;
    const float* kvv = g_kv + (size_t)row * KVW + h * 96 + 32;
    splith(kvv[lane]      + gate * ver[lane],      hh_, ll_);
    g_v_h[base + lane]      = hh_; g_v_l[base + lane]      = ll_;
    splith(kvv[lane + 32] + gate * ver[lane + 32], hh_, ll_);
    g_v_h[base + lane + 32] = hh_; g_v_l[base + lane + 32] = ll_;
}

// ---------------- tensor-core causal flash attention (double-buffered) ----
__global__ __launch_bounds__(128) void attn_mma()
{
    extern __shared__ __align__(1024) char dsm[];
    uint32_t smb = smem_u32(dsm);
    int tid = threadIdx.x;
    int wid = tid >> 5, lane = tid & 31;
    int q0 = (gridDim.x - 1 - blockIdx.x) * 64;
    int hh = blockIdx.y;
    int b  = blockIdx.z;
    int t4 = lane & 3, g = lane >> 2;

#pragma unroll
    for (int j = 0; j < 4; j++) {
        int idxq = tid + j * 128;
        int r = idxq >> 3, ch = idxq & 7;
        uint32_t off = (uint32_t)(r * 128 + ch * 16);
        off ^= (off >> 3) & 0x70;
        size_t src = (size_t)(b * T_ + q0 + r) * C_ + hh * 64 + ch * 8;
        CP16(smb + off,        g_q_h + src);
        CP16(smb + 8192 + off, g_q_l + src);
    }
    CPCOMMIT();

    auto issueKV = [&](int k0, int st) {
        uint32_t base = smb + 16384 + st * 32768;
#pragma unroll
        for (int j = 0; j < 4; j++) {
            int idxq = tid + j * 128;
            int r = idxq >> 3, ch = idxq & 7;
            uint32_t off = (uint32_t)(r * 128 + ch * 16);
            off ^= (off >> 3) & 0x70;
            size_t src = (size_t)(b * T_ + k0 + r) * C_ + hh * 64 + ch * 8;
            CP16(base + off,         g_k_h + src);
            CP16(base + 8192 + off,  g_k_l + src);
            CP16(base + 16384 + off, g_v_h + src);
            CP16(base + 24576 + off, g_v_l + src);
        }
        CPCOMMIT();
    };

    int nt = q0 / 64 + 1;
    issueKV(0, 0);

    CPWAITG(1);
    __syncthreads();

    int arow0 = wid * 16 + (lane & 15);
    int akof  = (lane & 16);
    uint32_t qh[4][4], ql[4][4];
#pragma unroll
    for (int ks = 0; ks < 4; ks++) {
        uint32_t off = (uint32_t)(arow0 * 128 + ks * 32 + akof);
        off ^= (off >> 3) & 0x70;
        ldsm_x4(qh[ks], smb + off);
        ldsm_x4(ql[ks], smb + 8192 + off);
    }

    float4 oacc[8];
#pragma unroll
    for (int i = 0; i < 8; i++) oacc[i] = make_float4(0.f, 0.f, 0.f, 0.f);
    float mrow0 = -1e30f, mrow1 = -1e30f, lrow0 = 0.f, lrow1 = 0.f;

    for (int t = 0; t < nt; t++) {
        if (t + 1 < nt) { issueKV((t + 1) * 64, (t + 1) & 1); CPWAITG(1); }
        else            { CPWAITG(0); }
        __syncthreads();

        uint32_t kb = smb + 16384 + (t & 1) * 32768;

        float4 sacc[8];
#pragma unroll
        for (int i = 0; i < 8; i++) sacc[i] = make_float4(0.f, 0.f, 0.f, 0.f);
#pragma unroll
        for (int ks = 0; ks < 4; ks++) {
#pragma unroll
            for (int njp = 0; njp < 4; njp++) {
                uint32_t kh[4], kl[4];
                uint32_t off = (uint32_t)(((lane & 15) + njp * 16) * 128 + ks * 32 + akof);
                off ^= (off >> 3) & 0x70;
                ldsm_x4(kh, kb + off);
                ldsm_x4(kl, kb + 8192 + off);
                mma16816(sacc[2 * njp],     qh[ks], kh[0], kh[2]);
                mma16816(sacc[2 * njp + 1], qh[ks], kh[1], kh[3]);
                mma16816(sacc[2 * njp],     qh[ks], kl[0], kl[2]);
                mma16816(sacc[2 * njp + 1], qh[ks], kl[1], kl[3]);
                mma16816(sacc[2 * njp],     ql[ks], kh[0], kh[2]);
                mma16816(sacc[2 * njp + 1], ql[ks], kh[1], kh[3]);
            }
        }

        if (t == nt - 1) {
            int qiA = wid * 16 + g, qiB = qiA + 8;
#pragma unroll
            for (int nj = 0; nj < 8; nj++) {
                int ki = nj * 8 + t4 * 2;
                if (ki     > qiA) sacc[nj].x = -1e30f;
                if (ki + 1 > qiA) sacc[nj].y = -1e30f;
                if (ki     > qiB) sacc[nj].z = -1e30f;
                if (ki + 1 > qiB) sacc[nj].w = -1e30f;
            }
        }

        float mx0 = -1e30f, mx1 = -1e30f;
#pragma unroll
        for (int nj = 0; nj < 8; nj++) {
            mx0 = fmaxf(mx0, fmaxf(sacc[nj].x, sacc[nj].y));
            mx1 = fmaxf(mx1, fmaxf(sacc[nj].z, sacc[nj].w));
        }
        mx0 = fmaxf(mx0, __shfl_xor_sync(0xffffffffu, mx0, 1));
        mx0 = fmaxf(mx0, __shfl_xor_sync(0xffffffffu, mx0, 2));
        mx1 = fmaxf(mx1, __shfl_xor_sync(0xffffffffu, mx1, 1));
        mx1 = fmaxf(mx1, __shfl_xor_sync(0xffffffffu, mx1, 2));
        float mn0 = fmaxf(mrow0, mx0), mn1 = fmaxf(mrow1, mx1);
        float c0 = __expf(mrow0 - mn0), c1 = __expf(mrow1 - mn1);
        float sum0 = 0.f, sum1 = 0.f;
#pragma unroll
        for (int nj = 0; nj < 8; nj++) {
            sacc[nj].x = __expf(sacc[nj].x - mn0);
            sacc[nj].y = __expf(sacc[nj].y - mn0);
            sacc[nj].z = __expf(sacc[nj].z - mn1);
            sacc[nj].w = __expf(sacc[nj].w - mn1);
            sum0 += sacc[nj].x + sacc[nj].y;
            sum1 += sacc[nj].z + sacc[nj].w;
        }
        sum0 += __shfl_xor_sync(0xffffffffu, sum0, 1);
        sum0 += __shfl_xor_sync(0xffffffffu, sum0, 2);
        sum1 += __shfl_xor_sync(0xffffffffu, sum1, 1);
        sum1 += __shfl_xor_sync(0xffffffffu, sum1, 2);
        lrow0 = lrow0 * c0 + sum0;
        lrow1 = lrow1 * c1 + sum1;
        mrow0 = mn0; mrow1 = mn1;
#pragma unroll
        for (int nd = 0; nd < 8; nd++) {
            oacc[nd].x *= c0; oacc[nd].y *= c0;
            oacc[nd].z *= c1; oacc[nd].w *= c1;
        }

#pragma unroll
        for (int kk = 0; kk < 4; kk++) {
            uint32_t ah[4], al[4];
            splith2(sacc[2*kk].x,   sacc[2*kk].y,   ah[0], al[0]);
            splith2(sacc[2*kk].z,   sacc[2*kk].w,   ah[1], al[1]);
            splith2(sacc[2*kk+1].x, sacc[2*kk+1].y, ah[2], al[2]);
            splith2(sacc[2*kk+1].z, sacc[2*kk+1].w, ah[3], al[3]);
#pragma unroll
            for (int ndp = 0; ndp < 4; ndp++) {
                uint32_t vh[4], vl[4];
                uint32_t off = (uint32_t)((kk * 16 + (lane & 15)) * 128 + ndp * 32 + akof);
                off ^= (off >> 3) & 0x70;
                ldsm_x4t(vh, kb + 16384 + off);
                ldsm_x4t(vl, kb + 24576 + off);
                mma16816(oacc[2 * ndp],     ah, vh[0], vh[1]);
                mma16816(oacc[2 * ndp + 1], ah, vh[2], vh[3]);
                mma16816(oacc[2 * ndp],     ah, vl[0], vl[1]);
                mma16816(oacc[2 * ndp + 1], ah, vl[2], vl[3]);
                mma16816(oacc[2 * ndp],     al, vh[0], vh[1]);
                mma16816(oacc[2 * ndp + 1], al, vh[2], vh[3]);
            }
        }
        __syncthreads();
    }

    float inv0 = 1.0f / lrow0, inv1 = 1.0f / lrow1;
    int r0 = q0 + wid * 16 + g, r1 = r0 + 8;
    size_t b0 = (size_t)(b * T_ + r0) * C_ + hh * 64;
    size_t b1 = (size_t)(b * T_ + r1) * C_ + hh * 64;
#pragma unroll
    for (int nd = 0; nd < 8; nd++) {
        int d = nd * 8 + t4 * 2;
        uint32_t ph, pl;
        splith2(oacc[nd].x * inv0, oacc[nd].y * inv0, ph, pl);
        *reinterpret_cast<uint32_t*>(g_y_h + b0 + d) = ph;
        *reinterpret_cast<uint32_t*>(g_y_l + b0 + d) = pl;
        splith2(oacc[nd].z * inv1, oacc[nd].w * inv1, ph, pl);
        *reinterpret_cast<uint32_t*>(g_y_h + b1 + d) = ph;
        *reinterpret_cast<uint32_t*>(g_y_l + b1 + d) = pl;
    }
}

// ---------------- host orchestration ----------------
extern "C" void kernel_launch(void* const* d_in, const int* in_sizes, int n_in,
                              void* d_out, int out_size)
{
    (void)in_sizes; (void)n_in; (void)out_size;
    const int*   idx  = (const int*)  d_in[0];
    const float* cosp = (const float*)d_in[1];
    const float* sinp = (const float*)d_in[2];
    const float* wte  = (const float*)d_in[3];
    const float* vemb = (const float*)d_in[4];
    const float* wd   = (const float*)d_in[5];
    const float* wukv = (const float*)d_in[6];
    const float* wuq  = (const float*)d_in[7];
    const float* vg   = (const float*)d_in[8];
    const float* ap   = (const float*)d_in[9];
    const float* fc   = (const float*)d_in[10];
    const float* pj   = (const float*)d_in[11];
    const float* lr   = (const float*)d_in[12];
    const float* lx   = (const float*)d_in[13];
    const float* lmh  = (const float*)d_in[14];
    float* out = (float*)d_out;

    float *px, *pdown, *pkv, *pqpre;
    cudaGetSymbolAddress((void**)&px,    g_x);
    cudaGetSymbolAddress((void**)&pdown, g_down);
    cudaGetSymbolAddress((void**)&pkv,   g_kv);
    cudaGetSymbolAddress((void**)&pqpre, g_qpre);

    __half *wd_h, *wd_l, *wukv_h, *wukv_l, *wuq_h, *wuq_l, *ap_h, *ap_l;
    __half *fc_h, *fc_l, *pj_h, *pj_l, *lmh_h, *lmh_l;
    __half *xn_h, *xn_l, *dn_h, *dn_l, *y_h, *y_l, *h_h, *h_l;
    cudaGetSymbolAddress((void**)&wd_h,   g_wd_h);   cudaGetSymbolAddress((void**)&wd_l,   g_wd_l);
    cudaGetSymbolAddress((void**)&wukv_h, g_wukv_h); cudaGetSymbolAddress((void**)&wukv_l, g_wukv_l);
    cudaGetSymbolAddress((void**)&wuq_h,  g_wuq_h);  cudaGetSymbolAddress((void**)&wuq_l,  g_wuq_l);
    cudaGetSymbolAddress((void**)&ap_h,   g_ap_h);   cudaGetSymbolAddress((void**)&ap_l,   g_ap_l);
    cudaGetSymbolAddress((void**)&fc_h,   g_fc_h);   cudaGetSymbolAddress((void**)&fc_l,   g_fc_l);
    cudaGetSymbolAddress((void**)&pj_h,   g_pj_h);   cudaGetSymbolAddress((void**)&pj_l,   g_pj_l);
    cudaGetSymbolAddress((void**)&lmh_h,  g_lmh_h);  cudaGetSymbolAddress((void**)&lmh_l,  g_lmh_l);
    cudaGetSymbolAddress((void**)&xn_h,   g_xn_h);   cudaGetSymbolAddress((void**)&xn_l,   g_xn_l);
    cudaGetSymbolAddress((void**)&dn_h,   g_dn_h);   cudaGetSymbolAddress((void**)&dn_l,   g_dn_l);
    cudaGetSymbolAddress((void**)&y_h,    g_y_h);    cudaGetSymbolAddress((void**)&y_l,    g_y_l);
    cudaGetSymbolAddress((void**)&h_h,    g_h_h);    cudaGetSymbolAddress((void**)&h_l,    g_h_l);

    const int SM128 = 3 * (128 * 128 + 16384);   // 96 KB
    const int SM64  = 3 * (64 * 128 + 16384);    // 72 KB
    cudaFuncSetAttribute(gemm_h4<128>, cudaFuncAttributeMaxDynamicSharedMemorySize, SM128);
    cudaFuncSetAttribute(gemm_h4<64>,  cudaFuncAttributeMaxDynamicSharedMemorySize, SM64);
    const int ASM = 81920;
    cudaFuncSetAttribute(attn_mma, cudaFuncAttributeMaxDynamicSharedMemorySize, ASM);

    // ---- side streams + events (host resources; device work identical per call) ----
    static cudaStream_t sA = nullptr, sB = nullptr;
    static cudaEvent_t evFork = nullptr, evEarly = nullptr, evBig = nullptr,
                       evDown = nullptr, evQ = nullptr;
    if (!sA) {
        cudaStreamCreateWithFlags(&sA, cudaStreamNonBlocking);
        cudaStreamCreateWithFlags(&sB, cudaStreamNonBlocking);
        cudaEventCreateWithFlags(&evFork,  cudaEventDisableTiming);
        cudaEventCreateWithFlags(&evEarly, cudaEventDisableTiming);
        cudaEventCreateWithFlags(&evBig,   cudaEventDisableTiming);
        cudaEventCreateWithFlags(&evDown,  cudaEventDisableTiming);
        cudaEventCreateWithFlags(&evQ,     cudaEventDisableTiming);
    }

    const int GM1 = NTOK / 128;   // 16
    const int GM2 = NTOK / 64;    // 32

    // ---- fork ----
    cudaEventRecord(evFork, 0);
    cudaStreamWaitEvent(sA, evFork, 0);
    cudaStreamWaitEvent(sB, evFork, 0);

    // early splits on sA (needed by down/kv/qpre)
    wsplit_pad4<<<2048, 256, 0, sA>>>(wd, (uint2*)wd_h, (uint2*)wd_l, L_ * C_ * WDP / 4);
    wsplit16<<<(int)((long)L_ * DC_ * KVW / 16 / 256), 256, 0, sA>>>(
        (const float4*)wukv, (uint4*)wukv_h, (uint4*)wukv_l, (long)L_ * DC_ * KVW / 16);
    wsplit16<<<(int)((long)L_ * DC1_ * C_ / 16 / 256), 256, 0, sA>>>(
        (const float4*)wuq, (uint4*)wuq_h, (uint4*)wuq_l, (long)L_ * DC1_ * C_ / 16);
    cudaEventRecord(evEarly, sA);

    // big splits on sB (needed from layer-0 ap/fc/pj and lm_head)
    wsplit16<<<(int)((long)L_ * C_ * C_ / 16 / 256), 256, 0, sB>>>(
        (const float4*)ap, (uint4*)ap_h, (uint4*)ap_l, (long)L_ * C_ * C_ / 16);
    wsplit16<<<(int)((long)L_ * C_ * 4 * C_ / 16 / 256), 256, 0, sB>>>(
        (const float4*)fc, (uint4*)fc_h, (uint4*)fc_l, (long)L_ * C_ * 4 * C_ / 16);
    wsplit16<<<(int)((long)L_ * 4 * C_ * C_ / 16 / 256), 256, 0, sB>>>(
        (const float4*)pj, (uint4*)pj_h, (uint4*)pj_l, (long)L_ * 4 * C_ * C_ / 16);
    wsplit16<<<(int)((long)C_ * V_ / 16 / 256), 256, 0, sB>>>(
        (const float4*)lmh, (uint4*)lmh_h, (uint4*)lmh_l, (long)C_ * V_ / 16);
    cudaEventRecord(evBig, sB);

    // main stream: embed + mix_norm overlap the early splits
    embed_kernel<<<NTOK, 256>>>(idx, wte);
    mix_norm_kernel<<<NTOK, 256>>>(lr, lx, 0);
    cudaStreamWaitEvent(0, evEarly, 0);

    for (int l = 0; l < L_; l++) {
        if (l > 0) mix_norm_kernel<<<NTOK, 256>>>(lr, lx, l);

        // down: MT=64, grid 32x5 = 160
        gemm_h4<64><<<dim3(GM2, WDP / 128), 256, SM64>>>(
            xn_h, xn_l, wd_h + (size_t)l * C_ * WDP, wd_l + (size_t)l * C_ * WDP,
            pdown, nullptr, dn_h, dn_l,
            DOWNW, C_, C_, WDP, DOWNW, DOWNW, 0, 3);
        cudaEventRecord(evDown, 0);

        // qpre on sA (parallel with kv on main)
        cudaStreamWaitEvent(sA, evDown, 0);
        gemm_h4<64><<<dim3(GM2, C_ / 128), 256, SM64, sA>>>(
            dn_h + DC_, dn_l + DC_, wuq_h + (size_t)l * DC1_ * C_, wuq_l + (size_t)l * DC1_ * C_,
            pqpre, nullptr, nullptr, nullptr,
            C_, DC1_, DOWNW, C_, C_, 0, 0, 3);
        cudaEventRecord(evQ, sA);

        // kv on main: MT=128, grid 16x12 = 192
        gemm_h4<128><<<dim3(GM1, KVW / 128), 256, SM128>>>(
            dn_h, dn_l, wukv_h + (size_t)l * DC_ * KVW, wukv_l + (size_t)l * DC_ * KVW,
            pkv, nullptr, nullptr, nullptr,
            KVW, DC_, DOWNW, KVW, KVW, 0, 0, 3);
        cudaStreamWaitEvent(0, evQ, 0);

        build_qkv_kernel<<<NTOK, 512>>>(idx, cosp, sinp,
                                        vg + (size_t)l * 32 * H_,
                                        vemb + (size_t)l * V_ * C_);

        attn_mma<<<dim3(T_ / 64, H_, B_), 128, ASM>>>();

        if (l == 0) cudaStreamWaitEvent(0, evBig, 0);   // join big splits

        // ap: MT=64, grid 32x8 = 256
        gemm_h4<64><<<dim3(GM2, C_ / 128), 256, SM64>>>(
            y_h, y_l, ap_h + (size_t)l * C_ * C_, ap_l + (size_t)l * C_ * C_,
            px, px, nullptr, nullptr,
            C_, C_, C_, C_, C_, 0, 0, 3);

        mix_norm_kernel<<<NTOK, 256>>>(nullptr, nullptr, 0);

        // fc: MT=128, grid 16x32 = 512
        gemm_h4<128><<<dim3(GM1, 4 * C_ / 128), 256, SM128>>>(
            xn_h, xn_l, fc_h + (size_t)l * C_ * 4 * C_, fc_l + (size_t)l * C_ * 4 * C_,
            nullptr, nullptr, h_h, h_l,
            4 * C_, C_, C_, 4 * C_, 0, 4 * C_, 2, 3);

        // pj: MT=64, grid 32x8 = 256
        gemm_h4<64><<<dim3(GM2, C_ / 128), 256, SM64>>>(
            h_h, h_l, pj_h + (size_t)l * 4 * C_ * C_, pj_l + (size_t)l * 4 * C_ * C_,
            px, px, nullptr, nullptr,
            C_, 4 * C_, 4 * C_, C_, C_, 0, 0, 3);
    }

    mix_norm_kernel<<<NTOK, 256>>>(nullptr, nullptr, 0);
    // lm_head: MT=128, grid 16x250 = 4000, 2-term
    gemm_h4<128><<<dim3(GM1, V_ / 128), 256, SM128>>>(
        xn_h, xn_l, lmh_h, lmh_l,
        out, nullptr, nullptr, nullptr,
        V_, C_, C_, V_, V_, 0, 1, 2);
}

// round 14
// speedup vs baseline: 1.8123x; 1.0080x over previous
#include <cuda_runtime.h>
#include <cuda_fp16.h>
#include <math.h>
#include <stdint.h>

// ---------------- problem constants ----------------
#define B_    2
#define T_    1024
#define C_    1024
#define H_    16
#define HD_   64
#define DC_   256
#define DC1_  256
#define DR_   32
#define DN_   32
#define V_    32000
#define L_    4
#define NTOK  (B_*T_)             // 2048
#define DOWNW (DC_+DC1_+DR_)      // 544
#define WDP   640                 // padded wd output width
#define KVW   (H_*(DN_+HD_))      // 1536
#define EPS_  1.1920929e-07f

// ---------------- fp32 scratch ----------------
__device__ float g_x   [NTOK*C_];
__device__ float g_x0  [NTOK*C_];
__device__ float g_xn  [NTOK*C_];
__device__ float g_down[NTOK*DOWNW];
__device__ float g_kv  [NTOK*KVW];
__device__ float g_qpre[NTOK*C_];

// ---------------- fp16 hi/lo planes ----------------
__device__ __half g_wd_h  [L_*C_*WDP],    g_wd_l  [L_*C_*WDP];
__device__ __half g_wukv_h[L_*DC_*KVW],   g_wukv_l[L_*DC_*KVW];
__device__ __half g_wuq_h [L_*DC1_*C_],   g_wuq_l [L_*DC1_*C_];
__device__ __half g_ap_h  [L_*C_*C_],     g_ap_l  [L_*C_*C_];
__device__ __half g_fc_h  [L_*C_*4*C_],   g_fc_l  [L_*C_*4*C_];
__device__ __half g_pj_h  [L_*4*C_*C_],   g_pj_l  [L_*4*C_*C_];
__device__ __half g_lmh_h [C_*V_],        g_lmh_l [C_*V_];
__device__ __half g_xn_h  [NTOK*C_],      g_xn_l  [NTOK*C_];
__device__ __half g_dn_h  [NTOK*DOWNW],   g_dn_l  [NTOK*DOWNW];
__device__ __half g_y_h   [NTOK*C_],      g_y_l   [NTOK*C_];
__device__ __half g_h_h   [NTOK*4*C_],    g_h_l   [NTOK*4*C_];
__device__ __half g_q_h   [NTOK*C_],      g_q_l   [NTOK*C_];
__device__ __half g_k_h   [NTOK*C_],      g_k_l   [NTOK*C_];
__device__ __half g_v_h   [NTOK*C_],      g_v_l   [NTOK*C_];

// ---------------- helpers ----------------
__device__ __forceinline__ uint32_t smem_u32(const void* p) {
    uint32_t a;
    asm("{ .reg .u64 t; cvta.to.shared.u64 t, %1; cvt.u32.u64 %0, t; }" : "=r"(a) : "l"(p));
    return a;
}
__device__ __forceinline__ float warp_sum(float v) {
    v += __shfl_xor_sync(0xffffffffu, v, 16);
    v += __shfl_xor_sync(0xffffffffu, v, 8);
    v += __shfl_xor_sync(0xffffffffu, v, 4);
    v += __shfl_xor_sync(0xffffffffu, v, 2);
    v += __shfl_xor_sync(0xffffffffu, v, 1);
    return v;
}
__device__ __forceinline__ float block_sum(float v) {
    __shared__ float sh[32];
    int lane = threadIdx.x & 31, wid = threadIdx.x >> 5;
    v = warp_sum(v);
    if (lane == 0) sh[wid] = v;
    __syncthreads();
    int nw = blockDim.x >> 5;
    if (wid == 0) {
        float t = (lane < nw) ? sh[lane] : 0.f;
        t = warp_sum(t);
        if (lane == 0) sh[0] = t;
    }
    __syncthreads();
    return sh[0];
}
__device__ __forceinline__ void splith(float x, __half& hi, __half& lo) {
    hi = __float2half_rn(x);
    lo = __float2half_rn(x - __half2float(hi));
}
__device__ __forceinline__ uint32_t packh2(__half a, __half b) {
    return (uint32_t)__half_as_ushort(a) | ((uint32_t)__half_as_ushort(b) << 16);
}
__device__ __forceinline__ void splith2(float x, float y, uint32_t& hi, uint32_t& lo) {
    __half2 hh = __float22half2_rn(make_float2(x, y));
    float2 back = __half22float2(hh);
    __half2 ll = __float22half2_rn(make_float2(x - back.x, y - back.y));
    hi = *reinterpret_cast<uint32_t*>(&hh);
    lo = *reinterpret_cast<uint32_t*>(&ll);
}

// ---------------- mma / ldmatrix / cp.async wrappers ----------------
__device__ __forceinline__ void ldsm_x4(uint32_t* r, uint32_t addr) {
    asm volatile("ldmatrix.sync.aligned.m8n8.x4.shared.b16 {%0,%1,%2,%3}, [%4];"
                 : "=r"(r[0]), "=r"(r[1]), "=r"(r[2]), "=r"(r[3]) : "r"(addr));
}
__device__ __forceinline__ void ldsm_x4t(uint32_t* r, uint32_t addr) {
    asm volatile("ldmatrix.sync.aligned.m8n8.x4.trans.shared.b16 {%0,%1,%2,%3}, [%4];"
                 : "=r"(r[0]), "=r"(r[1]), "=r"(r[2]), "=r"(r[3]) : "r"(addr));
}
__device__ __forceinline__ void mma16816(float4& d, const uint32_t* a, uint32_t b0, uint32_t b1) {
    asm volatile(
        "mma.sync.aligned.m16n8k16.row.col.f32.f16.f16.f32 "
        "{%0,%1,%2,%3},{%4,%5,%6,%7},{%8,%9},{%0,%1,%2,%3};"
        : "+f"(d.x), "+f"(d.y), "+f"(d.z), "+f"(d.w)
        : "r"(a[0]), "r"(a[1]), "r"(a[2]), "r"(a[3]), "r"(b0), "r"(b1));
}
#define CP16(dst, src) \
    asm volatile("cp.async.cg.shared.global [%0], [%1], 16;" :: "r"(dst), "l"(src) : "memory")
#define CPCOMMIT() asm volatile("cp.async.commit_group;" ::: "memory")
#define CPWAITG(n) asm volatile("cp.async.wait_group " #n ";" ::: "memory")

// ---------------- split: 16 floats/thread, exact grid ----------------
__global__ void wsplit16(const float4* __restrict__ src,
                         uint4* __restrict__ hi, uint4* __restrict__ lo, long n16)
{
    long i = (long)blockIdx.x * blockDim.x + threadIdx.x;
    if (i >= n16) return;
    float4 f0 = src[4 * i];
    float4 f1 = src[4 * i + 1];
    float4 f2 = src[4 * i + 2];
    float4 f3 = src[4 * i + 3];
    uint4 h0, l0, h1, l1;
    splith2(f0.x, f0.y, h0.x, l0.x); splith2(f0.z, f0.w, h0.y, l0.y);
    splith2(f1.x, f1.y, h0.z, l0.z); splith2(f1.z, f1.w, h0.w, l0.w);
    splith2(f2.x, f2.y, h1.x, l1.x); splith2(f2.z, f2.w, h1.y, l1.y);
    splith2(f3.x, f3.y, h1.z, l1.z); splith2(f3.z, f3.w, h1.w, l1.w);
    hi[2 * i] = h0; hi[2 * i + 1] = h1;
    lo[2 * i] = l0; lo[2 * i + 1] = l1;
}

// ---------------- padded split, vectorized (wd only) --------------------
__global__ void wsplit_pad4(const float* __restrict__ src,
                            uint2* __restrict__ hi, uint2* __restrict__ lo, int n4)
{
    int stride = gridDim.x * blockDim.x;
    for (int i = blockIdx.x * blockDim.x + threadIdx.x; i < n4; i += stride) {
        int row = i / (WDP / 4);
        int c4  = i - row * (WDP / 4);
        float4 f = make_float4(0.f, 0.f, 0.f, 0.f);
        if (c4 < DOWNW / 4)
            f = *reinterpret_cast<const float4*>(src + (size_t)row * DOWNW + c4 * 4);
        uint2 h, l;
        splith2(f.x, f.y, h.x, l.x);
        splith2(f.z, f.w, h.y, l.y);
        hi[i] = h; lo[i] = l;
    }
}

// ---------------- embedding + rmsnorm ----------------
__global__ void embed_kernel(const int* __restrict__ idx, const float* __restrict__ wte) {
    int row = blockIdx.x;
    int tok = idx[row];
    const float* src = wte + (size_t)tok * C_;
    float s = 0.f;
    for (int i = threadIdx.x; i < C_; i += blockDim.x) { float v = src[i]; s += v * v; }
    s = block_sum(s);
    float r = rsqrtf(s * (1.0f / C_) + EPS_);
    for (int i = threadIdx.x; i < C_; i += blockDim.x) {
        float v = src[i] * r;
        g_x [(size_t)row * C_ + i] = v;
        g_x0[(size_t)row * C_ + i] = v;
    }
}

__global__ void mix_norm_kernel(const float* lr, const float* lx, int layer) {
    int row = blockIdx.x;
    float a = lr ? lr[layer] : 1.0f;
    float b = lx ? lx[layer] : 0.0f;
    float*       xr  = g_x  + (size_t)row * C_;
    const float* x0r = g_x0 + (size_t)row * C_;
    float s = 0.f;
    for (int i = threadIdx.x; i < C_; i += blockDim.x) {
        float v = a * xr[i] + b * x0r[i];
        xr[i] = v;
        s += v * v;
    }
    s = block_sum(s);
    float r = rsqrtf(s * (1.0f / C_) + EPS_);
    for (int i = threadIdx.x; i < C_; i += blockDim.x) {
        float v = xr[i] * r;
        g_xn[(size_t)row * C_ + i] = v;
        __half h, l;
        splith(v, h, l);
        g_xn_h[(size_t)row * C_ + i] = h;
        g_xn_l[(size_t)row * C_ + i] = l;
    }
}

// ---------------- 3xFP16 tensor-core GEMM v6 (templated M-tile) ----------
template<int MT>
__global__ __launch_bounds__(256, 2) void gemm_h4(
    const __half* __restrict__ Ah, const __half* __restrict__ Al,
    const __half* __restrict__ Bh, const __half* __restrict__ Bl,
    float* __restrict__ C, const float* __restrict__ D,
    __half* __restrict__ Chi, __half* __restrict__ Clo,
    int N, int K, int lda, int ldb, int ldc, int ldp, int mode, int nterms)
{
    constexpr int MI  = MT / 32;
    constexpr int APB = MT * 128;
    constexpr int STG = APB + 16384;

    extern __shared__ __align__(1024) char sm[];
    int tid = threadIdx.x;
    int wid = tid >> 5, lane = tid & 31;
    int warp_m = wid >> 2, warp_n = wid & 3;
    int m0 = blockIdx.x * MT, n0 = blockIdx.y * 128;
    uint32_t smb = smem_u32(sm);

    float4 acc[MI][4];
#pragma unroll
    for (int i = 0; i < MI; i++)
#pragma unroll
        for (int j = 0; j < 4; j++) acc[i][j] = make_float4(0.f, 0.f, 0.f, 0.f);

    int a_m   = tid >> 3;
    int a_hl  = (tid >> 2) & 1;
    int a_j   = tid & 3;
    int b_k0  = tid >> 4;
    int b_j   = tid & 15;
    const __half* Asel = a_hl ? Al : Ah;

    int arow0 = warp_m * (MT / 2) + (lane & 15);
    int akof  = (lane & 16);
    int bkr   = (lane & 15);
    int bco   = warp_n * 64 + ((lane >> 4) << 4);
    int ksrot = wid & 1;

    int nk = K >> 5;

    auto issue = [&](int kt, int stg) {
        uint32_t sA = smb + stg * STG;
        uint32_t sB = sA + APB;
#pragma unroll
        for (int r = 0; r < MT / 32; r++) {
            int m = a_m + r * 32;
            uint32_t off = (uint32_t)(m * 128 + a_hl * 64 + a_j * 16);
            off ^= (off >> 3) & 0x70;
            const __half* src = Asel + (size_t)(m0 + m) * lda + kt * 32 + a_j * 8;
            CP16(sA + off, src);
        }
#pragma unroll
        for (int r = 0; r < 4; r++) {
            int k = b_k0 + (r & 1) * 16;
            const __half* Bp = (r < 2) ? Bh : Bl;
            uint32_t off = ((uint32_t)(k * 256 + b_j * 16)) ^ ((uint32_t)(k & 7) << 4);
            off += (r < 2) ? 0u : 8192u;
            const __half* src = Bp + (size_t)(kt * 32 + k) * ldb + n0 + b_j * 8;
            CP16(sB + off, src);
        }
        CPCOMMIT();
    };

    issue(0, 0);
    issue(1, 1);

    for (int kt = 0; kt < nk; kt++) {
        if (kt == nk - 1) { CPWAITG(0); } else { CPWAITG(1); }
        __syncthreads();
        if (kt + 2 < nk) issue(kt + 2, (kt + 2) % 3);

        int s = kt % 3;
        uint32_t sA  = smb + s * STG;
        uint32_t sBh = sA + APB;
        uint32_t sBl = sBh + 8192;
#pragma unroll
        for (int ks0 = 0; ks0 < 2; ks0++) {
            int ks = ks0 ^ ksrot;
            uint32_t af[MI][4], bh[2][4], bl[2][4];
#pragma unroll
            for (int mi = 0; mi < MI; mi++) {
                uint32_t oh = (uint32_t)((arow0 + mi * 16) * 128 + ks * 32 + akof);
                oh ^= (oh >> 3) & 0x70;
                ldsm_x4(af[mi], sA + oh);
            }
#pragma unroll
            for (int nj = 0; nj < 2; nj++) {
                int krow = ks * 16 + bkr;
                uint32_t off = (uint32_t)(krow * 256 + bco + nj * 32) ^ ((uint32_t)(krow & 7) << 4);
                ldsm_x4t(bh[nj], sBh + off);
                ldsm_x4t(bl[nj], sBl + off);
            }
#pragma unroll
            for (int mi = 0; mi < MI; mi++)
#pragma unroll
                for (int ni = 0; ni < 4; ni++)
                    mma16816(acc[mi][ni], af[mi], bh[ni >> 1][(ni & 1) * 2], bh[ni >> 1][(ni & 1) * 2 + 1]);
#pragma unroll
            for (int mi = 0; mi < MI; mi++)
#pragma unroll
                for (int ni = 0; ni < 4; ni++)
                    mma16816(acc[mi][ni], af[mi], bl[ni >> 1][(ni & 1) * 2], bl[ni >> 1][(ni & 1) * 2 + 1]);
            if (nterms == 3) {
#pragma unroll
                for (int mi = 0; mi < MI; mi++) {
                    uint32_t ol = (uint32_t)((arow0 + mi * 16) * 128 + ks * 32 + akof + 64);
                    ol ^= (ol >> 3) & 0x70;
                    ldsm_x4(af[mi], sA + ol);
                }
#pragma unroll
                for (int mi = 0; mi < MI; mi++)
#pragma unroll
                    for (int ni = 0; ni < 4; ni++)
                        mma16816(acc[mi][ni], af[mi], bh[ni >> 1][(ni & 1) * 2], bh[ni >> 1][(ni & 1) * 2 + 1]);
            }
        }
    }

    int g = lane >> 2, t4 = lane & 3;
#pragma unroll
    for (int mi = 0; mi < MI; mi++) {
        int r0 = m0 + warp_m * (MT / 2) + mi * 16 + g;
#pragma unroll
        for (int ni = 0; ni < 4; ni++) {
            int col = n0 + warp_n * 32 + ni * 8 + 2 * t4;
            if (col >= N) continue;
            float4 v = acc[mi][ni];
            if (D) {
                float2 d0 = *reinterpret_cast<const float2*>(D + (size_t)r0 * ldc + col);
                float2 d1 = *reinterpret_cast<const float2*>(D + (size_t)(r0 + 8) * ldc + col);
                v.x += d0.x; v.y += d0.y; v.z += d1.x; v.w += d1.y;
            }
            if (mode == 1) {
                v.x = 15.0f * tanhf(v.x * (1.f / 15.f));
                v.y = 15.0f * tanhf(v.y * (1.f / 15.f));
                v.z = 15.0f * tanhf(v.z * (1.f / 15.f));
                v.w = 15.0f * tanhf(v.w * (1.f / 15.f));
            } else if (mode == 2) {
                v.x = (v.x > 0.f) ? v.x * v.x : 0.f;
                v.y = (v.y > 0.f) ? v.y * v.y : 0.f;
                v.z = (v.z > 0.f) ? v.z * v.z : 0.f;
                v.w = (v.w > 0.f) ? v.w * v.w : 0.f;
            }
            if (C) {
                *reinterpret_cast<float2*>(C + (size_t)r0 * ldc + col) = make_float2(v.x, v.y);
                *reinterpret_cast<float2*>(C + (size_t)(r0 + 8) * ldc + col) = make_float2(v.z, v.w);
            }
            if (Chi) {
                uint32_t ph0, pl0, ph1, pl1;
                splith2(v.x, v.y, ph0, pl0);
                splith2(v.z, v.w, ph1, pl1);
                *reinterpret_cast<uint32_t*>(Chi + (size_t)r0 * ldp + col)       = ph0;
                *reinterpret_cast<uint32_t*>(Clo + (size_t)r0 * ldp + col)       = pl0;
                *reinterpret_cast<uint32_t*>(Chi + (size_t)(r0 + 8) * ldp + col) = ph1;
                *reinterpret_cast<uint32_t*>(Clo + (size_t)(r0 + 8) * ldp + col) = pl1;
            }
        }
    }
}

// ---------------- per-token q/k/v build -> fp16 hi/lo planes --------------
__global__ void build_qkv_kernel(const int* __restrict__ idx,
                                 const float* __restrict__ cosp, const float* __restrict__ sinp,
                                 const float* __restrict__ vg, const float* __restrict__ vetab)
{
    int row = blockIdx.x;
    int h    = threadIdx.x >> 5;
    int lane = threadIdx.x & 31;
    const float* cosr = cosp + (size_t)row * (DR_ / 2);
    const float* sinr = sinp + (size_t)row * (DR_ / 2);

    float gv = g_xn[(size_t)row * C_ + lane] * vg[lane * H_ + h];
    gv = warp_sum(gv);
    float gate = 2.0f / (1.0f + __expf(-gv));

    int r16 = (lane < 16) ? lane : lane - 16;
    float c = cosr[r16], s = sinr[r16];
    size_t base = (size_t)row * C_ + h * 64;

    float kn = g_kv[(size_t)row * KVW + h * 96 + lane];
    const float* dro = g_down + (size_t)row * DOWNW + 512;
    float kr = (lane < 16) ? (dro[lane] * c + dro[lane + 16] * s)
                           : (-dro[lane - 16] * s + dro[lane] * c);
    float ssk = warp_sum(kn * kn + kr * kr);
    float rk = rsqrtf(ssk * (1.0f / 64.0f) + EPS_);
    __half hh_, ll_;
    splith(kn * rk, hh_, ll_);  g_k_h[base + lane]      = hh_; g_k_l[base + lane]      = ll_;
    splith(kr * rk, hh_, ll_);  g_k_h[base + lane + 32] = hh_; g_k_l[base + lane + 32] = ll_;

    const float* qp = g_qpre + (size_t)row * C_ + h * 64;
    float qn = qp[lane];
    float qr = (lane < 16) ? (qp[32 + lane] * c + qp[48 + lane] * s)
                           : (-qp[16 + lane] * s + qp[32 + lane] * c);
    float ssq = warp_sum(qn * qn + qr * qr);
    float rq = rsqrtf(ssq * (1.0f / 64.0f) + EPS_) * 0.125f;
    splith(qn * rq, hh_, ll_);  g_q_h[base + lane]      = hh_; g_q_l[base + lane]      = ll_;
    splith(qr * rq, hh_, ll_);  g_q_h[base + lane + 32] = hh_; g_q_l[base + lane + 32] = ll_;

    int tok = idx[row];
    const float* ver = vetab + (size_t)tok * C_ + h * 64;
    const float* kvv = g_kv + (size_t)row * KVW + h * 96 + 32;
    splith(kvv[lane]      + gate * ver[lane],      hh_, ll_);
    g_v_h[base + lane]      = hh_; g_v_l[base + lane]      = ll_;
    splith(kvv[lane + 32] + gate * ver[lane + 32], hh_, ll_);
    g_v_h[base + lane + 32] = hh_; g_v_l[base + lane + 32] = ll_;
}

// ---------------- tensor-core causal flash attention (double-buffered) ----
__global__ __launch_bounds__(128) void attn_mma()
{
    extern __shared__ __align__(1024) char dsm[];
    uint32_t smb = smem_u32(dsm);
    int tid = threadIdx.x;
    int wid = tid >> 5, lane = tid & 31;
    int q0 = (gridDim.x - 1 - blockIdx.x) * 64;
    int hh = blockIdx.y;
    int b  = blockIdx.z;
    int t4 = lane & 3, g = lane >> 2;

#pragma unroll
    for (int j = 0; j < 4; j++) {
        int idxq = tid + j * 128;
        int r = idxq >> 3, ch = idxq & 7;
        uint32_t off = (uint32_t)(r * 128 + ch * 16);
        off ^= (off >> 3) & 0x70;
        size_t src = (size_t)(b * T_ + q0 + r) * C_ + hh * 64 + ch * 8;
        CP16(smb + off,        g_q_h + src);
        CP16(smb + 8192 + off, g_q_l + src);
    }
    CPCOMMIT();

    auto issueKV = [&](int k0, int st) {
        uint32_t base = smb + 16384 + st * 32768;
#pragma unroll
        for (int j = 0; j < 4; j++) {
            int idxq = tid + j * 128;
            int r = idxq >> 3, ch = idxq & 7;
            uint32_t off = (uint32_t)(r * 128 + ch * 16);
            off ^= (off >> 3) & 0x70;
            size_t src = (size_t)(b * T_ + k0 + r) * C_ + hh * 64 + ch * 8;
            CP16(base + off,         g_k_h + src);
            CP16(base + 8192 + off,  g_k_l + src);
            CP16(base + 16384 + off, g_v_h + src);
            CP16(base + 24576 + off, g_v_l + src);
        }
        CPCOMMIT();
    };

    int nt = q0 / 64 + 1;
    issueKV(0, 0);

    CPWAITG(1);
    __syncthreads();

    int arow0 = wid * 16 + (lane & 15);
    int akof  = (lane & 16);
    uint32_t qh[4][4], ql[4][4];
#pragma unroll
    for (int ks = 0; ks < 4; ks++) {
        uint32_t off = (uint32_t)(arow0 * 128 + ks * 32 + akof);
        off ^= (off >> 3) & 0x70;
        ldsm_x4(qh[ks], smb + off);
        ldsm_x4(ql[ks], smb + 8192 + off);
    }

    float4 oacc[8];
#pragma unroll
    for (int i = 0; i < 8; i++) oacc[i] = make_float4(0.f, 0.f, 0.f, 0.f);
    float mrow0 = -1e30f, mrow1 = -1e30f, lrow0 = 0.f, lrow1 = 0.f;

    for (int t = 0; t < nt; t++) {
        if (t + 1 < nt) { issueKV((t + 1) * 64, (t + 1) & 1); CPWAITG(1); }
        else            { CPWAITG(0); }
        __syncthreads();

        uint32_t kb = smb + 16384 + (t & 1) * 32768;

        float4 sacc[8];
#pragma unroll
        for (int i = 0; i < 8; i++) sacc[i] = make_float4(0.f, 0.f, 0.f, 0.f);
#pragma unroll
        for (int ks = 0; ks < 4; ks++) {
#pragma unroll
            for (int njp = 0; njp < 4; njp++) {
                uint32_t kh[4], kl[4];
                uint32_t off = (uint32_t)(((lane & 15) + njp * 16) * 128 + ks * 32 + akof);
                off ^= (off >> 3) & 0x70;
                ldsm_x4(kh, kb + off);
                ldsm_x4(kl, kb + 8192 + off);
                mma16816(sacc[2 * njp],     qh[ks], kh[0], kh[2]);
                mma16816(sacc[2 * njp + 1], qh[ks], kh[1], kh[3]);
                mma16816(sacc[2 * njp],     qh[ks], kl[0], kl[2]);
                mma16816(sacc[2 * njp + 1], qh[ks], kl[1], kl[3]);
                mma16816(sacc[2 * njp],     ql[ks], kh[0], kh[2]);
                mma16816(sacc[2 * njp + 1], ql[ks], kh[1], kh[3]);
            }
        }

        if (t == nt - 1) {
            int qiA = wid * 16 + g, qiB = qiA + 8;
#pragma unroll
            for (int nj = 0; nj < 8; nj++) {
                int ki = nj * 8 + t4 * 2;
                if (ki     > qiA) sacc[nj].x = -1e30f;
                if (ki + 1 > qiA) sacc[nj].y = -1e30f;
                if (ki     > qiB) sacc[nj].z = -1e30f;
                if (ki + 1 > qiB) sacc[nj].w = -1e30f;
            }
        }

        float mx0 = -1e30f, mx1 = -1e30f;
#pragma unroll
        for (int nj = 0; nj < 8; nj++) {
            mx0 = fmaxf(mx0, fmaxf(sacc[nj].x, sacc[nj].y));
            mx1 = fmaxf(mx1, fmaxf(sacc[nj].z, sacc[nj].w));
        }
        mx0 = fmaxf(mx0, __shfl_xor_sync(0xffffffffu, mx0, 1));
        mx0 = fmaxf(mx0, __shfl_xor_sync(0xffffffffu, mx0, 2));
        mx1 = fmaxf(mx1, __shfl_xor_sync(0xffffffffu, mx1, 1));
        mx1 = fmaxf(mx1, __shfl_xor_sync(0xffffffffu, mx1, 2));
        float mn0 = fmaxf(mrow0, mx0), mn1 = fmaxf(mrow1, mx1);
        float c0 = __expf(mrow0 - mn0), c1 = __expf(mrow1 - mn1);
        float sum0 = 0.f, sum1 = 0.f;
#pragma unroll
        for (int nj = 0; nj < 8; nj++) {
            sacc[nj].x = __expf(sacc[nj].x - mn0);
            sacc[nj].y = __expf(sacc[nj].y - mn0);
            sacc[nj].z = __expf(sacc[nj].z - mn1);
            sacc[nj].w = __expf(sacc[nj].w - mn1);
            sum0 += sacc[nj].x + sacc[nj].y;
            sum1 += sacc[nj].z + sacc[nj].w;
        }
        sum0 += __shfl_xor_sync(0xffffffffu, sum0, 1);
        sum0 += __shfl_xor_sync(0xffffffffu, sum0, 2);
        sum1 += __shfl_xor_sync(0xffffffffu, sum1, 1);
        sum1 += __shfl_xor_sync(0xffffffffu, sum1, 2);
        lrow0 = lrow0 * c0 + sum0;
        lrow1 = lrow1 * c1 + sum1;
        mrow0 = mn0; mrow1 = mn1;
#pragma unroll
        for (int nd = 0; nd < 8; nd++) {
            oacc[nd].x *= c0; oacc[nd].y *= c0;
            oacc[nd].z *= c1; oacc[nd].w *= c1;
        }

#pragma unroll
        for (int kk = 0; kk < 4; kk++) {
            uint32_t ah[4], al[4];
            splith2(sacc[2*kk].x,   sacc[2*kk].y,   ah[0], al[0]);
            splith2(sacc[2*kk].z,   sacc[2*kk].w,   ah[1], al[1]);
            splith2(sacc[2*kk+1].x, sacc[2*kk+1].y, ah[2], al[2]);
            splith2(sacc[2*kk+1].z, sacc[2*kk+1].w, ah[3], al[3]);
#pragma unroll
            for (int ndp = 0; ndp < 4; ndp++) {
                uint32_t vh[4], vl[4];
                uint32_t off = (uint32_t)((kk * 16 + (lane & 15)) * 128 + ndp * 32 + akof);
                off ^= (off >> 3) & 0x70;
                ldsm_x4t(vh, kb + 16384 + off);
                ldsm_x4t(vl, kb + 24576 + off);
                mma16816(oacc[2 * ndp],     ah, vh[0], vh[1]);
                mma16816(oacc[2 * ndp + 1], ah, vh[2], vh[3]);
                mma16816(oacc[2 * ndp],     ah, vl[0], vl[1]);
                mma16816(oacc[2 * ndp + 1], ah, vl[2], vl[3]);
                mma16816(oacc[2 * ndp],     al, vh[0], vh[1]);
                mma16816(oacc[2 * ndp + 1], al, vh[2], vh[3]);
            }
        }
        __syncthreads();
    }

    float inv0 = 1.0f / lrow0, inv1 = 1.0f / lrow1;
    int r0 = q0 + wid * 16 + g, r1 = r0 + 8;
    size_t b0 = (size_t)(b * T_ + r0) * C_ + hh * 64;
    size_t b1 = (size_t)(b * T_ + r1) * C_ + hh * 64;
#pragma unroll
    for (int nd = 0; nd < 8; nd++) {
        int d = nd * 8 + t4 * 2;
        uint32_t ph, pl;
        splith2(oacc[nd].x * inv0, oacc[nd].y * inv0, ph, pl);
        *reinterpret_cast<uint32_t*>(g_y_h + b0 + d) = ph;
        *reinterpret_cast<uint32_t*>(g_y_l + b0 + d) = pl;
        splith2(oacc[nd].z * inv1, oacc[nd].w * inv1, ph, pl);
        *reinterpret_cast<uint32_t*>(g_y_h + b1 + d) = ph;
        *reinterpret_cast<uint32_t*>(g_y_l + b1 + d) = pl;
    }
}

// ---------------- host orchestration ----------------
extern "C" void kernel_launch(void* const* d_in, const int* in_sizes, int n_in,
                              void* d_out, int out_size)
{
    (void)in_sizes; (void)n_in; (void)out_size;
    const int*   idx  = (const int*)  d_in[0];
    const float* cosp = (const float*)d_in[1];
    const float* sinp = (const float*)d_in[2];
    const float* wte  = (const float*)d_in[3];
    const float* vemb = (const float*)d_in[4];
    const float* wd   = (const float*)d_in[5];
    const float* wukv = (const float*)d_in[6];
    const float* wuq  = (const float*)d_in[7];
    const float* vg   = (const float*)d_in[8];
    const float* ap   = (const float*)d_in[9];
    const float* fc   = (const float*)d_in[10];
    const float* pj   = (const float*)d_in[11];
    const float* lr   = (const float*)d_in[12];
    const float* lx   = (const float*)d_in[13];
    const float* lmh  = (const float*)d_in[14];
    float* out = (float*)d_out;

    float *px, *pdown, *pkv, *pqpre;
    cudaGetSymbolAddress((void**)&px,    g_x);
    cudaGetSymbolAddress((void**)&pdown, g_down);
    cudaGetSymbolAddress((void**)&pkv,   g_kv);
    cudaGetSymbolAddress((void**)&pqpre, g_qpre);

    __half *wd_h, *wd_l, *wukv_h, *wukv_l, *wuq_h, *wuq_l, *ap_h, *ap_l;
    __half *fc_h, *fc_l, *pj_h, *pj_l, *lmh_h, *lmh_l;
    __half *xn_h, *xn_l, *dn_h, *dn_l, *y_h, *y_l, *h_h, *h_l;
    cudaGetSymbolAddress((void**)&wd_h,   g_wd_h);   cudaGetSymbolAddress((void**)&wd_l,   g_wd_l);
    cudaGetSymbolAddress((void**)&wukv_h, g_wukv_h); cudaGetSymbolAddress((void**)&wukv_l, g_wukv_l);
    cudaGetSymbolAddress((void**)&wuq_h,  g_wuq_h);  cudaGetSymbolAddress((void**)&wuq_l,  g_wuq_l);
    cudaGetSymbolAddress((void**)&ap_h,   g_ap_h);   cudaGetSymbolAddress((void**)&ap_l,   g_ap_l);
    cudaGetSymbolAddress((void**)&fc_h,   g_fc_h);   cudaGetSymbolAddress((void**)&fc_l,   g_fc_l);
    cudaGetSymbolAddress((void**)&pj_h,   g_pj_h);   cudaGetSymbolAddress((void**)&pj_l,   g_pj_l);
    cudaGetSymbolAddress((void**)&lmh_h,  g_lmh_h);  cudaGetSymbolAddress((void**)&lmh_l,  g_lmh_l);
    cudaGetSymbolAddress((void**)&xn_h,   g_xn_h);   cudaGetSymbolAddress((void**)&xn_l,   g_xn_l);
    cudaGetSymbolAddress((void**)&dn_h,   g_dn_h);   cudaGetSymbolAddress((void**)&dn_l,   g_dn_l);
    cudaGetSymbolAddress((void**)&y_h,    g_y_h);    cudaGetSymbolAddress((void**)&y_l,    g_y_l);
    cudaGetSymbolAddress((void**)&h_h,    g_h_h);    cudaGetSymbolAddress((void**)&h_l,    g_h_l);

    const int SM128 = 3 * (128 * 128 + 16384);   // 96 KB
    const int SM64  = 3 * (64 * 128 + 16384);    // 72 KB
    cudaFuncSetAttribute(gemm_h4<128>, cudaFuncAttributeMaxDynamicSharedMemorySize, SM128);
    cudaFuncSetAttribute(gemm_h4<64>,  cudaFuncAttributeMaxDynamicSharedMemorySize, SM64);
    const int ASM = 81920;
    cudaFuncSetAttribute(attn_mma, cudaFuncAttributeMaxDynamicSharedMemorySize, ASM);

    // ---- side streams + events (host resources; device work identical per call) ----
    static cudaStream_t sA = nullptr, sB = nullptr;
    static cudaEvent_t evFork = nullptr, evEarly = nullptr, evBig = nullptr,
                       evDown = nullptr, evQ = nullptr;
    if (!sA) {
        cudaStreamCreateWithFlags(&sA, cudaStreamNonBlocking);
        cudaStreamCreateWithFlags(&sB, cudaStreamNonBlocking);
        cudaEventCreateWithFlags(&evFork,  cudaEventDisableTiming);
        cudaEventCreateWithFlags(&evEarly, cudaEventDisableTiming);
        cudaEventCreateWithFlags(&evBig,   cudaEventDisableTiming);
        cudaEventCreateWithFlags(&evDown,  cudaEventDisableTiming);
        cudaEventCreateWithFlags(&evQ,     cudaEventDisableTiming);
    }

    const int GM1 = NTOK / 128;   // 16
    const int GM2 = NTOK / 64;    // 32

    // ---- fork ----
    cudaEventRecord(evFork, 0);
    cudaStreamWaitEvent(sA, evFork, 0);
    cudaStreamWaitEvent(sB, evFork, 0);

    // early splits on sA (needed by down/kv/qpre)
    wsplit_pad4<<<2048, 256, 0, sA>>>(wd, (uint2*)wd_h, (uint2*)wd_l, L_ * C_ * WDP / 4);
    wsplit16<<<(int)((long)L_ * DC_ * KVW / 16 / 256), 256, 0, sA>>>(
        (const float4*)wukv, (uint4*)wukv_h, (uint4*)wukv_l, (long)L_ * DC_ * KVW / 16);
    wsplit16<<<(int)((long)L_ * DC1_ * C_ / 16 / 256), 256, 0, sA>>>(
        (const float4*)wuq, (uint4*)wuq_h, (uint4*)wuq_l, (long)L_ * DC1_ * C_ / 16);
    cudaEventRecord(evEarly, sA);

    // big splits on sB (needed from layer-0 ap/fc/pj and lm_head)
    wsplit16<<<(int)((long)L_ * C_ * C_ / 16 / 256), 256, 0, sB>>>(
        (const float4*)ap, (uint4*)ap_h, (uint4*)ap_l, (long)L_ * C_ * C_ / 16);
    wsplit16<<<(int)((long)L_ * C_ * 4 * C_ / 16 / 256), 256, 0, sB>>>(
        (const float4*)fc, (uint4*)fc_h, (uint4*)fc_l, (long)L_ * C_ * 4 * C_ / 16);
    wsplit16<<<(int)((long)L_ * 4 * C_ * C_ / 16 / 256), 256, 0, sB>>>(
        (const float4*)pj, (uint4*)pj_h, (uint4*)pj_l, (long)L_ * 4 * C_ * C_ / 16);
    wsplit16<<<(int)((long)C_ * V_ / 16 / 256), 256, 0, sB>>>(
        (const float4*)lmh, (uint4*)lmh_h, (uint4*)lmh_l, (long)C_ * V_ / 16);
    cudaEventRecord(evBig, sB);

    // main stream: embed + mix_norm overlap the early splits
    embed_kernel<<<NTOK, 256>>>(idx, wte);
    mix_norm_kernel<<<NTOK, 256>>>(lr, lx, 0);
    cudaStreamWaitEvent(0, evEarly, 0);

    for (int l = 0; l < L_; l++) {
        if (l > 0) mix_norm_kernel<<<NTOK, 256>>>(lr, lx, l);

        // down: MT=64, grid 32x5 = 160
        gemm_h4<64><<<dim3(GM2, WDP / 128), 256, SM64>>>(
            xn_h, xn_l, wd_h + (size_t)l * C_ * WDP, wd_l + (size_t)l * C_ * WDP,
            pdown, nullptr, dn_h, dn_l,
            DOWNW, C_, C_, WDP, DOWNW, DOWNW, 0, 3);
        cudaEventRecord(evDown, 0);

        // qpre on sA (parallel with kv on main)
        cudaStreamWaitEvent(sA, evDown, 0);
        gemm_h4<64><<<dim3(GM2, C_ / 128), 256, SM64, sA>>>(
            dn_h + DC_, dn_l + DC_, wuq_h + (size_t)l * DC1_ * C_, wuq_l + (size_t)l * DC1_ * C_,
            pqpre, nullptr, nullptr, nullptr,
            C_, DC1_, DOWNW, C_, C_, 0, 0, 3);
        cudaEventRecord(evQ, sA);

        // kv on main: MT=128, grid 16x12 = 192
        gemm_h4<128><<<dim3(GM1, KVW / 128), 256, SM128>>>(
            dn_h, dn_l, wukv_h + (size_t)l * DC_ * KVW, wukv_l + (size_t)l * DC_ * KVW,
            pkv, nullptr, nullptr, nullptr,
            KVW, DC_, DOWNW, KVW, KVW, 0, 0, 3);
        cudaStreamWaitEvent(0, evQ, 0);

        build_qkv_kernel<<<NTOK, 512>>>(idx, cosp, sinp,
                                        vg + (size_t)l * 32 * H_,
                                        vemb + (size_t)l * V_ * C_);

        attn_mma<<<dim3(T_ / 64, H_, B_), 128, ASM>>>();

        if (l == 0) cudaStreamWaitEvent(0, evBig, 0);   // join big splits

        // ap: MT=64, grid 32x8 = 256
        gemm_h4<64><<<dim3(GM2, C_ / 128), 256, SM64>>>(
            y_h, y_l, ap_h + (size_t)l * C_ * C_, ap_l + (size_t)l * C_ * C_,
            px, px, nullptr, nullptr,
            C_, C_, C_, C_, C_, 0, 0, 3);

        mix_norm_kernel<<<NTOK, 256>>>(nullptr, nullptr, 0);

        // fc: MT=128, grid 16x32 = 512
        gemm_h4<128><<<dim3(GM1, 4 * C_ / 128), 256, SM128>>>(
            xn_h, xn_l, fc_h + (size_t)l * C_ * 4 * C_, fc_l + (size_t)l * C_ * 4 * C_,
            nullptr, nullptr, h_h, h_l,
            4 * C_, C_, C_, 4 * C_, 0, 4 * C_, 2, 3);

        // pj: MT=64, grid 32x8 = 256
        gemm_h4<64><<<dim3(GM2, C_ / 128), 256, SM64>>>(
            h_h, h_l, pj_h + (size_t)l * 4 * C_ * C_, pj_l + (size_t)l * 4 * C_ * C_,
            px, px, nullptr, nullptr,
            C_, 4 * C_, 4 * C_, C_, C_, 0, 0, 3);
    }

    mix_norm_kernel<<<NTOK, 256>>>(nullptr, nullptr, 0);
    // lm_head: MT=128, grid 16x250 = 4000, 2-term
    gemm_h4<128><<<dim3(GM1, V_ / 128), 256, SM128>>>(
        xn_h, xn_l, lmh_h, lmh_l,
        out, nullptr, nullptr, nullptr,
        V_, C_, C_, V_, V_, 0, 1, 2);
}